// round 2
// baseline (speedup 1.0000x reference)
#include <cuda_runtime.h>
#include <math.h>

// Problem constants (from reference)
#define N_NODES 50000
#define N_EDGES 800000
#define TOT_E   850000   // edges + self loops
#define HD      128

// ---------------- device scratch (allocation-free rule: device globals) -----
__device__ float g_bufA[(size_t)N_NODES * HD];
__device__ float g_bufB[(size_t)N_NODES * HD];
__device__ int   g_src[N_EDGES];        // normalized int32 edge src
__device__ int   g_dst[N_EDGES];        // normalized int32 edge dst
__device__ int   g_flag;                // 1 = edge_index is int32, 0 = int64
__device__ int   g_cnt[N_NODES];        // counts, later reused as fill cursor
__device__ int   g_off[N_NODES + 1];    // CSR row offsets (by dst)
__device__ int   g_csr[TOT_E];          // src node per CSR slot
__device__ float g_inv[N_NODES];        // rsqrt(deg)
__device__ float g_s[N_NODES];          // xw @ a_src
__device__ float g_d[N_NODES];          // xw @ a_dst
__device__ float g_esc[TOT_E];          // per-edge attention scratch

// ---------------- edge dtype detection + normalization ----------------------
// If the buffer holds int64 values (all < 2^31, non-negative), every odd
// 32-bit word (the high half) is 0. If it holds int32 node ids (random in
// [0, 50000)), odd words are almost surely nonzero. Reads only the first
// 8 KB, safe under either interpretation.
__global__ void k_detect(const unsigned int* __restrict__ w) {
    __shared__ int sflag;
    if (threadIdx.x == 0) sflag = 0;
    __syncthreads();
    if (w[2 * threadIdx.x + 1] != 0u) atomicOr(&sflag, 1);
    __syncthreads();
    if (threadIdx.x == 0) g_flag = sflag;
}

__global__ void k_convert(const void* __restrict__ ei) {
    int e = blockIdx.x * blockDim.x + threadIdx.x;
    if (e >= N_EDGES) return;
    if (g_flag) {
        const int* p = (const int*)ei;
        g_src[e] = p[e];
        g_dst[e] = p[N_EDGES + e];
    } else {
        const long long* p = (const long long*)ei;
        g_src[e] = (int)p[e];
        g_dst[e] = (int)p[N_EDGES + e];
    }
}

// ---------------- CSR build ------------------------------------------------
__global__ void k_init_counts() {
    int i = blockIdx.x * blockDim.x + threadIdx.x;
    if (i < N_NODES) g_cnt[i] = 1;   // self loop
}

__global__ void k_count() {
    int e = blockIdx.x * blockDim.x + threadIdx.x;
    if (e < N_EDGES) atomicAdd(&g_cnt[g_dst[e]], 1);
}

// single-block scan over 50000 counts -> exclusive offsets
__global__ void k_scan() {
    __shared__ int sdata[1024];
    __shared__ int s_carry;
    int tid = threadIdx.x;
    if (tid == 0) s_carry = 0;
    __syncthreads();
    for (int base = 0; base < N_NODES; base += 1024) {
        int i = base + tid;
        int v = (i < N_NODES) ? g_cnt[i] : 0;
        sdata[tid] = v;
        __syncthreads();
        for (int off = 1; off < 1024; off <<= 1) {
            int t = (tid >= off) ? sdata[tid - off] : 0;
            __syncthreads();
            sdata[tid] += t;
            __syncthreads();
        }
        int incl = sdata[tid];
        int carry = s_carry;
        if (i < N_NODES) g_off[i] = carry + incl - v;
        __syncthreads();
        if (tid == 1023) s_carry = carry + sdata[1023];
        __syncthreads();
    }
    if (tid == 0) g_off[N_NODES] = s_carry;
}

__global__ void k_finalize() {
    int i = blockIdx.x * blockDim.x + threadIdx.x;
    if (i < N_NODES) {
        int b = g_off[i];
        int e = g_off[i + 1];
        g_cnt[i] = b;                         // reuse as cursor
        g_inv[i] = rsqrtf((float)(e - b));
    }
}

__global__ void k_fill_loops() {
    int i = blockIdx.x * blockDim.x + threadIdx.x;
    if (i < N_NODES) {
        int pos = atomicAdd(&g_cnt[i], 1);
        g_csr[pos] = i;
    }
}

__global__ void k_fill_edges() {
    int e = blockIdx.x * blockDim.x + threadIdx.x;
    if (e < N_EDGES) {
        int pos = atomicAdd(&g_cnt[g_dst[e]], 1);
        g_csr[pos] = g_src[e];
    }
}

// ---------------- fp32 SGEMM: Y[M,BN] = X[M,128] @ W[128,BN] (+bias) --------
template <int BN>
__global__ void __launch_bounds__(256)
gemm_k128(const float* __restrict__ X, const float* __restrict__ W,
          const float* __restrict__ bias, float* __restrict__ Y, int M) {
    constexpr int TN = BN / 16;
    __shared__ float Xs[32][132];   // transposed: Xs[k][row]
    __shared__ float Ws[32][BN];

    int tid  = threadIdx.x;
    int trow = tid >> 4;    // 0..15, rows trow*8..+7
    int tcol = tid & 15;    // 0..15, cols tcol*TN..+TN-1
    int row0 = blockIdx.x * 128;

    float acc[8][TN];
#pragma unroll
    for (int i = 0; i < 8; ++i)
#pragma unroll
        for (int j = 0; j < TN; ++j) acc[i][j] = 0.f;

    for (int kt = 0; kt < 128; kt += 32) {
        // X tile (128 rows x 32 k), stored transposed
#pragma unroll
        for (int it = 0; it < 4; ++it) {
            int idx = it * 256 + tid;       // 0..1023 (vec4 slots)
            int r   = idx >> 3;             // 0..127
            int c4  = (idx & 7) * 4;        // 0..28
            int gr  = row0 + r;
            float4 v = make_float4(0.f, 0.f, 0.f, 0.f);
            if (gr < M) v = *(const float4*)&X[(size_t)gr * 128 + kt + c4];
            Xs[c4 + 0][r] = v.x;
            Xs[c4 + 1][r] = v.y;
            Xs[c4 + 2][r] = v.z;
            Xs[c4 + 3][r] = v.w;
        }
        // W tile (32 x BN)
#pragma unroll
        for (int it = 0; it < (32 * BN) / 1024; ++it) {
            int idx = it * 256 + tid;
            int r   = idx / (BN / 4);
            int c   = (idx % (BN / 4)) * 4;
            *(float4*)&Ws[r][c] = *(const float4*)&W[(size_t)(kt + r) * BN + c];
        }
        __syncthreads();
#pragma unroll
        for (int kk = 0; kk < 32; ++kk) {
            float a[8];
            *(float4*)&a[0] = *(const float4*)&Xs[kk][trow * 8];
            *(float4*)&a[4] = *(const float4*)&Xs[kk][trow * 8 + 4];
            float b[TN];
#pragma unroll
            for (int j = 0; j < TN; j += 4)
                *(float4*)&b[j] = *(const float4*)&Ws[kk][tcol * TN + j];
#pragma unroll
            for (int i2 = 0; i2 < 8; ++i2)
#pragma unroll
                for (int j = 0; j < TN; ++j)
                    acc[i2][j] += a[i2] * b[j];
        }
        __syncthreads();
    }
#pragma unroll
    for (int i = 0; i < 8; ++i) {
        int gr = row0 + trow * 8 + i;
        if (gr < M) {
#pragma unroll
            for (int j = 0; j < TN; j += 4) {
                float4 v;
                v.x = acc[i][j];     v.y = acc[i][j + 1];
                v.z = acc[i][j + 2]; v.w = acc[i][j + 3];
                if (bias) {
                    v.x += bias[tcol * TN + j];
                    v.y += bias[tcol * TN + j + 1];
                    v.z += bias[tcol * TN + j + 2];
                    v.w += bias[tcol * TN + j + 3];
                }
                *(float4*)&Y[(size_t)gr * BN + tcol * TN + j] = v;
            }
        }
    }
}

// ---------------- GCN aggregate: warp per dst node --------------------------
__global__ void gcn_agg(const float* __restrict__ xw,
                        const float* __restrict__ bias,
                        float* __restrict__ out) {
    int w = (blockIdx.x * blockDim.x + threadIdx.x) >> 5;
    if (w >= N_NODES) return;
    int lane = threadIdx.x & 31;
    int beg = g_off[w], end = g_off[w + 1];
    float invd = g_inv[w];
    const float4* xw4 = (const float4*)xw;
    float4 acc = make_float4(0.f, 0.f, 0.f, 0.f);
    int p = beg;
    for (; p + 1 < end; p += 2) {
        int s0 = g_csr[p], s1 = g_csr[p + 1];
        float c0 = invd * g_inv[s0];
        float c1 = invd * g_inv[s1];
        float4 v0 = xw4[(size_t)s0 * 32 + lane];
        float4 v1 = xw4[(size_t)s1 * 32 + lane];
        acc.x += c0 * v0.x + c1 * v1.x;
        acc.y += c0 * v0.y + c1 * v1.y;
        acc.z += c0 * v0.z + c1 * v1.z;
        acc.w += c0 * v0.w + c1 * v1.w;
    }
    if (p < end) {
        int s0 = g_csr[p];
        float c0 = invd * g_inv[s0];
        float4 v0 = xw4[(size_t)s0 * 32 + lane];
        acc.x += c0 * v0.x; acc.y += c0 * v0.y;
        acc.z += c0 * v0.z; acc.w += c0 * v0.w;
    }
    float4 b = ((const float4*)bias)[lane];
    acc.x = fmaxf(acc.x + b.x, 0.f);
    acc.y = fmaxf(acc.y + b.y, 0.f);
    acc.z = fmaxf(acc.z + b.z, 0.f);
    acc.w = fmaxf(acc.w + b.w, 0.f);
    ((float4*)out)[(size_t)w * 32 + lane] = acc;
}

// ---------------- per-node attention pre-dots: s = xw@a_s, d = xw@a_d -------
__global__ void att_scores(const float* __restrict__ xw,
                           const float* __restrict__ a_s,
                           const float* __restrict__ a_d) {
    int w = (blockIdx.x * blockDim.x + threadIdx.x) >> 5;
    if (w >= N_NODES) return;
    int lane = threadIdx.x & 31;
    float4 v  = ((const float4*)xw)[(size_t)w * 32 + lane];
    float4 as = ((const float4*)a_s)[lane];
    float4 ad = ((const float4*)a_d)[lane];
    float ps = v.x * as.x + v.y * as.y + v.z * as.z + v.w * as.w;
    float pd = v.x * ad.x + v.y * ad.y + v.z * ad.z + v.w * ad.w;
#pragma unroll
    for (int o = 16; o; o >>= 1) {
        ps += __shfl_xor_sync(0xffffffffu, ps, o);
        pd += __shfl_xor_sync(0xffffffffu, pd, o);
    }
    if (lane == 0) { g_s[w] = ps; g_d[w] = pd; }
}

// ---------------- GAT: segment softmax + aggregate, warp per dst node -------
__global__ void gat_agg(const float* __restrict__ xw,
                        const float* __restrict__ bias,
                        float* __restrict__ out) {
    int w = (blockIdx.x * blockDim.x + threadIdx.x) >> 5;
    if (w >= N_NODES) return;
    int lane = threadIdx.x & 31;
    int beg = g_off[w], end = g_off[w + 1];
    float dd = g_d[w];

    // pass 1: e = leaky_relu(s[src] + d[dst]), segment max
    float m = -1e30f;
    for (int p = beg + lane; p < end; p += 32) {
        int s = g_csr[p];
        float e = g_s[s] + dd;
        e = (e > 0.f) ? e : 0.2f * e;
        g_esc[p] = e;
        m = fmaxf(m, e);
    }
#pragma unroll
    for (int o = 16; o; o >>= 1) m = fmaxf(m, __shfl_xor_sync(0xffffffffu, m, o));

    // pass 2: exp and segment sum
    float sum = 0.f;
    for (int p = beg + lane; p < end; p += 32) {
        float ex = __expf(g_esc[p] - m);
        g_esc[p] = ex;
        sum += ex;
    }
#pragma unroll
    for (int o = 16; o; o >>= 1) sum += __shfl_xor_sync(0xffffffffu, sum, o);
    float invden = 1.0f / sum;
    __syncwarp();

    // pass 3: weighted gather of xw[src]
    const float4* xw4 = (const float4*)xw;
    float4 acc = make_float4(0.f, 0.f, 0.f, 0.f);
    int p = beg;
    for (; p + 1 < end; p += 2) {
        int s0 = g_csr[p], s1 = g_csr[p + 1];
        float w0 = g_esc[p] * invden;
        float w1 = g_esc[p + 1] * invden;
        float4 v0 = xw4[(size_t)s0 * 32 + lane];
        float4 v1 = xw4[(size_t)s1 * 32 + lane];
        acc.x += w0 * v0.x + w1 * v1.x;
        acc.y += w0 * v0.y + w1 * v1.y;
        acc.z += w0 * v0.z + w1 * v1.z;
        acc.w += w0 * v0.w + w1 * v1.w;
    }
    if (p < end) {
        int s0 = g_csr[p];
        float w0 = g_esc[p] * invden;
        float4 v0 = xw4[(size_t)s0 * 32 + lane];
        acc.x += w0 * v0.x; acc.y += w0 * v0.y;
        acc.z += w0 * v0.z; acc.w += w0 * v0.w;
    }
    float4 b = ((const float4*)bias)[lane];
    acc.x = fmaxf(acc.x + b.x, 0.f);
    acc.y = fmaxf(acc.y + b.y, 0.f);
    acc.z = fmaxf(acc.z + b.z, 0.f);
    acc.w = fmaxf(acc.w + b.w, 0.f);
    ((float4*)out)[(size_t)w * 32 + lane] = acc;
}

// ---------------- host launch ------------------------------------------------
extern "C" void kernel_launch(void* const* d_in, const int* in_sizes, int n_in,
                              void* d_out, int out_size) {
    const float* x     = (const float*)d_in[0];
    const void*  ei    = d_in[1];                 // int32 or int64, detected on device
    const float* W1    = (const float*)d_in[2];
    const float* b1    = (const float*)d_in[3];
    const float* Wg1   = (const float*)d_in[4];
    const float* asrc1 = (const float*)d_in[5];
    const float* adst1 = (const float*)d_in[6];
    const float* bg1   = (const float*)d_in[7];
    const float* W2    = (const float*)d_in[8];
    const float* b2    = (const float*)d_in[9];
    const float* Wg2   = (const float*)d_in[10];
    const float* asrc2 = (const float*)d_in[11];
    const float* adst2 = (const float*)d_in[12];
    const float* bg2   = (const float*)d_in[13];
    const float* Wo    = (const float*)d_in[14];
    const float* bo    = (const float*)d_in[15];

    float* out_h = (float*)d_out;                       // [N, 128]
    float* out_z = out_h + (size_t)N_NODES * HD;        // [N, 64]

    float *pA = nullptr, *pB = nullptr;
    cudaGetSymbolAddress((void**)&pA, g_bufA);
    cudaGetSymbolAddress((void**)&pB, g_bufB);

    const int TB = 256;
    dim3 nb_node((N_NODES + TB - 1) / TB);
    dim3 nb_edge((N_EDGES + TB - 1) / TB);
    dim3 nb_warp(((size_t)N_NODES * 32 + TB - 1) / TB);
    dim3 nb_gemm((N_NODES + 127) / 128);

    // Edge dtype detection + normalization to int32
    k_detect<<<1, 1024>>>((const unsigned int*)ei);
    k_convert<<<nb_edge, TB>>>(ei);

    // CSR build (every call: deterministic work, no caching)
    k_init_counts<<<nb_node, TB>>>();
    k_count<<<nb_edge, TB>>>();
    k_scan<<<1, 1024>>>();
    k_finalize<<<nb_node, TB>>>();
    k_fill_loops<<<nb_node, TB>>>();
    k_fill_edges<<<nb_edge, TB>>>();

    // Layer 1: GCN
    gemm_k128<128><<<nb_gemm, TB>>>(x, W1, nullptr, pA, N_NODES);
    gcn_agg<<<nb_warp, TB>>>(pA, b1, pB);

    // Layer 2: GAT
    gemm_k128<128><<<nb_gemm, TB>>>(pB, Wg1, nullptr, pA, N_NODES);
    att_scores<<<nb_warp, TB>>>(pA, asrc1, adst1);
    gat_agg<<<nb_warp, TB>>>(pA, bg1, pB);

    // Layer 3: GCN
    gemm_k128<128><<<nb_gemm, TB>>>(pB, W2, nullptr, pA, N_NODES);
    gcn_agg<<<nb_warp, TB>>>(pA, b2, pB);

    // Layer 4: GAT -> h written directly into d_out
    gemm_k128<128><<<nb_gemm, TB>>>(pB, Wg2, nullptr, pA, N_NODES);
    att_scores<<<nb_warp, TB>>>(pA, asrc2, adst2);
    gat_agg<<<nb_warp, TB>>>(pA, bg2, out_h);

    // Output head: z = h @ Wo + bo
    gemm_k128<64><<<nb_gemm, TB>>>(out_h, Wo, bo, out_z, N_NODES);
}

// round 4
// speedup vs baseline: 1.0569x; 1.0569x over previous
#include <cuda_runtime.h>
#include <cuda_bf16.h>
#include <math.h>
#include <stdint.h>

// Problem constants
#define N_NODES 50000
#define N_EDGES 800000
#define TOT_E   850000
#define HD      128

// ---------------- device scratch --------------------------------------------
__device__ float g_bufA[(size_t)N_NODES * HD];
__device__ float g_bufB[(size_t)N_NODES * HD];
__device__ int   g_src[N_EDGES];
__device__ int   g_dst[N_EDGES];
__device__ int   g_flag;
__device__ int   g_cnt[N_NODES];
__device__ int   g_off[N_NODES + 1];
__device__ int   g_csr[TOT_E];
__device__ float g_inv[N_NODES];
__device__ float g_s[N_NODES];
__device__ float g_d[N_NODES];
__device__ float g_esc[TOT_E];
// fragment-permuted weight buffer: hi [128*BN ushorts] then lo [128*BN ushorts]
__device__ unsigned short g_wperm[2 * 128 * 128];

// ---------------- warp MMA helper --------------------------------------------
__device__ __forceinline__ void mma16816(float* d, const uint32_t* a, const uint32_t* b) {
    asm volatile(
        "mma.sync.aligned.m16n8k16.row.col.f32.bf16.bf16.f32 "
        "{%0,%1,%2,%3}, {%4,%5,%6,%7}, {%8,%9}, {%0,%1,%2,%3};"
        : "+f"(d[0]), "+f"(d[1]), "+f"(d[2]), "+f"(d[3])
        : "r"(a[0]), "r"(a[1]), "r"(a[2]), "r"(a[3]), "r"(b[0]), "r"(b[1]));
}

__device__ __forceinline__ uint32_t pack_bf16(float x, float y) {
    __nv_bfloat16 hx = __float2bfloat16(x), hy = __float2bfloat16(y);
    return (uint32_t)__bfloat16_as_ushort(hx) |
           ((uint32_t)__bfloat16_as_ushort(hy) << 16);
}

// ---------------- weight conversion: W[128,BN] -> fragment-permuted hi/lo ----
// B fragment for mma.m16n8k16 (col): reg = k_in_tile>=8, lane = (n&7)*4 + ((k&7)>>1),
// ushort half = k&1. b32 slot = ((nt*8+kt)*32+lane)*2 + reg.
__global__ void k_wconv(const float* __restrict__ W, int BN) {
    int total = 128 * BN;
    for (int idx = blockIdx.x * blockDim.x + threadIdx.x; idx < total;
         idx += blockDim.x * gridDim.x) {
        int k = idx / BN, n = idx % BN;
        float v = W[idx];
        __nv_bfloat16 h = __float2bfloat16(v);
        __nv_bfloat16 l = __float2bfloat16(v - __bfloat162float(h));
        int nt = n >> 3, kt = k >> 4, kk = k & 15;
        int reg = kk >> 3, klo = kk & 7;
        int lane = (n & 7) * 4 + (klo >> 1);
        int slot = ((nt * 8 + kt) * 32 + lane) * 2 + reg;
        int pos = slot * 2 + (kk & 1);
        g_wperm[pos] = __bfloat16_as_ushort(h);
        g_wperm[total + pos] = __bfloat16_as_ushort(l);
    }
}

// ---------------- HMMA bf16x3 GEMM: Y[M,BN] = X[M,128] @ W[128,BN] (+bias) ---
// Block: 128 rows, 256 threads (8 warps: 4 in m x 2 in n).
// SMEM: A hi/lo fragment-permuted (32KB each), B hi/lo copied from g_wperm.
template <int BN>
__global__ void __launch_bounds__(256)
tc_gemm(const float* __restrict__ X, const float* __restrict__ bias,
        float* __restrict__ Y, int M) {
    extern __shared__ char smem[];
    constexpr int NT = BN / 16;                 // n-tiles per warp
    constexpr int OFF_ALO = 32768;
    constexpr int OFF_B   = 65536;
    constexpr int B_HALF  = 128 * BN * 2;       // bytes of B hi part

    int tid  = threadIdx.x;
    int wid  = tid >> 5;
    int lane = tid & 31;
    int row0 = blockIdx.x * 128;

    // --- copy permuted weights (hi+lo) from global to SMEM -----------------
    {
        const uint4* src = (const uint4*)g_wperm;
        uint4* dst = (uint4*)(smem + OFF_B);
        int n16 = (2 * B_HALF) / 16;
        for (int i = tid; i < n16; i += 256) dst[i] = src[i];
    }

    // --- convert A (X tile) into fragment-permuted hi/lo SMEM --------------
    // A fragment: reg = ((cc>>3)<<1)|(rr>>3), lane = (rr&7)*4+((cc&7)>>1)
    {
        uint32_t* ah = (uint32_t*)smem;
        uint32_t* al = (uint32_t*)(smem + OFF_ALO);
#pragma unroll
        for (int it = 0; it < 16; ++it) {
            int idx = it * 256 + tid;
            int r = idx >> 5;               // 0..127
            int c = (idx & 31) * 4;         // 0..124
            int gr = row0 + r;
            float4 v = make_float4(0.f, 0.f, 0.f, 0.f);
            if (gr < M) v = *(const float4*)&X[(size_t)gr * 128 + c];
            __nv_bfloat16 h0 = __float2bfloat16(v.x), h1 = __float2bfloat16(v.y);
            __nv_bfloat16 h2 = __float2bfloat16(v.z), h3 = __float2bfloat16(v.w);
            float l0 = v.x - __bfloat162float(h0), l1 = v.y - __bfloat162float(h1);
            float l2 = v.z - __bfloat162float(h2), l3 = v.w - __bfloat162float(h3);
            uint32_t hi0 = (uint32_t)__bfloat16_as_ushort(h0) |
                           ((uint32_t)__bfloat16_as_ushort(h1) << 16);
            uint32_t hi1 = (uint32_t)__bfloat16_as_ushort(h2) |
                           ((uint32_t)__bfloat16_as_ushort(h3) << 16);
            uint32_t lo0 = pack_bf16(l0, l1);
            uint32_t lo1 = pack_bf16(l2, l3);
            int mt = r >> 4, rr = r & 15;
            int kt = c >> 4, cc = c & 15;
            int reg = ((cc >> 3) << 1) | (rr >> 3);
            int ln0 = (rr & 7) * 4 + ((cc & 7) >> 1);
            int base = (mt * 8 + kt) * 32;
            ah[(base + ln0) * 4 + reg]     = hi0;
            ah[(base + ln0 + 1) * 4 + reg] = hi1;
            al[(base + ln0) * 4 + reg]     = lo0;
            al[(base + ln0 + 1) * 4 + reg] = lo1;
        }
    }
    __syncthreads();

    // --- MMA mainloop: 3 passes (AhiBhi, AhiBlo, AloBhi) x 8 k-steps --------
    int wm = wid & 3;        // m position (32 rows)
    int wn = wid >> 2;       // n position (NT*8 cols)
    float acc[2][NT][4];
#pragma unroll
    for (int i = 0; i < 2; ++i)
#pragma unroll
        for (int j = 0; j < NT; ++j)
#pragma unroll
            for (int q = 0; q < 4; ++q) acc[i][j][q] = 0.f;

#pragma unroll
    for (int pass = 0; pass < 3; ++pass) {
        const uint4* Ab = (const uint4*)(smem + (pass == 2 ? OFF_ALO : 0));
        const uint2* Bb = (const uint2*)(smem + OFF_B + (pass == 1 ? B_HALF : 0));
#pragma unroll
        for (int kt = 0; kt < 8; ++kt) {
            uint4 a0 = Ab[((wm * 2 + 0) * 8 + kt) * 32 + lane];
            uint4 a1 = Ab[((wm * 2 + 1) * 8 + kt) * 32 + lane];
            uint2 b[NT];
#pragma unroll
            for (int j = 0; j < NT; ++j)
                b[j] = Bb[((wn * NT + j) * 8 + kt) * 32 + lane];
#pragma unroll
            for (int j = 0; j < NT; ++j) {
                mma16816(acc[0][j], (const uint32_t*)&a0, (const uint32_t*)&b[j]);
                mma16816(acc[1][j], (const uint32_t*)&a1, (const uint32_t*)&b[j]);
            }
        }
    }

    // --- epilogue: direct global stores of D fragments ----------------------
    int rbase = row0 + wm * 32 + (lane >> 2);
    int cbase = wn * NT * 8 + (lane & 3) * 2;
#pragma unroll
    for (int i = 0; i < 2; ++i) {
        int r = rbase + i * 16;
#pragma unroll
        for (int j = 0; j < NT; ++j) {
            int cc = cbase + j * 8;
            float bx = 0.f, by = 0.f;
            if (bias) { bx = bias[cc]; by = bias[cc + 1]; }
            if (r < M) {
                float2 v0 = make_float2(acc[i][j][0] + bx, acc[i][j][1] + by);
                *(float2*)&Y[(size_t)r * BN + cc] = v0;
            }
            if (r + 8 < M) {
                float2 v1 = make_float2(acc[i][j][2] + bx, acc[i][j][3] + by);
                *(float2*)&Y[(size_t)(r + 8) * BN + cc] = v1;
            }
        }
    }
}

// ---------------- edge dtype detect + convert --------------------------------
__global__ void k_detect(const unsigned int* __restrict__ w) {
    __shared__ int sflag;
    if (threadIdx.x == 0) sflag = 0;
    __syncthreads();
    if (w[2 * threadIdx.x + 1] != 0u) atomicOr(&sflag, 1);
    __syncthreads();
    if (threadIdx.x == 0) g_flag = sflag;
}

__global__ void k_convert(const void* __restrict__ ei) {
    int e = blockIdx.x * blockDim.x + threadIdx.x;
    if (e >= N_EDGES) return;
    if (g_flag) {
        const int* p = (const int*)ei;
        g_src[e] = p[e];
        g_dst[e] = p[N_EDGES + e];
    } else {
        const long long* p = (const long long*)ei;
        g_src[e] = (int)p[e];
        g_dst[e] = (int)p[N_EDGES + e];
    }
}

// ---------------- CSR build --------------------------------------------------
__global__ void k_init_counts() {
    int i = blockIdx.x * blockDim.x + threadIdx.x;
    if (i < N_NODES) g_cnt[i] = 1;
}
__global__ void k_count() {
    int e = blockIdx.x * blockDim.x + threadIdx.x;
    if (e < N_EDGES) atomicAdd(&g_cnt[g_dst[e]], 1);
}
__global__ void k_scan() {
    __shared__ int sdata[1024];
    __shared__ int s_carry;
    int tid = threadIdx.x;
    if (tid == 0) s_carry = 0;
    __syncthreads();
    for (int base = 0; base < N_NODES; base += 1024) {
        int i = base + tid;
        int v = (i < N_NODES) ? g_cnt[i] : 0;
        sdata[tid] = v;
        __syncthreads();
        for (int off = 1; off < 1024; off <<= 1) {
            int t = (tid >= off) ? sdata[tid - off] : 0;
            __syncthreads();
            sdata[tid] += t;
            __syncthreads();
        }
        int incl = sdata[tid];
        int carry = s_carry;
        if (i < N_NODES) g_off[i] = carry + incl - v;
        __syncthreads();
        if (tid == 1023) s_carry = carry + sdata[1023];
        __syncthreads();
    }
    if (tid == 0) g_off[N_NODES] = s_carry;
}
// finalize: cursor starts after the self-loop slot, which we write here
__global__ void k_finalize() {
    int i = blockIdx.x * blockDim.x + threadIdx.x;
    if (i < N_NODES) {
        int b = g_off[i], e = g_off[i + 1];
        g_csr[b] = i;          // self loop
        g_cnt[i] = b + 1;      // cursor
        g_inv[i] = rsqrtf((float)(e - b));
    }
}
__global__ void k_fill_edges() {
    int e = blockIdx.x * blockDim.x + threadIdx.x;
    if (e < N_EDGES) {
        int pos = atomicAdd(&g_cnt[g_dst[e]], 1);
        g_csr[pos] = g_src[e];
    }
}

// ---------------- GCN aggregate ----------------------------------------------
__global__ void gcn_agg(const float* __restrict__ xw,
                        const float* __restrict__ bias,
                        float* __restrict__ out) {
    int w = (blockIdx.x * blockDim.x + threadIdx.x) >> 5;
    if (w >= N_NODES) return;
    int lane = threadIdx.x & 31;
    int beg = g_off[w], end = g_off[w + 1];
    float invd = g_inv[w];
    const float4* xw4 = (const float4*)xw;
    float4 acc = make_float4(0.f, 0.f, 0.f, 0.f);
    int p = beg;
    for (; p + 1 < end; p += 2) {
        int s0 = g_csr[p], s1 = g_csr[p + 1];
        float c0 = invd * g_inv[s0];
        float c1 = invd * g_inv[s1];
        float4 v0 = xw4[(size_t)s0 * 32 + lane];
        float4 v1 = xw4[(size_t)s1 * 32 + lane];
        acc.x += c0 * v0.x + c1 * v1.x;
        acc.y += c0 * v0.y + c1 * v1.y;
        acc.z += c0 * v0.z + c1 * v1.z;
        acc.w += c0 * v0.w + c1 * v1.w;
    }
    if (p < end) {
        int s0 = g_csr[p];
        float c0 = invd * g_inv[s0];
        float4 v0 = xw4[(size_t)s0 * 32 + lane];
        acc.x += c0 * v0.x; acc.y += c0 * v0.y;
        acc.z += c0 * v0.z; acc.w += c0 * v0.w;
    }
    float4 b = ((const float4*)bias)[lane];
    acc.x = fmaxf(acc.x + b.x, 0.f);
    acc.y = fmaxf(acc.y + b.y, 0.f);
    acc.z = fmaxf(acc.z + b.z, 0.f);
    acc.w = fmaxf(acc.w + b.w, 0.f);
    ((float4*)out)[(size_t)w * 32 + lane] = acc;
}

// ---------------- attention pre-dots -----------------------------------------
__global__ void att_scores(const float* __restrict__ xw,
                           const float* __restrict__ a_s,
                           const float* __restrict__ a_d) {
    int w = (blockIdx.x * blockDim.x + threadIdx.x) >> 5;
    if (w >= N_NODES) return;
    int lane = threadIdx.x & 31;
    float4 v  = ((const float4*)xw)[(size_t)w * 32 + lane];
    float4 as = ((const float4*)a_s)[lane];
    float4 ad = ((const float4*)a_d)[lane];
    float ps = v.x * as.x + v.y * as.y + v.z * as.z + v.w * as.w;
    float pd = v.x * ad.x + v.y * ad.y + v.z * ad.z + v.w * ad.w;
#pragma unroll
    for (int o = 16; o; o >>= 1) {
        ps += __shfl_xor_sync(0xffffffffu, ps, o);
        pd += __shfl_xor_sync(0xffffffffu, pd, o);
    }
    if (lane == 0) { g_s[w] = ps; g_d[w] = pd; }
}

// ---------------- GAT aggregate ----------------------------------------------
__global__ void gat_agg(const float* __restrict__ xw,
                        const float* __restrict__ bias,
                        float* __restrict__ out) {
    int w = (blockIdx.x * blockDim.x + threadIdx.x) >> 5;
    if (w >= N_NODES) return;
    int lane = threadIdx.x & 31;
    int beg = g_off[w], end = g_off[w + 1];
    float dd = g_d[w];

    float m = -1e30f;
    for (int p = beg + lane; p < end; p += 32) {
        int s = g_csr[p];
        float e = g_s[s] + dd;
        e = (e > 0.f) ? e : 0.2f * e;
        g_esc[p] = e;
        m = fmaxf(m, e);
    }
#pragma unroll
    for (int o = 16; o; o >>= 1) m = fmaxf(m, __shfl_xor_sync(0xffffffffu, m, o));

    float sum = 0.f;
    for (int p = beg + lane; p < end; p += 32) {
        float ex = __expf(g_esc[p] - m);
        g_esc[p] = ex;
        sum += ex;
    }
#pragma unroll
    for (int o = 16; o; o >>= 1) sum += __shfl_xor_sync(0xffffffffu, sum, o);
    float invden = 1.0f / sum;
    __syncwarp();

    const float4* xw4 = (const float4*)xw;
    float4 acc = make_float4(0.f, 0.f, 0.f, 0.f);
    int p = beg;
    for (; p + 1 < end; p += 2) {
        int s0 = g_csr[p], s1 = g_csr[p + 1];
        float w0 = g_esc[p] * invden;
        float w1 = g_esc[p + 1] * invden;
        float4 v0 = xw4[(size_t)s0 * 32 + lane];
        float4 v1 = xw4[(size_t)s1 * 32 + lane];
        acc.x += w0 * v0.x + w1 * v1.x;
        acc.y += w0 * v0.y + w1 * v1.y;
        acc.z += w0 * v0.z + w1 * v1.z;
        acc.w += w0 * v0.w + w1 * v1.w;
    }
    if (p < end) {
        int s0 = g_csr[p];
        float w0 = g_esc[p] * invden;
        float4 v0 = xw4[(size_t)s0 * 32 + lane];
        acc.x += w0 * v0.x; acc.y += w0 * v0.y;
        acc.z += w0 * v0.z; acc.w += w0 * v0.w;
    }
    float4 b = ((const float4*)bias)[lane];
    acc.x = fmaxf(acc.x + b.x, 0.f);
    acc.y = fmaxf(acc.y + b.y, 0.f);
    acc.z = fmaxf(acc.z + b.z, 0.f);
    acc.w = fmaxf(acc.w + b.w, 0.f);
    ((float4*)out)[(size_t)w * 32 + lane] = acc;
}

// ---------------- host launch --------------------------------------------------
extern "C" void kernel_launch(void* const* d_in, const int* in_sizes, int n_in,
                              void* d_out, int out_size) {
    const float* x     = (const float*)d_in[0];
    const void*  ei    = d_in[1];
    const float* W1    = (const float*)d_in[2];
    const float* b1    = (const float*)d_in[3];
    const float* Wg1   = (const float*)d_in[4];
    const float* asrc1 = (const float*)d_in[5];
    const float* adst1 = (const float*)d_in[6];
    const float* bg1   = (const float*)d_in[7];
    const float* W2    = (const float*)d_in[8];
    const float* b2    = (const float*)d_in[9];
    const float* Wg2   = (const float*)d_in[10];
    const float* asrc2 = (const float*)d_in[11];
    const float* adst2 = (const float*)d_in[12];
    const float* bg2   = (const float*)d_in[13];
    const float* Wo    = (const float*)d_in[14];
    const float* bo    = (const float*)d_in[15];

    float* out_h = (float*)d_out;
    float* out_z = out_h + (size_t)N_NODES * HD;

    float *pA = nullptr, *pB = nullptr;
    cudaGetSymbolAddress((void**)&pA, g_bufA);
    cudaGetSymbolAddress((void**)&pB, g_bufB);

    const int TB = 256;
    dim3 nb_node((N_NODES + TB - 1) / TB);
    dim3 nb_edge((N_EDGES + TB - 1) / TB);
    dim3 nb_warp(((size_t)N_NODES * 32 + TB - 1) / TB);
    dim3 nb_gemm((N_NODES + 127) / 128);

    const int SMEM128 = 65536 + 128 * 128 * 2 * 2;   // 131072
    const int SMEM64  = 65536 + 128 * 64 * 2 * 2;    // 98304
    static int attr_done = 0;
    cudaFuncSetAttribute(tc_gemm<128>, cudaFuncAttributeMaxDynamicSharedMemorySize, SMEM128);
    cudaFuncSetAttribute(tc_gemm<64>,  cudaFuncAttributeMaxDynamicSharedMemorySize, SMEM64);
    (void)attr_done;

    k_detect<<<1, 1024>>>((const unsigned int*)ei);
    k_convert<<<nb_edge, TB>>>(ei);

    k_init_counts<<<nb_node, TB>>>();
    k_count<<<nb_edge, TB>>>();
    k_scan<<<1, 1024>>>();
    k_finalize<<<nb_node, TB>>>();
    k_fill_edges<<<nb_edge, TB>>>();

    // Layer 1: GCN
    k_wconv<<<32, 256>>>(W1, 128);
    tc_gemm<128><<<nb_gemm, TB, SMEM128>>>(x, nullptr, pA, N_NODES);
    gcn_agg<<<nb_warp, TB>>>(pA, b1, pB);

    // Layer 2: GAT
    k_wconv<<<32, 256>>>(Wg1, 128);
    tc_gemm<128><<<nb_gemm, TB, SMEM128>>>(pB, nullptr, pA, N_NODES);
    att_scores<<<nb_warp, TB>>>(pA, asrc1, adst1);
    gat_agg<<<nb_warp, TB>>>(pA, bg1, pB);

    // Layer 3: GCN
    k_wconv<<<32, 256>>>(W2, 128);
    tc_gemm<128><<<nb_gemm, TB, SMEM128>>>(pB, nullptr, pA, N_NODES);
    gcn_agg<<<nb_warp, TB>>>(pA, b2, pB);

    // Layer 4: GAT -> h into d_out
    k_wconv<<<32, 256>>>(Wg2, 128);
    tc_gemm<128><<<nb_gemm, TB, SMEM128>>>(pB, nullptr, pA, N_NODES);
    att_scores<<<nb_warp, TB>>>(pA, asrc2, adst2);
    gat_agg<<<nb_warp, TB>>>(pA, bg2, out_h);

    // Output head: z = h @ Wo + bo
    k_wconv<<<32, 256>>>(Wo, 64);
    tc_gemm<64><<<nb_gemm, TB, SMEM64>>>(out_h, bo, out_z, N_NODES);
}

// round 5
// speedup vs baseline: 1.2637x; 1.1957x over previous
#include <cuda_runtime.h>
#include <cuda_bf16.h>
#include <math.h>
#include <stdint.h>

// Problem constants
#define N_NODES 50000
#define N_EDGES 800000
#define TOT_E   850000
#define HD      128
#define NB_SCAN 49            // ceil(50000/1024)

// ---------------- device scratch --------------------------------------------
__device__ float g_bufA[(size_t)N_NODES * HD];
__device__ float g_bufB[(size_t)N_NODES * HD];
__device__ int   g_src[N_EDGES];
__device__ int   g_dst[N_EDGES];
__device__ int   g_flag;
__device__ int   g_cnt[N_NODES];
__device__ int   g_off[N_NODES + 1];
__device__ int   g_csr[TOT_E];
__device__ int   g_bsum[64];
__device__ int   g_bpre[64];
__device__ float g_inv[N_NODES];
__device__ float g_s[N_NODES];
__device__ float g_d[N_NODES];
__device__ float g_esc[TOT_E];          // fallback only (deg > 64)
__device__ unsigned short g_wperm[2 * 128 * 128];

// ---------------- warp MMA helper --------------------------------------------
__device__ __forceinline__ void mma16816(float* d, const uint32_t* a, const uint32_t* b) {
    asm volatile(
        "mma.sync.aligned.m16n8k16.row.col.f32.bf16.bf16.f32 "
        "{%0,%1,%2,%3}, {%4,%5,%6,%7}, {%8,%9}, {%0,%1,%2,%3};"
        : "+f"(d[0]), "+f"(d[1]), "+f"(d[2]), "+f"(d[3])
        : "r"(a[0]), "r"(a[1]), "r"(a[2]), "r"(a[3]), "r"(b[0]), "r"(b[1]));
}

__device__ __forceinline__ uint32_t pack_bf16(float x, float y) {
    __nv_bfloat16 hx = __float2bfloat16(x), hy = __float2bfloat16(y);
    return (uint32_t)__bfloat16_as_ushort(hx) |
           ((uint32_t)__bfloat16_as_ushort(hy) << 16);
}

// ---------------- weight conversion -> fragment-permuted hi/lo ---------------
__global__ void k_wconv(const float* __restrict__ W, int BN) {
    int total = 128 * BN;
    for (int idx = blockIdx.x * blockDim.x + threadIdx.x; idx < total;
         idx += blockDim.x * gridDim.x) {
        int k = idx / BN, n = idx % BN;
        float v = W[idx];
        __nv_bfloat16 h = __float2bfloat16(v);
        __nv_bfloat16 l = __float2bfloat16(v - __bfloat162float(h));
        int nt = n >> 3, kt = k >> 4, kk = k & 15;
        int reg = kk >> 3, klo = kk & 7;
        int lane = (n & 7) * 4 + (klo >> 1);
        int slot = ((nt * 8 + kt) * 32 + lane) * 2 + reg;
        int pos = slot * 2 + (kk & 1);
        g_wperm[pos] = __bfloat16_as_ushort(h);
        g_wperm[total + pos] = __bfloat16_as_ushort(l);
    }
}

// ---------------- HMMA bf16x3 GEMM -------------------------------------------
template <int BN>
__global__ void __launch_bounds__(256)
tc_gemm(const float* __restrict__ X, const float* __restrict__ bias,
        float* __restrict__ Y, int M) {
    extern __shared__ char smem[];
    constexpr int NT = BN / 16;
    constexpr int OFF_ALO = 32768;
    constexpr int OFF_B   = 65536;
    constexpr int B_HALF  = 128 * BN * 2;

    int tid  = threadIdx.x;
    int wid  = tid >> 5;
    int lane = tid & 31;
    int row0 = blockIdx.x * 128;

    {
        const uint4* src = (const uint4*)g_wperm;
        uint4* dst = (uint4*)(smem + OFF_B);
        int n16 = (2 * B_HALF) / 16;
        for (int i = tid; i < n16; i += 256) dst[i] = src[i];
    }
    {
        uint32_t* ah = (uint32_t*)smem;
        uint32_t* al = (uint32_t*)(smem + OFF_ALO);
#pragma unroll
        for (int it = 0; it < 16; ++it) {
            int idx = it * 256 + tid;
            int r = idx >> 5;
            int c = (idx & 31) * 4;
            int gr = row0 + r;
            float4 v = make_float4(0.f, 0.f, 0.f, 0.f);
            if (gr < M) v = *(const float4*)&X[(size_t)gr * 128 + c];
            __nv_bfloat16 h0 = __float2bfloat16(v.x), h1 = __float2bfloat16(v.y);
            __nv_bfloat16 h2 = __float2bfloat16(v.z), h3 = __float2bfloat16(v.w);
            float l0 = v.x - __bfloat162float(h0), l1 = v.y - __bfloat162float(h1);
            float l2 = v.z - __bfloat162float(h2), l3 = v.w - __bfloat162float(h3);
            uint32_t hi0 = (uint32_t)__bfloat16_as_ushort(h0) |
                           ((uint32_t)__bfloat16_as_ushort(h1) << 16);
            uint32_t hi1 = (uint32_t)__bfloat16_as_ushort(h2) |
                           ((uint32_t)__bfloat16_as_ushort(h3) << 16);
            uint32_t lo0 = pack_bf16(l0, l1);
            uint32_t lo1 = pack_bf16(l2, l3);
            int mt = r >> 4, rr = r & 15;
            int kt = c >> 4, cc = c & 15;
            int reg = ((cc >> 3) << 1) | (rr >> 3);
            int ln0 = (rr & 7) * 4 + ((cc & 7) >> 1);
            int base = (mt * 8 + kt) * 32;
            ah[(base + ln0) * 4 + reg]     = hi0;
            ah[(base + ln0 + 1) * 4 + reg] = hi1;
            al[(base + ln0) * 4 + reg]     = lo0;
            al[(base + ln0 + 1) * 4 + reg] = lo1;
        }
    }
    __syncthreads();

    int wm = wid & 3;
    int wn = wid >> 2;
    float acc[2][NT][4];
#pragma unroll
    for (int i = 0; i < 2; ++i)
#pragma unroll
        for (int j = 0; j < NT; ++j)
#pragma unroll
            for (int q = 0; q < 4; ++q) acc[i][j][q] = 0.f;

#pragma unroll
    for (int pass = 0; pass < 3; ++pass) {
        const uint4* Ab = (const uint4*)(smem + (pass == 2 ? OFF_ALO : 0));
        const uint2* Bb = (const uint2*)(smem + OFF_B + (pass == 1 ? B_HALF : 0));
#pragma unroll
        for (int kt = 0; kt < 8; ++kt) {
            uint4 a0 = Ab[((wm * 2 + 0) * 8 + kt) * 32 + lane];
            uint4 a1 = Ab[((wm * 2 + 1) * 8 + kt) * 32 + lane];
            uint2 b[NT];
#pragma unroll
            for (int j = 0; j < NT; ++j)
                b[j] = Bb[((wn * NT + j) * 8 + kt) * 32 + lane];
#pragma unroll
            for (int j = 0; j < NT; ++j) {
                mma16816(acc[0][j], (const uint32_t*)&a0, (const uint32_t*)&b[j]);
                mma16816(acc[1][j], (const uint32_t*)&a1, (const uint32_t*)&b[j]);
            }
        }
    }

    int rbase = row0 + wm * 32 + (lane >> 2);
    int cbase = wn * NT * 8 + (lane & 3) * 2;
#pragma unroll
    for (int i = 0; i < 2; ++i) {
        int r = rbase + i * 16;
#pragma unroll
        for (int j = 0; j < NT; ++j) {
            int cc = cbase + j * 8;
            float bx = 0.f, by = 0.f;
            if (bias) { bx = bias[cc]; by = bias[cc + 1]; }
            if (r < M) {
                float2 v0 = make_float2(acc[i][j][0] + bx, acc[i][j][1] + by);
                *(float2*)&Y[(size_t)r * BN + cc] = v0;
            }
            if (r + 8 < M) {
                float2 v1 = make_float2(acc[i][j][2] + bx, acc[i][j][3] + by);
                *(float2*)&Y[(size_t)(r + 8) * BN + cc] = v1;
            }
        }
    }
}

// ---------------- edge dtype detect -------------------------------------------
__global__ void k_detect(const unsigned int* __restrict__ w) {
    __shared__ int sflag;
    if (threadIdx.x == 0) sflag = 0;
    __syncthreads();
    if (w[2 * threadIdx.x + 1] != 0u) atomicOr(&sflag, 1);
    __syncthreads();
    if (threadIdx.x == 0) g_flag = sflag;
}

// fused convert + degree count (g_cnt pre-zeroed by memset)
__global__ void k_convert_count(const void* __restrict__ ei) {
    int e = blockIdx.x * blockDim.x + threadIdx.x;
    if (e >= N_EDGES) return;
    int s, d;
    if (g_flag) {
        const int* p = (const int*)ei;
        s = p[e]; d = p[N_EDGES + e];
    } else {
        const long long* p = (const long long*)ei;
        s = (int)p[e]; d = (int)p[N_EDGES + e];
    }
    g_src[e] = s;
    g_dst[e] = d;
    atomicAdd(&g_cnt[d], 1);
}

// ---------------- multi-block scan (3 kernels) ---------------------------------
__global__ void k_scan1() {
    __shared__ int sd[1024];
    int tid = threadIdx.x;
    int i = blockIdx.x * 1024 + tid;
    int v = (i < N_NODES) ? g_cnt[i] + 1 : 0;   // +1 = self loop
    sd[tid] = v;
    __syncthreads();
    for (int off = 1; off < 1024; off <<= 1) {
        int t = (tid >= off) ? sd[tid - off] : 0;
        __syncthreads();
        sd[tid] += t;
        __syncthreads();
    }
    if (i < N_NODES) g_off[i] = sd[tid] - v;    // exclusive within block
    if (tid == 1023) g_bsum[blockIdx.x] = sd[1023];
}

__global__ void k_scan2() {
    __shared__ int sd[64];
    int tid = threadIdx.x;
    int v = (tid < NB_SCAN) ? g_bsum[tid] : 0;
    sd[tid] = v;
    __syncthreads();
    for (int off = 1; off < 64; off <<= 1) {
        int t = (tid >= off) ? sd[tid - off] : 0;
        __syncthreads();
        sd[tid] += t;
        __syncthreads();
    }
    if (tid < NB_SCAN) g_bpre[tid] = sd[tid] - v;
    if (tid == 63) g_off[N_NODES] = sd[63];
}

__global__ void k_scan3() {
    int i = blockIdx.x * 1024 + threadIdx.x;
    if (i < N_NODES) g_off[i] += g_bpre[blockIdx.x];
}

// finalize: self loop slot + cursor + inv-degree
__global__ void k_finalize() {
    int i = blockIdx.x * blockDim.x + threadIdx.x;
    if (i < N_NODES) {
        int b = g_off[i], e = g_off[i + 1];
        g_csr[b] = i;
        g_cnt[i] = b + 1;
        g_inv[i] = rsqrtf((float)(e - b));
    }
}

__global__ void k_fill_edges() {
    int e = blockIdx.x * blockDim.x + threadIdx.x;
    if (e < N_EDGES) {
        int pos = atomicAdd(&g_cnt[g_dst[e]], 1);
        g_csr[pos] = g_src[e];
    }
}

// ---------------- GCN aggregate -------------------------------------------------
__global__ void gcn_agg(const float* __restrict__ xw,
                        const float* __restrict__ bias,
                        float* __restrict__ out) {
    int w = (blockIdx.x * blockDim.x + threadIdx.x) >> 5;
    if (w >= N_NODES) return;
    int lane = threadIdx.x & 31;
    int beg = g_off[w], end = g_off[w + 1];
    float invd = g_inv[w];
    const float4* xw4 = (const float4*)xw;
    float4 acc = make_float4(0.f, 0.f, 0.f, 0.f);
    int p = beg;
    for (; p + 1 < end; p += 2) {
        int s0 = g_csr[p], s1 = g_csr[p + 1];
        float c0 = invd * g_inv[s0];
        float c1 = invd * g_inv[s1];
        float4 v0 = xw4[(size_t)s0 * 32 + lane];
        float4 v1 = xw4[(size_t)s1 * 32 + lane];
        acc.x += c0 * v0.x + c1 * v1.x;
        acc.y += c0 * v0.y + c1 * v1.y;
        acc.z += c0 * v0.z + c1 * v1.z;
        acc.w += c0 * v0.w + c1 * v1.w;
    }
    if (p < end) {
        int s0 = g_csr[p];
        float c0 = invd * g_inv[s0];
        float4 v0 = xw4[(size_t)s0 * 32 + lane];
        acc.x += c0 * v0.x; acc.y += c0 * v0.y;
        acc.z += c0 * v0.z; acc.w += c0 * v0.w;
    }
    float4 b = ((const float4*)bias)[lane];
    acc.x = fmaxf(acc.x + b.x, 0.f);
    acc.y = fmaxf(acc.y + b.y, 0.f);
    acc.z = fmaxf(acc.z + b.z, 0.f);
    acc.w = fmaxf(acc.w + b.w, 0.f);
    ((float4*)out)[(size_t)w * 32 + lane] = acc;
}

// ---------------- attention pre-dots ---------------------------------------------
__global__ void att_scores(const float* __restrict__ xw,
                           const float* __restrict__ a_s,
                           const float* __restrict__ a_d) {
    int w = (blockIdx.x * blockDim.x + threadIdx.x) >> 5;
    if (w >= N_NODES) return;
    int lane = threadIdx.x & 31;
    float4 v  = ((const float4*)xw)[(size_t)w * 32 + lane];
    float4 as = ((const float4*)a_s)[lane];
    float4 ad = ((const float4*)a_d)[lane];
    float ps = v.x * as.x + v.y * as.y + v.z * as.z + v.w * as.w;
    float pd = v.x * ad.x + v.y * ad.y + v.z * ad.z + v.w * ad.w;
#pragma unroll
    for (int o = 16; o; o >>= 1) {
        ps += __shfl_xor_sync(0xffffffffu, ps, o);
        pd += __shfl_xor_sync(0xffffffffu, pd, o);
    }
    if (lane == 0) { g_s[w] = ps; g_d[w] = pd; }
}

// ---------------- GAT aggregate: register-cached single-gather -----------------
__global__ void gat_agg(const float* __restrict__ xw,
                        const float* __restrict__ bias,
                        float* __restrict__ out) {
    int w = (blockIdx.x * blockDim.x + threadIdx.x) >> 5;
    if (w >= N_NODES) return;
    int lane = threadIdx.x & 31;
    int beg = g_off[w], end = g_off[w + 1];
    int deg = end - beg;
    float dd = g_d[w];
    const float4* xw4 = (const float4*)xw;
    float4 acc = make_float4(0.f, 0.f, 0.f, 0.f);

    if (deg <= 64) {
        // cache src ids + scores in 2 regs/lane, broadcast via shfl in gather
        int p0 = beg + lane, p1 = beg + 32 + lane;
        int s0 = 0, s1 = 0;
        float e0 = -1e30f, e1 = -1e30f;
        if (p0 < end) {
            s0 = g_csr[p0];
            float t = g_s[s0] + dd;
            e0 = (t > 0.f) ? t : 0.2f * t;
        }
        if (p1 < end) {
            s1 = g_csr[p1];
            float t = g_s[s1] + dd;
            e1 = (t > 0.f) ? t : 0.2f * t;
        }
        float m = fmaxf(e0, e1);
#pragma unroll
        for (int o = 16; o; o >>= 1) m = fmaxf(m, __shfl_xor_sync(0xffffffffu, m, o));
        float ex0 = (p0 < end) ? __expf(e0 - m) : 0.f;
        float ex1 = (p1 < end) ? __expf(e1 - m) : 0.f;
        float sum = ex0 + ex1;
#pragma unroll
        for (int o = 16; o; o >>= 1) sum += __shfl_xor_sync(0xffffffffu, sum, o);
        float invden = 1.0f / sum;

        int idx = 0;
        for (; idx + 1 < deg; idx += 2) {
            float exa = __shfl_sync(0xffffffffu, idx < 32 ? ex0 : ex1, idx & 31);
            int   sa  = __shfl_sync(0xffffffffu, idx < 32 ? s0 : s1, idx & 31);
            float exb = __shfl_sync(0xffffffffu, (idx + 1) < 32 ? ex0 : ex1, (idx + 1) & 31);
            int   sb  = __shfl_sync(0xffffffffu, (idx + 1) < 32 ? s0 : s1, (idx + 1) & 31);
            float wa = exa * invden, wb = exb * invden;
            float4 va = xw4[(size_t)sa * 32 + lane];
            float4 vb = xw4[(size_t)sb * 32 + lane];
            acc.x += wa * va.x + wb * vb.x;
            acc.y += wa * va.y + wb * vb.y;
            acc.z += wa * va.z + wb * vb.z;
            acc.w += wa * va.w + wb * vb.w;
        }
        if (idx < deg) {
            float exa = __shfl_sync(0xffffffffu, idx < 32 ? ex0 : ex1, idx & 31);
            int   sa  = __shfl_sync(0xffffffffu, idx < 32 ? s0 : s1, idx & 31);
            float wa = exa * invden;
            float4 va = xw4[(size_t)sa * 32 + lane];
            acc.x += wa * va.x; acc.y += wa * va.y;
            acc.z += wa * va.z; acc.w += wa * va.w;
        }
    } else {
        // rare fallback: 3-pass via g_esc
        float m = -1e30f;
        for (int p = beg + lane; p < end; p += 32) {
            int s = g_csr[p];
            float e = g_s[s] + dd;
            e = (e > 0.f) ? e : 0.2f * e;
            g_esc[p] = e;
            m = fmaxf(m, e);
        }
#pragma unroll
        for (int o = 16; o; o >>= 1) m = fmaxf(m, __shfl_xor_sync(0xffffffffu, m, o));
        float sum = 0.f;
        for (int p = beg + lane; p < end; p += 32) {
            float ex = __expf(g_esc[p] - m);
            g_esc[p] = ex;
            sum += ex;
        }
#pragma unroll
        for (int o = 16; o; o >>= 1) sum += __shfl_xor_sync(0xffffffffu, sum, o);
        float invden = 1.0f / sum;
        __syncwarp();
        for (int p = beg; p < end; ++p) {
            int s = g_csr[p];
            float wgt = g_esc[p] * invden;
            float4 v = xw4[(size_t)s * 32 + lane];
            acc.x += wgt * v.x; acc.y += wgt * v.y;
            acc.z += wgt * v.z; acc.w += wgt * v.w;
        }
    }

    float4 b = ((const float4*)bias)[lane];
    acc.x = fmaxf(acc.x + b.x, 0.f);
    acc.y = fmaxf(acc.y + b.y, 0.f);
    acc.z = fmaxf(acc.z + b.z, 0.f);
    acc.w = fmaxf(acc.w + b.w, 0.f);
    ((float4*)out)[(size_t)w * 32 + lane] = acc;
}

// ---------------- host launch -----------------------------------------------------
extern "C" void kernel_launch(void* const* d_in, const int* in_sizes, int n_in,
                              void* d_out, int out_size) {
    const float* x     = (const float*)d_in[0];
    const void*  ei    = d_in[1];
    const float* W1    = (const float*)d_in[2];
    const float* b1    = (const float*)d_in[3];
    const float* Wg1   = (const float*)d_in[4];
    const float* asrc1 = (const float*)d_in[5];
    const float* adst1 = (const float*)d_in[6];
    const float* bg1   = (const float*)d_in[7];
    const float* W2    = (const float*)d_in[8];
    const float* b2    = (const float*)d_in[9];
    const float* Wg2   = (const float*)d_in[10];
    const float* asrc2 = (const float*)d_in[11];
    const float* adst2 = (const float*)d_in[12];
    const float* bg2   = (const float*)d_in[13];
    const float* Wo    = (const float*)d_in[14];
    const float* bo    = (const float*)d_in[15];

    float* out_h = (float*)d_out;
    float* out_z = out_h + (size_t)N_NODES * HD;

    float *pA = nullptr, *pB = nullptr;
    int* pCnt = nullptr;
    cudaGetSymbolAddress((void**)&pA, g_bufA);
    cudaGetSymbolAddress((void**)&pB, g_bufB);
    cudaGetSymbolAddress((void**)&pCnt, g_cnt);

    const int TB = 256;
    dim3 nb_node((N_NODES + TB - 1) / TB);
    dim3 nb_edge((N_EDGES + TB - 1) / TB);
    dim3 nb_warp(((size_t)N_NODES * 32 + TB - 1) / TB);
    dim3 nb_gemm((N_NODES + 127) / 128);

    const int SMEM128 = 65536 + 128 * 128 * 2 * 2;
    const int SMEM64  = 65536 + 128 * 64 * 2 * 2;
    cudaFuncSetAttribute(tc_gemm<128>, cudaFuncAttributeMaxDynamicSharedMemorySize, SMEM128);
    cudaFuncSetAttribute(tc_gemm<64>,  cudaFuncAttributeMaxDynamicSharedMemorySize, SMEM64);

    // CSR build
    k_detect<<<1, 1024>>>((const unsigned int*)ei);
    cudaMemsetAsync(pCnt, 0, N_NODES * sizeof(int));
    k_convert_count<<<nb_edge, TB>>>(ei);
    k_scan1<<<NB_SCAN, 1024>>>();
    k_scan2<<<1, 64>>>();
    k_scan3<<<NB_SCAN, 1024>>>();
    k_finalize<<<nb_node, TB>>>();
    k_fill_edges<<<nb_edge, TB>>>();

    // Layer 1: GCN
    k_wconv<<<32, 256>>>(W1, 128);
    tc_gemm<128><<<nb_gemm, TB, SMEM128>>>(x, nullptr, pA, N_NODES);
    gcn_agg<<<nb_warp, TB>>>(pA, b1, pB);

    // Layer 2: GAT
    k_wconv<<<32, 256>>>(Wg1, 128);
    tc_gemm<128><<<nb_gemm, TB, SMEM128>>>(pB, nullptr, pA, N_NODES);
    att_scores<<<nb_warp, TB>>>(pA, asrc1, adst1);
    gat_agg<<<nb_warp, TB>>>(pA, bg1, pB);

    // Layer 3: GCN
    k_wconv<<<32, 256>>>(W2, 128);
    tc_gemm<128><<<nb_gemm, TB, SMEM128>>>(pB, nullptr, pA, N_NODES);
    gcn_agg<<<nb_warp, TB>>>(pA, b2, pB);

    // Layer 4: GAT -> h into d_out
    k_wconv<<<32, 256>>>(Wg2, 128);
    tc_gemm<128><<<nb_gemm, TB, SMEM128>>>(pB, nullptr, pA, N_NODES);
    att_scores<<<nb_warp, TB>>>(pA, asrc2, adst2);
    gat_agg<<<nb_warp, TB>>>(pA, bg2, out_h);

    // Output head: z = h @ Wo + bo
    k_wconv<<<32, 256>>>(Wo, 64);
    tc_gemm<64><<<nb_gemm, TB, SMEM64>>>(out_h, bo, out_z, N_NODES);
}

// round 6
// speedup vs baseline: 1.2982x; 1.0273x over previous
#include <cuda_runtime.h>
#include <cuda_bf16.h>
#include <math.h>
#include <stdint.h>

// Problem constants
#define N_NODES 50000
#define N_EDGES 800000
#define TOT_E   850000
#define HD      128
#define NB_SCAN 49            // ceil(50000/1024)

// ---------------- device scratch --------------------------------------------
__device__ float g_bufA[(size_t)N_NODES * HD];
__device__ float g_bufB[(size_t)N_NODES * HD];
__device__ int   g_src[N_EDGES];
__device__ int   g_dst[N_EDGES];
__device__ int   g_flag;
__device__ int   g_cnt[N_NODES];
__device__ int   g_off[N_NODES + 1];    // local-scan scratch
__device__ int   g_off2[N_NODES + 1];   // final CSR offsets
__device__ int   g_csr[TOT_E];
__device__ int   g_bsum[64];
__device__ int   g_bpre[64];
__device__ float g_inv[N_NODES];
__device__ float g_s[N_NODES];
__device__ float g_d[N_NODES];
__device__ float g_esc[TOT_E];          // fallback only (deg > 64)
__device__ unsigned short g_wperm[5][2 * 128 * 128];

// ---------------- warp MMA helper --------------------------------------------
__device__ __forceinline__ void mma16816(float* d, const uint32_t* a, const uint32_t* b) {
    asm volatile(
        "mma.sync.aligned.m16n8k16.row.col.f32.bf16.bf16.f32 "
        "{%0,%1,%2,%3}, {%4,%5,%6,%7}, {%8,%9}, {%0,%1,%2,%3};"
        : "+f"(d[0]), "+f"(d[1]), "+f"(d[2]), "+f"(d[3])
        : "r"(a[0]), "r"(a[1]), "r"(a[2]), "r"(a[3]), "r"(b[0]), "r"(b[1]));
}

__device__ __forceinline__ uint32_t pack_bf16(float x, float y) {
    __nv_bfloat16 hx = __float2bfloat16(x), hy = __float2bfloat16(y);
    return (uint32_t)__bfloat16_as_ushort(hx) |
           ((uint32_t)__bfloat16_as_ushort(hy) << 16);
}

// ---------------- weight conversion: ALL weights, one launch ------------------
__global__ void k_wconv_all(const float* __restrict__ W1, const float* __restrict__ Wg1,
                            const float* __restrict__ W2, const float* __restrict__ Wg2,
                            const float* __restrict__ Wo) {
    int w = blockIdx.y;
    const float* W = (w == 0) ? W1 : (w == 1) ? Wg1 : (w == 2) ? W2 : (w == 3) ? Wg2 : Wo;
    int BN = (w == 4) ? 64 : 128;
    int total = 128 * BN;
    unsigned short* dst = g_wperm[w];
    for (int idx = blockIdx.x * blockDim.x + threadIdx.x; idx < total;
         idx += blockDim.x * gridDim.x) {
        int k = idx / BN, n = idx % BN;
        float v = W[idx];
        __nv_bfloat16 h = __float2bfloat16(v);
        __nv_bfloat16 l = __float2bfloat16(v - __bfloat162float(h));
        int nt = n >> 3, kt = k >> 4, kk = k & 15;
        int reg = kk >> 3, klo = kk & 7;
        int lane = (n & 7) * 4 + (klo >> 1);
        int slot = ((nt * 8 + kt) * 32 + lane) * 2 + reg;
        int pos = slot * 2 + (kk & 1);
        dst[pos] = __bfloat16_as_ushort(h);
        dst[total + pos] = __bfloat16_as_ushort(l);
    }
}

// ---------------- HMMA bf16x3 GEMM + optional fused attention dots -----------
template <int BN>
__global__ void __launch_bounds__(256)
tc_gemm(const float* __restrict__ X, const unsigned short* __restrict__ wperm,
        const float* __restrict__ bias, float* __restrict__ Y, int M,
        const float* __restrict__ a_s, const float* __restrict__ a_d) {
    extern __shared__ char smem[];
    constexpr int NT = BN / 16;
    constexpr int OFF_ALO = 32768;
    constexpr int OFF_B   = 65536;
    constexpr int B_HALF  = 128 * BN * 2;

    int tid  = threadIdx.x;
    int wid  = tid >> 5;
    int lane = tid & 31;
    int row0 = blockIdx.x * 128;

    {
        const uint4* src = (const uint4*)wperm;
        uint4* dst = (uint4*)(smem + OFF_B);
        int n16 = (2 * B_HALF) / 16;
        for (int i = tid; i < n16; i += 256) dst[i] = src[i];
    }
    {
        uint32_t* ah = (uint32_t*)smem;
        uint32_t* al = (uint32_t*)(smem + OFF_ALO);
#pragma unroll
        for (int it = 0; it < 16; ++it) {
            int idx = it * 256 + tid;
            int r = idx >> 5;
            int c = (idx & 31) * 4;
            int gr = row0 + r;
            float4 v = make_float4(0.f, 0.f, 0.f, 0.f);
            if (gr < M) v = *(const float4*)&X[(size_t)gr * 128 + c];
            __nv_bfloat16 h0 = __float2bfloat16(v.x), h1 = __float2bfloat16(v.y);
            __nv_bfloat16 h2 = __float2bfloat16(v.z), h3 = __float2bfloat16(v.w);
            float l0 = v.x - __bfloat162float(h0), l1 = v.y - __bfloat162float(h1);
            float l2 = v.z - __bfloat162float(h2), l3 = v.w - __bfloat162float(h3);
            uint32_t hi0 = (uint32_t)__bfloat16_as_ushort(h0) |
                           ((uint32_t)__bfloat16_as_ushort(h1) << 16);
            uint32_t hi1 = (uint32_t)__bfloat16_as_ushort(h2) |
                           ((uint32_t)__bfloat16_as_ushort(h3) << 16);
            uint32_t lo0 = pack_bf16(l0, l1);
            uint32_t lo1 = pack_bf16(l2, l3);
            int mt = r >> 4, rr = r & 15;
            int kt = c >> 4, cc = c & 15;
            int reg = ((cc >> 3) << 1) | (rr >> 3);
            int ln0 = (rr & 7) * 4 + ((cc & 7) >> 1);
            int base = (mt * 8 + kt) * 32;
            ah[(base + ln0) * 4 + reg]     = hi0;
            ah[(base + ln0 + 1) * 4 + reg] = hi1;
            al[(base + ln0) * 4 + reg]     = lo0;
            al[(base + ln0 + 1) * 4 + reg] = lo1;
        }
    }
    __syncthreads();

    int wm = wid & 3;
    int wn = wid >> 2;
    float acc[2][NT][4];
#pragma unroll
    for (int i = 0; i < 2; ++i)
#pragma unroll
        for (int j = 0; j < NT; ++j)
#pragma unroll
            for (int q = 0; q < 4; ++q) acc[i][j][q] = 0.f;

#pragma unroll
    for (int pass = 0; pass < 3; ++pass) {
        const uint4* Ab = (const uint4*)(smem + (pass == 2 ? OFF_ALO : 0));
        const uint2* Bb = (const uint2*)(smem + OFF_B + (pass == 1 ? B_HALF : 0));
#pragma unroll
        for (int kt = 0; kt < 8; ++kt) {
            uint4 a0 = Ab[((wm * 2 + 0) * 8 + kt) * 32 + lane];
            uint4 a1 = Ab[((wm * 2 + 1) * 8 + kt) * 32 + lane];
            uint2 b[NT];
#pragma unroll
            for (int j = 0; j < NT; ++j)
                b[j] = Bb[((wn * NT + j) * 8 + kt) * 32 + lane];
#pragma unroll
            for (int j = 0; j < NT; ++j) {
                mma16816(acc[0][j], (const uint32_t*)&a0, (const uint32_t*)&b[j]);
                mma16816(acc[1][j], (const uint32_t*)&a1, (const uint32_t*)&b[j]);
            }
        }
    }

    int rbase = row0 + wm * 32 + (lane >> 2);
    int cbase = wn * NT * 8 + (lane & 3) * 2;
#pragma unroll
    for (int i = 0; i < 2; ++i) {
        int r = rbase + i * 16;
#pragma unroll
        for (int j = 0; j < NT; ++j) {
            int cc = cbase + j * 8;
            float bx = 0.f, by = 0.f;
            if (bias) { bx = bias[cc]; by = bias[cc + 1]; }
            if (r < M) {
                float2 v0 = make_float2(acc[i][j][0] + bx, acc[i][j][1] + by);
                *(float2*)&Y[(size_t)r * BN + cc] = v0;
            }
            if (r + 8 < M) {
                float2 v1 = make_float2(acc[i][j][2] + bx, acc[i][j][3] + by);
                *(float2*)&Y[(size_t)(r + 8) * BN + cc] = v1;
            }
        }
    }

    // fused attention pre-dots: partial dot over this warp's 64 cols, reduce
    // across the 4 lanes of each row, atomicAdd into g_s/g_d (zeroed upstream)
    if (a_s) {
        float ps[2][2] = {{0.f, 0.f}, {0.f, 0.f}};
        float pd[2][2] = {{0.f, 0.f}, {0.f, 0.f}};
#pragma unroll
        for (int i = 0; i < 2; ++i)
#pragma unroll
            for (int j = 0; j < NT; ++j) {
                int cc = cbase + j * 8;
                float as0 = a_s[cc], as1 = a_s[cc + 1];
                float ad0 = a_d[cc], ad1 = a_d[cc + 1];
                ps[i][0] += acc[i][j][0] * as0 + acc[i][j][1] * as1;
                pd[i][0] += acc[i][j][0] * ad0 + acc[i][j][1] * ad1;
                ps[i][1] += acc[i][j][2] * as0 + acc[i][j][3] * as1;
                pd[i][1] += acc[i][j][2] * ad0 + acc[i][j][3] * ad1;
            }
#pragma unroll
        for (int i = 0; i < 2; ++i)
#pragma unroll
            for (int h = 0; h < 2; ++h) {
                float s = ps[i][h], d = pd[i][h];
                s += __shfl_xor_sync(0xffffffffu, s, 1);
                s += __shfl_xor_sync(0xffffffffu, s, 2);
                d += __shfl_xor_sync(0xffffffffu, d, 1);
                d += __shfl_xor_sync(0xffffffffu, d, 2);
                if ((lane & 3) == 0) {
                    int r = row0 + wm * 32 + i * 16 + h * 8 + (lane >> 2);
                    if (r < M) {
                        atomicAdd(&g_s[r], s);
                        atomicAdd(&g_d[r], d);
                    }
                }
            }
    }
}

// ---------------- edge dtype detect -------------------------------------------
__global__ void k_detect(const unsigned int* __restrict__ w) {
    __shared__ int sflag;
    if (threadIdx.x == 0) sflag = 0;
    __syncthreads();
    if (w[2 * threadIdx.x + 1] != 0u) atomicOr(&sflag, 1);
    __syncthreads();
    if (threadIdx.x == 0) g_flag = sflag;
}

// fused convert + degree count (g_cnt pre-zeroed by memset)
__global__ void k_convert_count(const void* __restrict__ ei) {
    int e = blockIdx.x * blockDim.x + threadIdx.x;
    if (e >= N_EDGES) return;
    int s, d;
    if (g_flag) {
        const int* p = (const int*)ei;
        s = p[e]; d = p[N_EDGES + e];
    } else {
        const long long* p = (const long long*)ei;
        s = (int)p[e]; d = (int)p[N_EDGES + e];
    }
    g_src[e] = s;
    g_dst[e] = d;
    atomicAdd(&g_cnt[d], 1);
}

// ---------------- multi-block scan -------------------------------------------
__global__ void k_scan1() {
    __shared__ int sd[1024];
    int tid = threadIdx.x;
    int i = blockIdx.x * 1024 + tid;
    int v = (i < N_NODES) ? g_cnt[i] + 1 : 0;   // +1 = self loop
    sd[tid] = v;
    __syncthreads();
    for (int off = 1; off < 1024; off <<= 1) {
        int t = (tid >= off) ? sd[tid - off] : 0;
        __syncthreads();
        sd[tid] += t;
        __syncthreads();
    }
    if (i < N_NODES) g_off[i] = sd[tid] - v;
    if (tid == 1023) g_bsum[blockIdx.x] = sd[1023];
}

__global__ void k_scan2() {
    __shared__ int sd[64];
    int tid = threadIdx.x;
    int v = (tid < NB_SCAN) ? g_bsum[tid] : 0;
    sd[tid] = v;
    __syncthreads();
    for (int off = 1; off < 64; off <<= 1) {
        int t = (tid >= off) ? sd[tid - off] : 0;
        __syncthreads();
        sd[tid] += t;
        __syncthreads();
    }
    if (tid < NB_SCAN) g_bpre[tid] = sd[tid] - v;
    if (tid == 63) g_off[N_NODES] = sd[63];
}

// fused scan add-back + finalize: writes final offsets to g_off2
__global__ void k_scan3_fin() {
    int i = blockIdx.x * 1024 + threadIdx.x;
    if (i >= N_NODES) return;
    int b = g_off[i] + g_bpre[i >> 10];
    int e = (i + 1 == N_NODES) ? g_off[N_NODES]
                               : g_off[i + 1] + g_bpre[(i + 1) >> 10];
    g_off2[i] = b;
    if (i + 1 == N_NODES) g_off2[N_NODES] = g_off[N_NODES];
    g_csr[b] = i;          // self loop
    g_cnt[i] = b + 1;      // fill cursor
    g_inv[i] = rsqrtf((float)(e - b));
}

__global__ void k_fill_edges() {
    int e = blockIdx.x * blockDim.x + threadIdx.x;
    if (e < N_EDGES) {
        int pos = atomicAdd(&g_cnt[g_dst[e]], 1);
        g_csr[pos] = g_src[e];
    }
}

// ---------------- GCN aggregate (also zeroes g_s/g_d for next GAT layer) ------
__global__ void gcn_agg(const float* __restrict__ xw,
                        const float* __restrict__ bias,
                        float* __restrict__ out) {
    int w = (blockIdx.x * blockDim.x + threadIdx.x) >> 5;
    if (w >= N_NODES) return;
    int lane = threadIdx.x & 31;
    if (lane == 0) { g_s[w] = 0.f; g_d[w] = 0.f; }
    int beg = g_off2[w], end = g_off2[w + 1];
    float invd = g_inv[w];
    const float4* xw4 = (const float4*)xw;
    float4 acc = make_float4(0.f, 0.f, 0.f, 0.f);
    int p = beg;
    for (; p + 1 < end; p += 2) {
        int s0 = g_csr[p], s1 = g_csr[p + 1];
        float c0 = invd * g_inv[s0];
        float c1 = invd * g_inv[s1];
        float4 v0 = xw4[(size_t)s0 * 32 + lane];
        float4 v1 = xw4[(size_t)s1 * 32 + lane];
        acc.x += c0 * v0.x + c1 * v1.x;
        acc.y += c0 * v0.y + c1 * v1.y;
        acc.z += c0 * v0.z + c1 * v1.z;
        acc.w += c0 * v0.w + c1 * v1.w;
    }
    if (p < end) {
        int s0 = g_csr[p];
        float c0 = invd * g_inv[s0];
        float4 v0 = xw4[(size_t)s0 * 32 + lane];
        acc.x += c0 * v0.x; acc.y += c0 * v0.y;
        acc.z += c0 * v0.z; acc.w += c0 * v0.w;
    }
    float4 b = ((const float4*)bias)[lane];
    acc.x = fmaxf(acc.x + b.x, 0.f);
    acc.y = fmaxf(acc.y + b.y, 0.f);
    acc.z = fmaxf(acc.z + b.z, 0.f);
    acc.w = fmaxf(acc.w + b.w, 0.f);
    ((float4*)out)[(size_t)w * 32 + lane] = acc;
}

// ---------------- GAT aggregate: register-cached single-gather ----------------
__global__ void gat_agg(const float* __restrict__ xw,
                        const float* __restrict__ bias,
                        float* __restrict__ out) {
    int w = (blockIdx.x * blockDim.x + threadIdx.x) >> 5;
    if (w >= N_NODES) return;
    int lane = threadIdx.x & 31;
    int beg = g_off2[w], end = g_off2[w + 1];
    int deg = end - beg;
    float dd = g_d[w];
    const float4* xw4 = (const float4*)xw;
    float4 acc = make_float4(0.f, 0.f, 0.f, 0.f);

    if (deg <= 64) {
        int p0 = beg + lane, p1 = beg + 32 + lane;
        int s0 = 0, s1 = 0;
        float e0 = -1e30f, e1 = -1e30f;
        if (p0 < end) {
            s0 = g_csr[p0];
            float t = g_s[s0] + dd;
            e0 = (t > 0.f) ? t : 0.2f * t;
        }
        if (p1 < end) {
            s1 = g_csr[p1];
            float t = g_s[s1] + dd;
            e1 = (t > 0.f) ? t : 0.2f * t;
        }
        float m = fmaxf(e0, e1);
#pragma unroll
        for (int o = 16; o; o >>= 1) m = fmaxf(m, __shfl_xor_sync(0xffffffffu, m, o));
        float ex0 = (p0 < end) ? __expf(e0 - m) : 0.f;
        float ex1 = (p1 < end) ? __expf(e1 - m) : 0.f;
        float sum = ex0 + ex1;
#pragma unroll
        for (int o = 16; o; o >>= 1) sum += __shfl_xor_sync(0xffffffffu, sum, o);
        float invden = 1.0f / sum;

        int idx = 0;
        for (; idx + 1 < deg; idx += 2) {
            float exa = __shfl_sync(0xffffffffu, idx < 32 ? ex0 : ex1, idx & 31);
            int   sa  = __shfl_sync(0xffffffffu, idx < 32 ? s0 : s1, idx & 31);
            float exb = __shfl_sync(0xffffffffu, (idx + 1) < 32 ? ex0 : ex1, (idx + 1) & 31);
            int   sb  = __shfl_sync(0xffffffffu, (idx + 1) < 32 ? s0 : s1, (idx + 1) & 31);
            float wa = exa * invden, wb = exb * invden;
            float4 va = xw4[(size_t)sa * 32 + lane];
            float4 vb = xw4[(size_t)sb * 32 + lane];
            acc.x += wa * va.x + wb * vb.x;
            acc.y += wa * va.y + wb * vb.y;
            acc.z += wa * va.z + wb * vb.z;
            acc.w += wa * va.w + wb * vb.w;
        }
        if (idx < deg) {
            float exa = __shfl_sync(0xffffffffu, idx < 32 ? ex0 : ex1, idx & 31);
            int   sa  = __shfl_sync(0xffffffffu, idx < 32 ? s0 : s1, idx & 31);
            float wa = exa * invden;
            float4 va = xw4[(size_t)sa * 32 + lane];
            acc.x += wa * va.x; acc.y += wa * va.y;
            acc.z += wa * va.z; acc.w += wa * va.w;
        }
    } else {
        float m = -1e30f;
        for (int p = beg + lane; p < end; p += 32) {
            int s = g_csr[p];
            float e = g_s[s] + dd;
            e = (e > 0.f) ? e : 0.2f * e;
            g_esc[p] = e;
            m = fmaxf(m, e);
        }
#pragma unroll
        for (int o = 16; o; o >>= 1) m = fmaxf(m, __shfl_xor_sync(0xffffffffu, m, o));
        float sum = 0.f;
        for (int p = beg + lane; p < end; p += 32) {
            float ex = __expf(g_esc[p] - m);
            g_esc[p] = ex;
            sum += ex;
        }
#pragma unroll
        for (int o = 16; o; o >>= 1) sum += __shfl_xor_sync(0xffffffffu, sum, o);
        float invden = 1.0f / sum;
        __syncwarp();
        for (int p = beg; p < end; ++p) {
            int s = g_csr[p];
            float wgt = g_esc[p] * invden;
            float4 v = xw4[(size_t)s * 32 + lane];
            acc.x += wgt * v.x; acc.y += wgt * v.y;
            acc.z += wgt * v.z; acc.w += wgt * v.w;
        }
    }

    float4 b = ((const float4*)bias)[lane];
    acc.x = fmaxf(acc.x + b.x, 0.f);
    acc.y = fmaxf(acc.y + b.y, 0.f);
    acc.z = fmaxf(acc.z + b.z, 0.f);
    acc.w = fmaxf(acc.w + b.w, 0.f);
    ((float4*)out)[(size_t)w * 32 + lane] = acc;
}

// ---------------- host launch ---------------------------------------------------
extern "C" void kernel_launch(void* const* d_in, const int* in_sizes, int n_in,
                              void* d_out, int out_size) {
    const float* x     = (const float*)d_in[0];
    const void*  ei    = d_in[1];
    const float* W1    = (const float*)d_in[2];
    const float* b1    = (const float*)d_in[3];
    const float* Wg1   = (const float*)d_in[4];
    const float* asrc1 = (const float*)d_in[5];
    const float* adst1 = (const float*)d_in[6];
    const float* bg1   = (const float*)d_in[7];
    const float* W2    = (const float*)d_in[8];
    const float* b2    = (const float*)d_in[9];
    const float* Wg2   = (const float*)d_in[10];
    const float* asrc2 = (const float*)d_in[11];
    const float* adst2 = (const float*)d_in[12];
    const float* bg2   = (const float*)d_in[13];
    const float* Wo    = (const float*)d_in[14];
    const float* bo    = (const float*)d_in[15];

    float* out_h = (float*)d_out;
    float* out_z = out_h + (size_t)N_NODES * HD;

    float *pA = nullptr, *pB = nullptr;
    int* pCnt = nullptr;
    unsigned short* pW = nullptr;
    cudaGetSymbolAddress((void**)&pA, g_bufA);
    cudaGetSymbolAddress((void**)&pB, g_bufB);
    cudaGetSymbolAddress((void**)&pCnt, g_cnt);
    cudaGetSymbolAddress((void**)&pW, g_wperm);
    const size_t WSTRIDE = 2 * 128 * 128;

    const int TB = 256;
    dim3 nb_node((N_NODES + TB - 1) / TB);
    dim3 nb_edge((N_EDGES + TB - 1) / TB);
    dim3 nb_warp(((size_t)N_NODES * 32 + TB - 1) / TB);
    dim3 nb_gemm((N_NODES + 127) / 128);

    const int SMEM128 = 65536 + 128 * 128 * 2 * 2;
    const int SMEM64  = 65536 + 128 * 64 * 2 * 2;
    cudaFuncSetAttribute(tc_gemm<128>, cudaFuncAttributeMaxDynamicSharedMemorySize, SMEM128);
    cudaFuncSetAttribute(tc_gemm<64>,  cudaFuncAttributeMaxDynamicSharedMemorySize, SMEM64);

    // CSR build + weight conversion
    k_detect<<<1, 1024>>>((const unsigned int*)ei);
    cudaMemsetAsync(pCnt, 0, N_NODES * sizeof(int));
    k_wconv_all<<<dim3(36, 5), TB>>>(W1, Wg1, W2, Wg2, Wo);
    k_convert_count<<<nb_edge, TB>>>(ei);
    k_scan1<<<NB_SCAN, 1024>>>();
    k_scan2<<<1, 64>>>();
    k_scan3_fin<<<NB_SCAN, 1024>>>();
    k_fill_edges<<<nb_edge, TB>>>();

    // Layer 1: GCN (gcn_agg zeroes g_s/g_d for layer 2)
    tc_gemm<128><<<nb_gemm, TB, SMEM128>>>(x, pW, nullptr, pA, N_NODES, nullptr, nullptr);
    gcn_agg<<<nb_warp, TB>>>(pA, b1, pB);

    // Layer 2: GAT (att dots fused into GEMM epilogue)
    tc_gemm<128><<<nb_gemm, TB, SMEM128>>>(pB, pW + WSTRIDE, nullptr, pA, N_NODES, asrc1, adst1);
    gat_agg<<<nb_warp, TB>>>(pA, bg1, pB);

    // Layer 3: GCN (gcn_agg zeroes g_s/g_d for layer 4)
    tc_gemm<128><<<nb_gemm, TB, SMEM128>>>(pB, pW + 2 * WSTRIDE, nullptr, pA, N_NODES, nullptr, nullptr);
    gcn_agg<<<nb_warp, TB>>>(pA, b2, pB);

    // Layer 4: GAT -> h into d_out
    tc_gemm<128><<<nb_gemm, TB, SMEM128>>>(pB, pW + 3 * WSTRIDE, nullptr, pA, N_NODES, asrc2, adst2);
    gat_agg<<<nb_warp, TB>>>(pA, bg2, out_h);

    // Output head: z = h @ Wo + bo
    tc_gemm<64><<<nb_gemm, TB, SMEM64>>>(out_h, pW + 4 * WSTRIDE, bo, out_z, N_NODES, nullptr, nullptr);
}

// round 7
// speedup vs baseline: 1.3626x; 1.0496x over previous
#include <cuda_runtime.h>
#include <cuda_bf16.h>
#include <math.h>
#include <stdint.h>

// Problem constants
#define N_NODES 50000
#define N_EDGES 800000
#define TOT_E   850000
#define HD      128
#define NB_SCAN 49            // ceil(50000/1024)

// ---------------- device scratch --------------------------------------------
__device__ float g_bufA[(size_t)N_NODES * HD];
__device__ float g_bufB[(size_t)N_NODES * HD];
__device__ int   g_src[N_EDGES];
__device__ int   g_dst[N_EDGES];
__device__ int   g_flag;
__device__ int   g_cnt[N_NODES];
__device__ int   g_off[N_NODES + 1];    // local-scan scratch
__device__ int   g_off2[N_NODES + 1];   // final CSR offsets
__device__ int   g_csr[TOT_E];
__device__ int   g_bsum[64];
__device__ int   g_bpre[64];
__device__ float g_inv[N_NODES];
__device__ float g_s[N_NODES];
__device__ float g_d[N_NODES];
__device__ float g_esc[TOT_E];          // fallback only (deg > 64)
__device__ unsigned short g_wperm[5][2 * 128 * 128];

// ---------------- warp MMA helper --------------------------------------------
__device__ __forceinline__ void mma16816(float* d, const uint32_t* a, const uint32_t* b) {
    asm volatile(
        "mma.sync.aligned.m16n8k16.row.col.f32.bf16.bf16.f32 "
        "{%0,%1,%2,%3}, {%4,%5,%6,%7}, {%8,%9}, {%0,%1,%2,%3};"
        : "+f"(d[0]), "+f"(d[1]), "+f"(d[2]), "+f"(d[3])
        : "r"(a[0]), "r"(a[1]), "r"(a[2]), "r"(a[3]), "r"(b[0]), "r"(b[1]));
}

__device__ __forceinline__ uint32_t pack_bf16(float x, float y) {
    __nv_bfloat16 hx = __float2bfloat16(x), hy = __float2bfloat16(y);
    return (uint32_t)__bfloat16_as_ushort(hx) |
           ((uint32_t)__bfloat16_as_ushort(hy) << 16);
}

// ---------------- pre: zero counts + (block 0) detect edge dtype --------------
__global__ void k_pre(const unsigned int* __restrict__ w) {
    int i = blockIdx.x * 1024 + threadIdx.x;
    if (i < N_NODES) g_cnt[i] = 0;
    if (blockIdx.x == 0) {
        __shared__ int sflag;
        if (threadIdx.x == 0) sflag = 0;
        __syncthreads();
        if (w[2 * threadIdx.x + 1] != 0u) atomicOr(&sflag, 1);
        __syncthreads();
        if (threadIdx.x == 0) g_flag = sflag;
    }
}

// ---------------- fused: edge convert+count (y=0) | weight conversion (y=1) --
__global__ void k_convert_count(const void* __restrict__ ei,
                                const float* __restrict__ W1, const float* __restrict__ Wg1,
                                const float* __restrict__ W2, const float* __restrict__ Wg2,
                                const float* __restrict__ Wo) {
    if (blockIdx.y == 0) {
        int e = blockIdx.x * blockDim.x + threadIdx.x;
        if (e >= N_EDGES) return;
        int s, d;
        if (g_flag) {
            const int* p = (const int*)ei;
            s = p[e]; d = p[N_EDGES + e];
        } else {
            const long long* p = (const long long*)ei;
            s = (int)p[e]; d = (int)p[N_EDGES + e];
        }
        g_src[e] = s;
        g_dst[e] = d;
        atomicAdd(&g_cnt[d], 1);
    } else {
        int idx = blockIdx.x * blockDim.x + threadIdx.x;
        if (idx >= 4 * 16384 + 8192) return;
        int wsel, base, BN;
        if (idx < 16384)      { wsel = 0; base = 0;      BN = 128; }
        else if (idx < 32768) { wsel = 1; base = 16384;  BN = 128; }
        else if (idx < 49152) { wsel = 2; base = 32768;  BN = 128; }
        else if (idx < 65536) { wsel = 3; base = 49152;  BN = 128; }
        else                  { wsel = 4; base = 65536;  BN = 64;  }
        const float* W = (wsel == 0) ? W1 : (wsel == 1) ? Wg1 : (wsel == 2) ? W2
                       : (wsel == 3) ? Wg2 : Wo;
        int li = idx - base;
        int total = 128 * BN;
        int k = li / BN, n = li % BN;
        float v = W[li];
        __nv_bfloat16 h = __float2bfloat16(v);
        __nv_bfloat16 l = __float2bfloat16(v - __bfloat162float(h));
        int nt = n >> 3, kt = k >> 4, kk = k & 15;
        int reg = kk >> 3, klo = kk & 7;
        int lane = (n & 7) * 4 + (klo >> 1);
        int slot = ((nt * 8 + kt) * 32 + lane) * 2 + reg;
        int pos = slot * 2 + (kk & 1);
        g_wperm[wsel][pos] = __bfloat16_as_ushort(h);
        g_wperm[wsel][total + pos] = __bfloat16_as_ushort(l);
    }
}

// ---------------- multi-block scan -------------------------------------------
__global__ void k_scan1() {
    __shared__ int sd[1024];
    int tid = threadIdx.x;
    int i = blockIdx.x * 1024 + tid;
    int v = (i < N_NODES) ? g_cnt[i] + 1 : 0;   // +1 = self loop
    sd[tid] = v;
    __syncthreads();
    for (int off = 1; off < 1024; off <<= 1) {
        int t = (tid >= off) ? sd[tid - off] : 0;
        __syncthreads();
        sd[tid] += t;
        __syncthreads();
    }
    if (i < N_NODES) g_off[i] = sd[tid] - v;
    if (tid == 1023) g_bsum[blockIdx.x] = sd[1023];
}

__global__ void k_scan2() {
    __shared__ int sd[64];
    int tid = threadIdx.x;
    int v = (tid < NB_SCAN) ? g_bsum[tid] : 0;
    sd[tid] = v;
    __syncthreads();
    for (int off = 1; off < 64; off <<= 1) {
        int t = (tid >= off) ? sd[tid - off] : 0;
        __syncthreads();
        sd[tid] += t;
        __syncthreads();
    }
    if (tid < NB_SCAN) g_bpre[tid] = sd[tid] - v;
    if (tid == 63) g_off[N_NODES] = sd[63];
}

__global__ void k_scan3_fin() {
    int i = blockIdx.x * 1024 + threadIdx.x;
    if (i >= N_NODES) return;
    int b = g_off[i] + g_bpre[i >> 10];
    int e = (i + 1 == N_NODES) ? g_off[N_NODES]
                               : g_off[i + 1] + g_bpre[(i + 1) >> 10];
    g_off2[i] = b;
    if (i + 1 == N_NODES) g_off2[N_NODES] = g_off[N_NODES];
    g_csr[b] = i;          // self loop
    g_cnt[i] = b + 1;      // fill cursor
    g_inv[i] = rsqrtf((float)(e - b));
}

__global__ void k_fill_edges() {
    int e = blockIdx.x * blockDim.x + threadIdx.x;
    if (e < N_EDGES) {
        int pos = atomicAdd(&g_cnt[g_dst[e]], 1);
        g_csr[pos] = g_src[e];
    }
}

// ---------------- HMMA bf16x3 GEMM + optional fused attention dots -----------
// Mainloop restructured: per kt, load Ahi+Alo+Bhi once -> AhiBhi + AloBhi,
// then Blo -> AhiBlo. 192 B/lane/kt instead of 288.
template <int BN>
__global__ void __launch_bounds__(256)
tc_gemm(const float* __restrict__ X, const unsigned short* __restrict__ wperm,
        const float* __restrict__ bias, float* __restrict__ Y, int M,
        const float* __restrict__ a_s, const float* __restrict__ a_d) {
    extern __shared__ char smem[];
    constexpr int NT = BN / 16;
    constexpr int OFF_ALO = 32768;
    constexpr int OFF_B   = 65536;
    constexpr int B_HALF  = 128 * BN * 2;

    int tid  = threadIdx.x;
    int wid  = tid >> 5;
    int lane = tid & 31;
    int row0 = blockIdx.x * 128;

    {
        const uint4* src = (const uint4*)wperm;
        uint4* dst = (uint4*)(smem + OFF_B);
        int n16 = (2 * B_HALF) / 16;
        for (int i = tid; i < n16; i += 256) dst[i] = src[i];
    }
    {
        uint32_t* ah = (uint32_t*)smem;
        uint32_t* al = (uint32_t*)(smem + OFF_ALO);
#pragma unroll
        for (int it = 0; it < 16; ++it) {
            int idx = it * 256 + tid;
            int r = idx >> 5;
            int c = (idx & 31) * 4;
            int gr = row0 + r;
            float4 v = make_float4(0.f, 0.f, 0.f, 0.f);
            if (gr < M) v = *(const float4*)&X[(size_t)gr * 128 + c];
            __nv_bfloat16 h0 = __float2bfloat16(v.x), h1 = __float2bfloat16(v.y);
            __nv_bfloat16 h2 = __float2bfloat16(v.z), h3 = __float2bfloat16(v.w);
            float l0 = v.x - __bfloat162float(h0), l1 = v.y - __bfloat162float(h1);
            float l2 = v.z - __bfloat162float(h2), l3 = v.w - __bfloat162float(h3);
            uint32_t hi0 = (uint32_t)__bfloat16_as_ushort(h0) |
                           ((uint32_t)__bfloat16_as_ushort(h1) << 16);
            uint32_t hi1 = (uint32_t)__bfloat16_as_ushort(h2) |
                           ((uint32_t)__bfloat16_as_ushort(h3) << 16);
            uint32_t lo0 = pack_bf16(l0, l1);
            uint32_t lo1 = pack_bf16(l2, l3);
            int mt = r >> 4, rr = r & 15;
            int kt = c >> 4, cc = c & 15;
            int reg = ((cc >> 3) << 1) | (rr >> 3);
            int ln0 = (rr & 7) * 4 + ((cc & 7) >> 1);
            int base = (mt * 8 + kt) * 32;
            ah[(base + ln0) * 4 + reg]     = hi0;
            ah[(base + ln0 + 1) * 4 + reg] = hi1;
            al[(base + ln0) * 4 + reg]     = lo0;
            al[(base + ln0 + 1) * 4 + reg] = lo1;
        }
    }
    __syncthreads();

    int wm = wid & 3;
    int wn = wid >> 2;
    float acc[2][NT][4];
#pragma unroll
    for (int i = 0; i < 2; ++i)
#pragma unroll
        for (int j = 0; j < NT; ++j)
#pragma unroll
            for (int q = 0; q < 4; ++q) acc[i][j][q] = 0.f;

    const uint4* Ah = (const uint4*)smem;
    const uint4* Al = (const uint4*)(smem + OFF_ALO);
    const uint2* Bh = (const uint2*)(smem + OFF_B);
    const uint2* Bl = (const uint2*)(smem + OFF_B + B_HALF);
#pragma unroll
    for (int kt = 0; kt < 8; ++kt) {
        uint4 ah0 = Ah[((wm * 2 + 0) * 8 + kt) * 32 + lane];
        uint4 ah1 = Ah[((wm * 2 + 1) * 8 + kt) * 32 + lane];
        uint4 al0 = Al[((wm * 2 + 0) * 8 + kt) * 32 + lane];
        uint4 al1 = Al[((wm * 2 + 1) * 8 + kt) * 32 + lane];
        uint2 b[NT];
#pragma unroll
        for (int j = 0; j < NT; ++j)
            b[j] = Bh[((wn * NT + j) * 8 + kt) * 32 + lane];
#pragma unroll
        for (int j = 0; j < NT; ++j) {
            mma16816(acc[0][j], (const uint32_t*)&ah0, (const uint32_t*)&b[j]);
            mma16816(acc[1][j], (const uint32_t*)&ah1, (const uint32_t*)&b[j]);
        }
#pragma unroll
        for (int j = 0; j < NT; ++j) {
            mma16816(acc[0][j], (const uint32_t*)&al0, (const uint32_t*)&b[j]);
            mma16816(acc[1][j], (const uint32_t*)&al1, (const uint32_t*)&b[j]);
        }
#pragma unroll
        for (int j = 0; j < NT; ++j)
            b[j] = Bl[((wn * NT + j) * 8 + kt) * 32 + lane];
#pragma unroll
        for (int j = 0; j < NT; ++j) {
            mma16816(acc[0][j], (const uint32_t*)&ah0, (const uint32_t*)&b[j]);
            mma16816(acc[1][j], (const uint32_t*)&ah1, (const uint32_t*)&b[j]);
        }
    }

    int rbase = row0 + wm * 32 + (lane >> 2);
    int cbase = wn * NT * 8 + (lane & 3) * 2;
#pragma unroll
    for (int i = 0; i < 2; ++i) {
        int r = rbase + i * 16;
#pragma unroll
        for (int j = 0; j < NT; ++j) {
            int cc = cbase + j * 8;
            float bx = 0.f, by = 0.f;
            if (bias) { bx = bias[cc]; by = bias[cc + 1]; }
            if (r < M) {
                float2 v0 = make_float2(acc[i][j][0] + bx, acc[i][j][1] + by);
                *(float2*)&Y[(size_t)r * BN + cc] = v0;
            }
            if (r + 8 < M) {
                float2 v1 = make_float2(acc[i][j][2] + bx, acc[i][j][3] + by);
                *(float2*)&Y[(size_t)(r + 8) * BN + cc] = v1;
            }
        }
    }

    if (a_s) {
        float ps[2][2] = {{0.f, 0.f}, {0.f, 0.f}};
        float pd[2][2] = {{0.f, 0.f}, {0.f, 0.f}};
#pragma unroll
        for (int i = 0; i < 2; ++i)
#pragma unroll
            for (int j = 0; j < NT; ++j) {
                int cc = cbase + j * 8;
                float as0 = a_s[cc], as1 = a_s[cc + 1];
                float ad0 = a_d[cc], ad1 = a_d[cc + 1];
                ps[i][0] += acc[i][j][0] * as0 + acc[i][j][1] * as1;
                pd[i][0] += acc[i][j][0] * ad0 + acc[i][j][1] * ad1;
                ps[i][1] += acc[i][j][2] * as0 + acc[i][j][3] * as1;
                pd[i][1] += acc[i][j][2] * ad0 + acc[i][j][3] * ad1;
            }
#pragma unroll
        for (int i = 0; i < 2; ++i)
#pragma unroll
            for (int h = 0; h < 2; ++h) {
                float s = ps[i][h], d = pd[i][h];
                s += __shfl_xor_sync(0xffffffffu, s, 1);
                s += __shfl_xor_sync(0xffffffffu, s, 2);
                d += __shfl_xor_sync(0xffffffffu, d, 1);
                d += __shfl_xor_sync(0xffffffffu, d, 2);
                if ((lane & 3) == 0) {
                    int r = row0 + wm * 32 + i * 16 + h * 8 + (lane >> 2);
                    if (r < M) {
                        atomicAdd(&g_s[r], s);
                        atomicAdd(&g_d[r], d);
                    }
                }
            }
    }
}

// ---------------- GCN aggregate (also zeroes g_s/g_d for next GAT layer) ------
__global__ void gcn_agg(const float* __restrict__ xw,
                        const float* __restrict__ bias,
                        float* __restrict__ out) {
    int w = (blockIdx.x * blockDim.x + threadIdx.x) >> 5;
    if (w >= N_NODES) return;
    int lane = threadIdx.x & 31;
    if (lane == 0) { g_s[w] = 0.f; g_d[w] = 0.f; }
    int beg = g_off2[w], end = g_off2[w + 1];
    float invd = g_inv[w];
    const float4* xw4 = (const float4*)xw;
    float4 acc = make_float4(0.f, 0.f, 0.f, 0.f);
    int p = beg;
    for (; p + 1 < end; p += 2) {
        int s0 = g_csr[p], s1 = g_csr[p + 1];
        float c0 = invd * g_inv[s0];
        float c1 = invd * g_inv[s1];
        float4 v0 = xw4[(size_t)s0 * 32 + lane];
        float4 v1 = xw4[(size_t)s1 * 32 + lane];
        acc.x += c0 * v0.x + c1 * v1.x;
        acc.y += c0 * v0.y + c1 * v1.y;
        acc.z += c0 * v0.z + c1 * v1.z;
        acc.w += c0 * v0.w + c1 * v1.w;
    }
    if (p < end) {
        int s0 = g_csr[p];
        float c0 = invd * g_inv[s0];
        float4 v0 = xw4[(size_t)s0 * 32 + lane];
        acc.x += c0 * v0.x; acc.y += c0 * v0.y;
        acc.z += c0 * v0.z; acc.w += c0 * v0.w;
    }
    float4 b = ((const float4*)bias)[lane];
    acc.x = fmaxf(acc.x + b.x, 0.f);
    acc.y = fmaxf(acc.y + b.y, 0.f);
    acc.z = fmaxf(acc.z + b.z, 0.f);
    acc.w = fmaxf(acc.w + b.w, 0.f);
    ((float4*)out)[(size_t)w * 32 + lane] = acc;
}

// ---------------- GAT aggregate: register-cached single-gather ----------------
__global__ void gat_agg(const float* __restrict__ xw,
                        const float* __restrict__ bias,
                        float* __restrict__ out) {
    int w = (blockIdx.x * blockDim.x + threadIdx.x) >> 5;
    if (w >= N_NODES) return;
    int lane = threadIdx.x & 31;
    int beg = g_off2[w], end = g_off2[w + 1];
    int deg = end - beg;
    float dd = g_d[w];
    const float4* xw4 = (const float4*)xw;
    float4 acc = make_float4(0.f, 0.f, 0.f, 0.f);

    if (deg <= 64) {
        int p0 = beg + lane, p1 = beg + 32 + lane;
        int s0 = 0, s1 = 0;
        float e0 = -1e30f, e1 = -1e30f;
        if (p0 < end) {
            s0 = g_csr[p0];
            float t = g_s[s0] + dd;
            e0 = (t > 0.f) ? t : 0.2f * t;
        }
        if (p1 < end) {
            s1 = g_csr[p1];
            float t = g_s[s1] + dd;
            e1 = (t > 0.f) ? t : 0.2f * t;
        }
        float m = fmaxf(e0, e1);
#pragma unroll
        for (int o = 16; o; o >>= 1) m = fmaxf(m, __shfl_xor_sync(0xffffffffu, m, o));
        float ex0 = (p0 < end) ? __expf(e0 - m) : 0.f;
        float ex1 = (p1 < end) ? __expf(e1 - m) : 0.f;
        float sum = ex0 + ex1;
#pragma unroll
        for (int o = 16; o; o >>= 1) sum += __shfl_xor_sync(0xffffffffu, sum, o);
        float invden = 1.0f / sum;

        int idx = 0;
        for (; idx + 1 < deg; idx += 2) {
            float exa = __shfl_sync(0xffffffffu, idx < 32 ? ex0 : ex1, idx & 31);
            int   sa  = __shfl_sync(0xffffffffu, idx < 32 ? s0 : s1, idx & 31);
            float exb = __shfl_sync(0xffffffffu, (idx + 1) < 32 ? ex0 : ex1, (idx + 1) & 31);
            int   sb  = __shfl_sync(0xffffffffu, (idx + 1) < 32 ? s0 : s1, (idx + 1) & 31);
            float wa = exa * invden, wb = exb * invden;
            float4 va = xw4[(size_t)sa * 32 + lane];
            float4 vb = xw4[(size_t)sb * 32 + lane];
            acc.x += wa * va.x + wb * vb.x;
            acc.y += wa * va.y + wb * vb.y;
            acc.z += wa * va.z + wb * vb.z;
            acc.w += wa * va.w + wb * vb.w;
        }
        if (idx < deg) {
            float exa = __shfl_sync(0xffffffffu, idx < 32 ? ex0 : ex1, idx & 31);
            int   sa  = __shfl_sync(0xffffffffu, idx < 32 ? s0 : s1, idx & 31);
            float wa = exa * invden;
            float4 va = xw4[(size_t)sa * 32 + lane];
            acc.x += wa * va.x; acc.y += wa * va.y;
            acc.z += wa * va.z; acc.w += wa * va.w;
        }
    } else {
        float m = -1e30f;
        for (int p = beg + lane; p < end; p += 32) {
            int s = g_csr[p];
            float e = g_s[s] + dd;
            e = (e > 0.f) ? e : 0.2f * e;
            g_esc[p] = e;
            m = fmaxf(m, e);
        }
#pragma unroll
        for (int o = 16; o; o >>= 1) m = fmaxf(m, __shfl_xor_sync(0xffffffffu, m, o));
        float sum = 0.f;
        for (int p = beg + lane; p < end; p += 32) {
            float ex = __expf(g_esc[p] - m);
            g_esc[p] = ex;
            sum += ex;
        }
#pragma unroll
        for (int o = 16; o; o >>= 1) sum += __shfl_xor_sync(0xffffffffu, sum, o);
        float invden = 1.0f / sum;
        __syncwarp();
        for (int p = beg; p < end; ++p) {
            int s = g_csr[p];
            float wgt = g_esc[p] * invden;
            float4 v = xw4[(size_t)s * 32 + lane];
            acc.x += wgt * v.x; acc.y += wgt * v.y;
            acc.z += wgt * v.z; acc.w += wgt * v.w;
        }
    }

    float4 b = ((const float4*)bias)[lane];
    acc.x = fmaxf(acc.x + b.x, 0.f);
    acc.y = fmaxf(acc.y + b.y, 0.f);
    acc.z = fmaxf(acc.z + b.z, 0.f);
    acc.w = fmaxf(acc.w + b.w, 0.f);
    ((float4*)out)[(size_t)w * 32 + lane] = acc;
}

// ---------------- host launch ---------------------------------------------------
extern "C" void kernel_launch(void* const* d_in, const int* in_sizes, int n_in,
                              void* d_out, int out_size) {
    const float* x     = (const float*)d_in[0];
    const void*  ei    = d_in[1];
    const float* W1    = (const float*)d_in[2];
    const float* b1    = (const float*)d_in[3];
    const float* Wg1   = (const float*)d_in[4];
    const float* asrc1 = (const float*)d_in[5];
    const float* adst1 = (const float*)d_in[6];
    const float* bg1   = (const float*)d_in[7];
    const float* W2    = (const float*)d_in[8];
    const float* b2    = (const float*)d_in[9];
    const float* Wg2   = (const float*)d_in[10];
    const float* asrc2 = (const float*)d_in[11];
    const float* adst2 = (const float*)d_in[12];
    const float* bg2   = (const float*)d_in[13];
    const float* Wo    = (const float*)d_in[14];
    const float* bo    = (const float*)d_in[15];

    float* out_h = (float*)d_out;
    float* out_z = out_h + (size_t)N_NODES * HD;

    float *pA = nullptr, *pB = nullptr;
    unsigned short* pW = nullptr;
    cudaGetSymbolAddress((void**)&pA, g_bufA);
    cudaGetSymbolAddress((void**)&pB, g_bufB);
    cudaGetSymbolAddress((void**)&pW, g_wperm);
    const size_t WSTRIDE = 2 * 128 * 128;

    const int TB = 256;
    dim3 nb_edge((N_EDGES + TB - 1) / TB);
    dim3 nb_warp(((size_t)N_NODES * 32 + TB - 1) / TB);
    dim3 nb_gemm((N_NODES + 127) / 128);

    const int SMEM128 = 65536 + 128 * 128 * 2 * 2;
    const int SMEM64  = 65536 + 128 * 64 * 2 * 2;
    cudaFuncSetAttribute(tc_gemm<128>, cudaFuncAttributeMaxDynamicSharedMemorySize, SMEM128);
    cudaFuncSetAttribute(tc_gemm<64>,  cudaFuncAttributeMaxDynamicSharedMemorySize, SMEM64);

    // CSR build + weight conversion
    k_pre<<<NB_SCAN, 1024>>>((const unsigned int*)ei);
    k_convert_count<<<dim3(nb_edge.x, 2), TB>>>(ei, W1, Wg1, W2, Wg2, Wo);
    k_scan1<<<NB_SCAN, 1024>>>();
    k_scan2<<<1, 64>>>();
    k_scan3_fin<<<NB_SCAN, 1024>>>();
    k_fill_edges<<<nb_edge, TB>>>();

    // Layer 1: GCN (gcn_agg zeroes g_s/g_d for layer 2)
    tc_gemm<128><<<nb_gemm, TB, SMEM128>>>(x, pW, nullptr, pA, N_NODES, nullptr, nullptr);
    gcn_agg<<<nb_warp, TB>>>(pA, b1, pB);

    // Layer 2: GAT (att dots fused into GEMM epilogue)
    tc_gemm<128><<<nb_gemm, TB, SMEM128>>>(pB, pW + WSTRIDE, nullptr, pA, N_NODES, asrc1, adst1);
    gat_agg<<<nb_warp, TB>>>(pA, bg1, pB);

    // Layer 3: GCN (gcn_agg zeroes g_s/g_d for layer 4)
    tc_gemm<128><<<nb_gemm, TB, SMEM128>>>(pB, pW + 2 * WSTRIDE, nullptr, pA, N_NODES, nullptr, nullptr);
    gcn_agg<<<nb_warp, TB>>>(pA, b2, pB);

    // Layer 4: GAT -> h into d_out
    tc_gemm<128><<<nb_gemm, TB, SMEM128>>>(pB, pW + 3 * WSTRIDE, nullptr, pA, N_NODES, asrc2, adst2);
    gat_agg<<<nb_warp, TB>>>(pA, bg2, out_h);

    // Output head: z = h @ Wo + bo
    tc_gemm<64><<<nb_gemm, TB, SMEM64>>>(out_h, pW + 4 * WSTRIDE, bo, out_z, N_NODES, nullptr, nullptr);
}

// round 8
// speedup vs baseline: 1.4668x; 1.0765x over previous
#include <cuda_runtime.h>
#include <cuda_bf16.h>
#include <cuda_fp16.h>
#include <math.h>
#include <stdint.h>

// Problem constants
#define N_NODES 50000
#define N_EDGES 800000
#define TOT_E   850000
#define HD      128
#define NB_SCAN 49            // ceil(50000/1024)

// ---------------- device scratch --------------------------------------------
__device__ float g_bufA[(size_t)N_NODES * HD];   // fp16 xw lives here (reinterpreted)
__device__ float g_bufB[(size_t)N_NODES * HD];   // fp32 aggregated features
__device__ int   g_src[N_EDGES];
__device__ int   g_dst[N_EDGES];
__device__ int   g_flag;
__device__ int   g_cnt[N_NODES];
__device__ int   g_off[N_NODES + 1];
__device__ int   g_off2[N_NODES + 1];
__device__ int   g_csr[TOT_E];
__device__ int   g_bsum[64];
__device__ int   g_bpre[64];
__device__ float g_inv[N_NODES];
__device__ float g_s[N_NODES];
__device__ float g_d[N_NODES];
__device__ float g_esc[TOT_E];          // fallback only (deg > 64)
__device__ unsigned short g_wperm[5][2 * 128 * 128];

// ---------------- warp MMA helper --------------------------------------------
__device__ __forceinline__ void mma16816(float* d, const uint32_t* a, const uint32_t* b) {
    asm volatile(
        "mma.sync.aligned.m16n8k16.row.col.f32.bf16.bf16.f32 "
        "{%0,%1,%2,%3}, {%4,%5,%6,%7}, {%8,%9}, {%0,%1,%2,%3};"
        : "+f"(d[0]), "+f"(d[1]), "+f"(d[2]), "+f"(d[3])
        : "r"(a[0]), "r"(a[1]), "r"(a[2]), "r"(a[3]), "r"(b[0]), "r"(b[1]));
}

__device__ __forceinline__ uint32_t pack_bf16(float x, float y) {
    __nv_bfloat16 hx = __float2bfloat16(x), hy = __float2bfloat16(y);
    return (uint32_t)__bfloat16_as_ushort(hx) |
           ((uint32_t)__bfloat16_as_ushort(hy) << 16);
}

// ---------------- pre: zero counts + (block 0) detect edge dtype --------------
__global__ void k_pre(const unsigned int* __restrict__ w) {
    int i = blockIdx.x * 1024 + threadIdx.x;
    if (i < N_NODES) g_cnt[i] = 0;
    if (blockIdx.x == 0) {
        __shared__ int sflag;
        if (threadIdx.x == 0) sflag = 0;
        __syncthreads();
        if (w[2 * threadIdx.x + 1] != 0u) atomicOr(&sflag, 1);
        __syncthreads();
        if (threadIdx.x == 0) g_flag = sflag;
    }
}

// ---------------- fused: edge convert+count (y=0) | weight conversion (y=1) --
__global__ void k_convert_count(const void* __restrict__ ei,
                                const float* __restrict__ W1, const float* __restrict__ Wg1,
                                const float* __restrict__ W2, const float* __restrict__ Wg2,
                                const float* __restrict__ Wo) {
    if (blockIdx.y == 0) {
        int e = blockIdx.x * blockDim.x + threadIdx.x;
        if (e >= N_EDGES) return;
        int s, d;
        if (g_flag) {
            const int* p = (const int*)ei;
            s = p[e]; d = p[N_EDGES + e];
        } else {
            const long long* p = (const long long*)ei;
            s = (int)p[e]; d = (int)p[N_EDGES + e];
        }
        g_src[e] = s;
        g_dst[e] = d;
        atomicAdd(&g_cnt[d], 1);
    } else {
        int idx = blockIdx.x * blockDim.x + threadIdx.x;
        if (idx >= 4 * 16384 + 8192) return;
        int wsel, base, BN;
        if (idx < 16384)      { wsel = 0; base = 0;      BN = 128; }
        else if (idx < 32768) { wsel = 1; base = 16384;  BN = 128; }
        else if (idx < 49152) { wsel = 2; base = 32768;  BN = 128; }
        else if (idx < 65536) { wsel = 3; base = 49152;  BN = 128; }
        else                  { wsel = 4; base = 65536;  BN = 64;  }
        const float* W = (wsel == 0) ? W1 : (wsel == 1) ? Wg1 : (wsel == 2) ? W2
                       : (wsel == 3) ? Wg2 : Wo;
        int li = idx - base;
        int total = 128 * BN;
        int k = li / BN, n = li % BN;
        float v = W[li];
        __nv_bfloat16 h = __float2bfloat16(v);
        __nv_bfloat16 l = __float2bfloat16(v - __bfloat162float(h));
        int nt = n >> 3, kt = k >> 4, kk = k & 15;
        int reg = kk >> 3, klo = kk & 7;
        int lane = (n & 7) * 4 + (klo >> 1);
        int slot = ((nt * 8 + kt) * 32 + lane) * 2 + reg;
        int pos = slot * 2 + (kk & 1);
        g_wperm[wsel][pos] = __bfloat16_as_ushort(h);
        g_wperm[wsel][total + pos] = __bfloat16_as_ushort(l);
    }
}

// ---------------- multi-block scan -------------------------------------------
__global__ void k_scan1() {
    __shared__ int sd[1024];
    int tid = threadIdx.x;
    int i = blockIdx.x * 1024 + tid;
    int v = (i < N_NODES) ? g_cnt[i] + 1 : 0;   // +1 = self loop
    sd[tid] = v;
    __syncthreads();
    for (int off = 1; off < 1024; off <<= 1) {
        int t = (tid >= off) ? sd[tid - off] : 0;
        __syncthreads();
        sd[tid] += t;
        __syncthreads();
    }
    if (i < N_NODES) g_off[i] = sd[tid] - v;
    if (tid == 1023) g_bsum[blockIdx.x] = sd[1023];
}

__global__ void k_scan2() {
    __shared__ int sd[64];
    int tid = threadIdx.x;
    int v = (tid < NB_SCAN) ? g_bsum[tid] : 0;
    sd[tid] = v;
    __syncthreads();
    for (int off = 1; off < 64; off <<= 1) {
        int t = (tid >= off) ? sd[tid - off] : 0;
        __syncthreads();
        sd[tid] += t;
        __syncthreads();
    }
    if (tid < NB_SCAN) g_bpre[tid] = sd[tid] - v;
    if (tid == 63) g_off[N_NODES] = sd[63];
}

__global__ void k_scan3_fin() {
    int i = blockIdx.x * 1024 + threadIdx.x;
    if (i >= N_NODES) return;
    int b = g_off[i] + g_bpre[i >> 10];
    int e = (i + 1 == N_NODES) ? g_off[N_NODES]
                               : g_off[i + 1] + g_bpre[(i + 1) >> 10];
    g_off2[i] = b;
    if (i + 1 == N_NODES) g_off2[N_NODES] = g_off[N_NODES];
    g_csr[b] = i;          // self loop
    g_cnt[i] = b + 1;      // fill cursor
    g_inv[i] = rsqrtf((float)(e - b));
}

__global__ void k_fill_edges() {
    int e = blockIdx.x * blockDim.x + threadIdx.x;
    if (e < N_EDGES) {
        int pos = atomicAdd(&g_cnt[g_dst[e]], 1);
        g_csr[pos] = g_src[e];
    }
}

// ---------------- HMMA bf16x3 GEMM, fp16 or fp32 output, fused att dots ------
template <int BN, bool OUT16>
__global__ void __launch_bounds__(256)
tc_gemm(const float* __restrict__ X, const unsigned short* __restrict__ wperm,
        const float* __restrict__ bias, void* __restrict__ Yv, int M,
        const float* __restrict__ a_s, const float* __restrict__ a_d) {
    extern __shared__ char smem[];
    constexpr int NT = BN / 16;
    constexpr int OFF_ALO = 32768;
    constexpr int OFF_B   = 65536;
    constexpr int B_HALF  = 128 * BN * 2;

    int tid  = threadIdx.x;
    int wid  = tid >> 5;
    int lane = tid & 31;
    int row0 = blockIdx.x * 128;

    {
        const uint4* src = (const uint4*)wperm;
        uint4* dst = (uint4*)(smem + OFF_B);
        int n16 = (2 * B_HALF) / 16;
        for (int i = tid; i < n16; i += 256) dst[i] = src[i];
    }
    {
        uint32_t* ah = (uint32_t*)smem;
        uint32_t* al = (uint32_t*)(smem + OFF_ALO);
#pragma unroll
        for (int it = 0; it < 16; ++it) {
            int idx = it * 256 + tid;
            int r = idx >> 5;
            int c = (idx & 31) * 4;
            int gr = row0 + r;
            float4 v = make_float4(0.f, 0.f, 0.f, 0.f);
            if (gr < M) v = *(const float4*)&X[(size_t)gr * 128 + c];
            __nv_bfloat16 h0 = __float2bfloat16(v.x), h1 = __float2bfloat16(v.y);
            __nv_bfloat16 h2 = __float2bfloat16(v.z), h3 = __float2bfloat16(v.w);
            float l0 = v.x - __bfloat162float(h0), l1 = v.y - __bfloat162float(h1);
            float l2 = v.z - __bfloat162float(h2), l3 = v.w - __bfloat162float(h3);
            uint32_t hi0 = (uint32_t)__bfloat16_as_ushort(h0) |
                           ((uint32_t)__bfloat16_as_ushort(h1) << 16);
            uint32_t hi1 = (uint32_t)__bfloat16_as_ushort(h2) |
                           ((uint32_t)__bfloat16_as_ushort(h3) << 16);
            uint32_t lo0 = pack_bf16(l0, l1);
            uint32_t lo1 = pack_bf16(l2, l3);
            int mt = r >> 4, rr = r & 15;
            int kt = c >> 4, cc = c & 15;
            int reg = ((cc >> 3) << 1) | (rr >> 3);
            int ln0 = (rr & 7) * 4 + ((cc & 7) >> 1);
            int base = (mt * 8 + kt) * 32;
            ah[(base + ln0) * 4 + reg]     = hi0;
            ah[(base + ln0 + 1) * 4 + reg] = hi1;
            al[(base + ln0) * 4 + reg]     = lo0;
            al[(base + ln0 + 1) * 4 + reg] = lo1;
        }
    }
    __syncthreads();

    int wm = wid & 3;
    int wn = wid >> 2;
    float acc[2][NT][4];
#pragma unroll
    for (int i = 0; i < 2; ++i)
#pragma unroll
        for (int j = 0; j < NT; ++j)
#pragma unroll
            for (int q = 0; q < 4; ++q) acc[i][j][q] = 0.f;

    const uint4* Ah = (const uint4*)smem;
    const uint4* Al = (const uint4*)(smem + OFF_ALO);
    const uint2* Bh = (const uint2*)(smem + OFF_B);
    const uint2* Bl = (const uint2*)(smem + OFF_B + B_HALF);
#pragma unroll
    for (int kt = 0; kt < 8; ++kt) {
        uint4 ah0 = Ah[((wm * 2 + 0) * 8 + kt) * 32 + lane];
        uint4 ah1 = Ah[((wm * 2 + 1) * 8 + kt) * 32 + lane];
        uint4 al0 = Al[((wm * 2 + 0) * 8 + kt) * 32 + lane];
        uint4 al1 = Al[((wm * 2 + 1) * 8 + kt) * 32 + lane];
        uint2 b[NT];
#pragma unroll
        for (int j = 0; j < NT; ++j)
            b[j] = Bh[((wn * NT + j) * 8 + kt) * 32 + lane];
#pragma unroll
        for (int j = 0; j < NT; ++j) {
            mma16816(acc[0][j], (const uint32_t*)&ah0, (const uint32_t*)&b[j]);
            mma16816(acc[1][j], (const uint32_t*)&ah1, (const uint32_t*)&b[j]);
        }
#pragma unroll
        for (int j = 0; j < NT; ++j) {
            mma16816(acc[0][j], (const uint32_t*)&al0, (const uint32_t*)&b[j]);
            mma16816(acc[1][j], (const uint32_t*)&al1, (const uint32_t*)&b[j]);
        }
#pragma unroll
        for (int j = 0; j < NT; ++j)
            b[j] = Bl[((wn * NT + j) * 8 + kt) * 32 + lane];
#pragma unroll
        for (int j = 0; j < NT; ++j) {
            mma16816(acc[0][j], (const uint32_t*)&ah0, (const uint32_t*)&b[j]);
            mma16816(acc[1][j], (const uint32_t*)&ah1, (const uint32_t*)&b[j]);
        }
    }

    int rbase = row0 + wm * 32 + (lane >> 2);
    int cbase = wn * NT * 8 + (lane & 3) * 2;
#pragma unroll
    for (int i = 0; i < 2; ++i) {
        int r = rbase + i * 16;
#pragma unroll
        for (int j = 0; j < NT; ++j) {
            int cc = cbase + j * 8;
            float bx = 0.f, by = 0.f;
            if (bias) { bx = bias[cc]; by = bias[cc + 1]; }
            if (OUT16) {
                __half* Y = (__half*)Yv;
                if (r < M)
                    *(__half2*)&Y[(size_t)r * BN + cc] =
                        __floats2half2_rn(acc[i][j][0] + bx, acc[i][j][1] + by);
                if (r + 8 < M)
                    *(__half2*)&Y[(size_t)(r + 8) * BN + cc] =
                        __floats2half2_rn(acc[i][j][2] + bx, acc[i][j][3] + by);
            } else {
                float* Y = (float*)Yv;
                if (r < M) {
                    float2 v0 = make_float2(acc[i][j][0] + bx, acc[i][j][1] + by);
                    *(float2*)&Y[(size_t)r * BN + cc] = v0;
                }
                if (r + 8 < M) {
                    float2 v1 = make_float2(acc[i][j][2] + bx, acc[i][j][3] + by);
                    *(float2*)&Y[(size_t)(r + 8) * BN + cc] = v1;
                }
            }
        }
    }

    if (a_s) {
        float ps[2][2] = {{0.f, 0.f}, {0.f, 0.f}};
        float pd[2][2] = {{0.f, 0.f}, {0.f, 0.f}};
#pragma unroll
        for (int i = 0; i < 2; ++i)
#pragma unroll
            for (int j = 0; j < NT; ++j) {
                int cc = cbase + j * 8;
                float as0 = a_s[cc], as1 = a_s[cc + 1];
                float ad0 = a_d[cc], ad1 = a_d[cc + 1];
                ps[i][0] += acc[i][j][0] * as0 + acc[i][j][1] * as1;
                pd[i][0] += acc[i][j][0] * ad0 + acc[i][j][1] * ad1;
                ps[i][1] += acc[i][j][2] * as0 + acc[i][j][3] * as1;
                pd[i][1] += acc[i][j][2] * ad0 + acc[i][j][3] * ad1;
            }
#pragma unroll
        for (int i = 0; i < 2; ++i)
#pragma unroll
            for (int h = 0; h < 2; ++h) {
                float s = ps[i][h], d = pd[i][h];
                s += __shfl_xor_sync(0xffffffffu, s, 1);
                s += __shfl_xor_sync(0xffffffffu, s, 2);
                d += __shfl_xor_sync(0xffffffffu, d, 1);
                d += __shfl_xor_sync(0xffffffffu, d, 2);
                if ((lane & 3) == 0) {
                    int r = row0 + wm * 32 + i * 16 + h * 8 + (lane >> 2);
                    if (r < M) {
                        atomicAdd(&g_s[r], s);
                        atomicAdd(&g_d[r], d);
                    }
                }
            }
    }
}

// ---------------- fp16 row gather helper --------------------------------------
__device__ __forceinline__ float4 load_row16(const uint2* xw, int s, int lane) {
    uint2 u = xw[(size_t)s * 32 + lane];     // 4 halfs = 8 B
    __half2 h0 = *reinterpret_cast<__half2*>(&u.x);
    __half2 h1 = *reinterpret_cast<__half2*>(&u.y);
    float2 f0 = __half22float2(h0);
    float2 f1 = __half22float2(h1);
    return make_float4(f0.x, f0.y, f1.x, f1.y);
}

// ---------------- GCN aggregate: fp16 gather, fp32 out -------------------------
__global__ void gcn_agg(const __half* __restrict__ xw,
                        const float* __restrict__ bias,
                        float* __restrict__ out) {
    int w = (blockIdx.x * blockDim.x + threadIdx.x) >> 5;
    if (w >= N_NODES) return;
    int lane = threadIdx.x & 31;
    if (lane == 0) { g_s[w] = 0.f; g_d[w] = 0.f; }
    int beg = g_off2[w], end = g_off2[w + 1];
    float invd = g_inv[w];
    const uint2* xw2 = (const uint2*)xw;
    float4 acc = make_float4(0.f, 0.f, 0.f, 0.f);
    int p = beg;
    for (; p + 1 < end; p += 2) {
        int s0 = g_csr[p], s1 = g_csr[p + 1];
        float c0 = invd * g_inv[s0];
        float c1 = invd * g_inv[s1];
        float4 v0 = load_row16(xw2, s0, lane);
        float4 v1 = load_row16(xw2, s1, lane);
        acc.x += c0 * v0.x + c1 * v1.x;
        acc.y += c0 * v0.y + c1 * v1.y;
        acc.z += c0 * v0.z + c1 * v1.z;
        acc.w += c0 * v0.w + c1 * v1.w;
    }
    if (p < end) {
        int s0 = g_csr[p];
        float c0 = invd * g_inv[s0];
        float4 v0 = load_row16(xw2, s0, lane);
        acc.x += c0 * v0.x; acc.y += c0 * v0.y;
        acc.z += c0 * v0.z; acc.w += c0 * v0.w;
    }
    float4 b = ((const float4*)bias)[lane];
    acc.x = fmaxf(acc.x + b.x, 0.f);
    acc.y = fmaxf(acc.y + b.y, 0.f);
    acc.z = fmaxf(acc.z + b.z, 0.f);
    acc.w = fmaxf(acc.w + b.w, 0.f);
    ((float4*)out)[(size_t)w * 32 + lane] = acc;
}

// ---------------- GAT aggregate: fp16 gather, register-cached ------------------
__global__ void gat_agg(const __half* __restrict__ xw,
                        const float* __restrict__ bias,
                        float* __restrict__ out) {
    int w = (blockIdx.x * blockDim.x + threadIdx.x) >> 5;
    if (w >= N_NODES) return;
    int lane = threadIdx.x & 31;
    int beg = g_off2[w], end = g_off2[w + 1];
    int deg = end - beg;
    float dd = g_d[w];
    const uint2* xw2 = (const uint2*)xw;
    float4 acc = make_float4(0.f, 0.f, 0.f, 0.f);

    if (deg <= 64) {
        int p0 = beg + lane, p1 = beg + 32 + lane;
        int s0 = 0, s1 = 0;
        float e0 = -1e30f, e1 = -1e30f;
        if (p0 < end) {
            s0 = g_csr[p0];
            float t = g_s[s0] + dd;
            e0 = (t > 0.f) ? t : 0.2f * t;
        }
        if (p1 < end) {
            s1 = g_csr[p1];
            float t = g_s[s1] + dd;
            e1 = (t > 0.f) ? t : 0.2f * t;
        }
        float m = fmaxf(e0, e1);
#pragma unroll
        for (int o = 16; o; o >>= 1) m = fmaxf(m, __shfl_xor_sync(0xffffffffu, m, o));
        float ex0 = (p0 < end) ? __expf(e0 - m) : 0.f;
        float ex1 = (p1 < end) ? __expf(e1 - m) : 0.f;
        float sum = ex0 + ex1;
#pragma unroll
        for (int o = 16; o; o >>= 1) sum += __shfl_xor_sync(0xffffffffu, sum, o);
        float invden = 1.0f / sum;

        int idx = 0;
        for (; idx + 1 < deg; idx += 2) {
            float exa = __shfl_sync(0xffffffffu, idx < 32 ? ex0 : ex1, idx & 31);
            int   sa  = __shfl_sync(0xffffffffu, idx < 32 ? s0 : s1, idx & 31);
            float exb = __shfl_sync(0xffffffffu, (idx + 1) < 32 ? ex0 : ex1, (idx + 1) & 31);
            int   sb  = __shfl_sync(0xffffffffu, (idx + 1) < 32 ? s0 : s1, (idx + 1) & 31);
            float wa = exa * invden, wb = exb * invden;
            float4 va = load_row16(xw2, sa, lane);
            float4 vb = load_row16(xw2, sb, lane);
            acc.x += wa * va.x + wb * vb.x;
            acc.y += wa * va.y + wb * vb.y;
            acc.z += wa * va.z + wb * vb.z;
            acc.w += wa * va.w + wb * vb.w;
        }
        if (idx < deg) {
            float exa = __shfl_sync(0xffffffffu, idx < 32 ? ex0 : ex1, idx & 31);
            int   sa  = __shfl_sync(0xffffffffu, idx < 32 ? s0 : s1, idx & 31);
            float wa = exa * invden;
            float4 va = load_row16(xw2, sa, lane);
            acc.x += wa * va.x; acc.y += wa * va.y;
            acc.z += wa * va.z; acc.w += wa * va.w;
        }
    } else {
        float m = -1e30f;
        for (int p = beg + lane; p < end; p += 32) {
            int s = g_csr[p];
            float e = g_s[s] + dd;
            e = (e > 0.f) ? e : 0.2f * e;
            g_esc[p] = e;
            m = fmaxf(m, e);
        }
#pragma unroll
        for (int o = 16; o; o >>= 1) m = fmaxf(m, __shfl_xor_sync(0xffffffffu, m, o));
        float sum = 0.f;
        for (int p = beg + lane; p < end; p += 32) {
            float ex = __expf(g_esc[p] - m);
            g_esc[p] = ex;
            sum += ex;
        }
#pragma unroll
        for (int o = 16; o; o >>= 1) sum += __shfl_xor_sync(0xffffffffu, sum, o);
        float invden = 1.0f / sum;
        __syncwarp();
        for (int p = beg; p < end; ++p) {
            int s = g_csr[p];
            float wgt = g_esc[p] * invden;
            float4 v = load_row16(xw2, s, lane);
            acc.x += wgt * v.x; acc.y += wgt * v.y;
            acc.z += wgt * v.z; acc.w += wgt * v.w;
        }
    }

    float4 b = ((const float4*)bias)[lane];
    acc.x = fmaxf(acc.x + b.x, 0.f);
    acc.y = fmaxf(acc.y + b.y, 0.f);
    acc.z = fmaxf(acc.z + b.z, 0.f);
    acc.w = fmaxf(acc.w + b.w, 0.f);
    ((float4*)out)[(size_t)w * 32 + lane] = acc;
}

// ---------------- host launch ---------------------------------------------------
extern "C" void kernel_launch(void* const* d_in, const int* in_sizes, int n_in,
                              void* d_out, int out_size) {
    const float* x     = (const float*)d_in[0];
    const void*  ei    = d_in[1];
    const float* W1    = (const float*)d_in[2];
    const float* b1    = (const float*)d_in[3];
    const float* Wg1   = (const float*)d_in[4];
    const float* asrc1 = (const float*)d_in[5];
    const float* adst1 = (const float*)d_in[6];
    const float* bg1   = (const float*)d_in[7];
    const float* W2    = (const float*)d_in[8];
    const float* b2    = (const float*)d_in[9];
    const float* Wg2   = (const float*)d_in[10];
    const float* asrc2 = (const float*)d_in[11];
    const float* adst2 = (const float*)d_in[12];
    const float* bg2   = (const float*)d_in[13];
    const float* Wo    = (const float*)d_in[14];
    const float* bo    = (const float*)d_in[15];

    float* out_h = (float*)d_out;
    float* out_z = out_h + (size_t)N_NODES * HD;

    float *pA = nullptr, *pB = nullptr;
    unsigned short* pW = nullptr;
    cudaGetSymbolAddress((void**)&pA, g_bufA);
    cudaGetSymbolAddress((void**)&pB, g_bufB);
    cudaGetSymbolAddress((void**)&pW, g_wperm);
    __half* pA16 = (__half*)pA;      // fp16 xw buffer (reuses g_bufA)
    const size_t WSTRIDE = 2 * 128 * 128;

    const int TB = 256;
    dim3 nb_edge((N_EDGES + TB - 1) / TB);
    dim3 nb_warp(((size_t)N_NODES * 32 + TB - 1) / TB);
    dim3 nb_gemm((N_NODES + 127) / 128);

    const int SMEM128 = 65536 + 128 * 128 * 2 * 2;
    const int SMEM64  = 65536 + 128 * 64 * 2 * 2;
    cudaFuncSetAttribute((const void*)tc_gemm<128, true>,
                         cudaFuncAttributeMaxDynamicSharedMemorySize, SMEM128);
    cudaFuncSetAttribute((const void*)tc_gemm<64, false>,
                         cudaFuncAttributeMaxDynamicSharedMemorySize, SMEM64);

    // CSR build + weight conversion
    k_pre<<<NB_SCAN, 1024>>>((const unsigned int*)ei);
    k_convert_count<<<dim3(nb_edge.x, 2), TB>>>(ei, W1, Wg1, W2, Wg2, Wo);
    k_scan1<<<NB_SCAN, 1024>>>();
    k_scan2<<<1, 64>>>();
    k_scan3_fin<<<NB_SCAN, 1024>>>();
    k_fill_edges<<<nb_edge, TB>>>();

    // Layer 1: GCN (xw in fp16; gcn_agg zeroes g_s/g_d for layer 2)
    tc_gemm<128, true><<<nb_gemm, TB, SMEM128>>>(x, pW, nullptr, pA16, N_NODES, nullptr, nullptr);
    gcn_agg<<<nb_warp, TB>>>(pA16, b1, pB);

    // Layer 2: GAT (att dots fused, fp32 accs; xw fp16)
    tc_gemm<128, true><<<nb_gemm, TB, SMEM128>>>(pB, pW + WSTRIDE, nullptr, pA16, N_NODES, asrc1, adst1);
    gat_agg<<<nb_warp, TB>>>(pA16, bg1, pB);

    // Layer 3: GCN
    tc_gemm<128, true><<<nb_gemm, TB, SMEM128>>>(pB, pW + 2 * WSTRIDE, nullptr, pA16, N_NODES, nullptr, nullptr);
    gcn_agg<<<nb_warp, TB>>>(pA16, b2, pB);

    // Layer 4: GAT -> h into d_out (fp32)
    tc_gemm<128, true><<<nb_gemm, TB, SMEM128>>>(pB, pW + 3 * WSTRIDE, nullptr, pA16, N_NODES, asrc2, adst2);
    gat_agg<<<nb_warp, TB>>>(pA16, bg2, out_h);

    // Output head: z = h @ Wo + bo (fp32 in/out)
    tc_gemm<64, false><<<nb_gemm, TB, SMEM64>>>(out_h, pW + 4 * WSTRIDE, bo, out_z, N_NODES, nullptr, nullptr);
}

// round 9
// speedup vs baseline: 1.4956x; 1.0196x over previous
#include <cuda_runtime.h>
#include <cuda_bf16.h>
#include <cuda_fp16.h>
#include <math.h>
#include <stdint.h>

// Problem constants
#define N_NODES 50000
#define N_EDGES 800000
#define TOT_E   850000
#define HD      128
#define NB_SCAN 49            // ceil(50000/1024)

// ---------------- device scratch --------------------------------------------
__device__ float g_bufA[(size_t)N_NODES * HD];   // fp16 xw (reinterpreted)
__device__ float g_bufB[(size_t)N_NODES * HD];   // fp16/fp32 aggregated features
__device__ int   g_src[N_EDGES];
__device__ int   g_dst[N_EDGES];
__device__ int   g_flag;
__device__ int   g_cnt[N_NODES];
__device__ int   g_off2[N_NODES + 1];
__device__ int   g_csr[TOT_E];
__device__ int   g_bpub[NB_SCAN];       // published block totals (-1 = not ready)
__device__ float g_inv[N_NODES];
__device__ float g_s[N_NODES];
__device__ float g_d[N_NODES];
__device__ float g_esc[TOT_E];          // fallback only (deg > 64)
__device__ unsigned short g_wperm[5][2 * 128 * 128];

// ---------------- warp MMA helper --------------------------------------------
__device__ __forceinline__ void mma16816(float* d, const uint32_t* a, const uint32_t* b) {
    asm volatile(
        "mma.sync.aligned.m16n8k16.row.col.f32.bf16.bf16.f32 "
        "{%0,%1,%2,%3}, {%4,%5,%6,%7}, {%8,%9}, {%0,%1,%2,%3};"
        : "+f"(d[0]), "+f"(d[1]), "+f"(d[2]), "+f"(d[3])
        : "r"(a[0]), "r"(a[1]), "r"(a[2]), "r"(a[3]), "r"(b[0]), "r"(b[1]));
}

__device__ __forceinline__ uint32_t pack_bf16(float x, float y) {
    __nv_bfloat16 hx = __float2bfloat16(x), hy = __float2bfloat16(y);
    return (uint32_t)__bfloat16_as_ushort(hx) |
           ((uint32_t)__bfloat16_as_ushort(hy) << 16);
}

// ---------------- pre: zero counts + init lookback + detect edge dtype --------
__global__ void k_pre(const unsigned int* __restrict__ w) {
    int i = blockIdx.x * 1024 + threadIdx.x;
    if (i < N_NODES) g_cnt[i] = 0;
    if (blockIdx.x == 1 && threadIdx.x < NB_SCAN) g_bpub[threadIdx.x] = -1;
    if (blockIdx.x == 0) {
        __shared__ int sflag;
        if (threadIdx.x == 0) sflag = 0;
        __syncthreads();
        if (w[2 * threadIdx.x + 1] != 0u) atomicOr(&sflag, 1);
        __syncthreads();
        if (threadIdx.x == 0) g_flag = sflag;
    }
}

// ---------------- fused: edge convert+count (y=0) | weight conversion (y=1) --
__global__ void k_convert_count(const void* __restrict__ ei,
                                const float* __restrict__ W1, const float* __restrict__ Wg1,
                                const float* __restrict__ W2, const float* __restrict__ Wg2,
                                const float* __restrict__ Wo) {
    if (blockIdx.y == 0) {
        int e = blockIdx.x * blockDim.x + threadIdx.x;
        if (e >= N_EDGES) return;
        int s, d;
        if (g_flag) {
            const int* p = (const int*)ei;
            s = p[e]; d = p[N_EDGES + e];
        } else {
            const long long* p = (const long long*)ei;
            s = (int)p[e]; d = (int)p[N_EDGES + e];
        }
        g_src[e] = s;
        g_dst[e] = d;
        atomicAdd(&g_cnt[d], 1);
    } else {
        int idx = blockIdx.x * blockDim.x + threadIdx.x;
        if (idx >= 4 * 16384 + 8192) return;
        int wsel, base, BN;
        if (idx < 16384)      { wsel = 0; base = 0;      BN = 128; }
        else if (idx < 32768) { wsel = 1; base = 16384;  BN = 128; }
        else if (idx < 49152) { wsel = 2; base = 32768;  BN = 128; }
        else if (idx < 65536) { wsel = 3; base = 49152;  BN = 128; }
        else                  { wsel = 4; base = 65536;  BN = 64;  }
        const float* W = (wsel == 0) ? W1 : (wsel == 1) ? Wg1 : (wsel == 2) ? W2
                       : (wsel == 3) ? Wg2 : Wo;
        int li = idx - base;
        int total = 128 * BN;
        int k = li / BN, n = li % BN;
        float v = W[li];
        __nv_bfloat16 h = __float2bfloat16(v);
        __nv_bfloat16 l = __float2bfloat16(v - __bfloat162float(h));
        int nt = n >> 3, kt = k >> 4, kk = k & 15;
        int reg = kk >> 3, klo = kk & 7;
        int lane = (n & 7) * 4 + (klo >> 1);
        int slot = ((nt * 8 + kt) * 32 + lane) * 2 + reg;
        int pos = slot * 2 + (kk & 1);
        g_wperm[wsel][pos] = __bfloat16_as_ushort(h);
        g_wperm[wsel][total + pos] = __bfloat16_as_ushort(l);
    }
}

// ---------------- single-kernel scan + finalize (decoupled lookback) ----------
__global__ void k_scan_fused() {
    __shared__ int sd[1024];
    __shared__ int s_prefix;
    int tid = threadIdx.x;
    int blk = blockIdx.x;
    int i = blk * 1024 + tid;
    int cnt = (i < N_NODES) ? g_cnt[i] + 1 : 0;   // +1 = self loop
    sd[tid] = cnt;
    __syncthreads();
    for (int off = 1; off < 1024; off <<= 1) {
        int t = (tid >= off) ? sd[tid - off] : 0;
        __syncthreads();
        sd[tid] += t;
        __syncthreads();
    }
    int incl = sd[tid];
    if (tid == 1023) *(volatile int*)&g_bpub[blk] = sd[1023];
    // lookback: sum predecessors' totals (all blocks resident; spin per slot)
    if (tid < 32) {
        int pre = 0;
        for (int j = tid; j < blk; j += 32) {
            int v;
            do { v = *(volatile int*)&g_bpub[j]; } while (v == -1);
            pre += v;
        }
#pragma unroll
        for (int o = 16; o; o >>= 1) pre += __shfl_xor_sync(0xffffffffu, pre, o);
        if (tid == 0) s_prefix = pre;
    }
    __syncthreads();
    if (i < N_NODES) {
        int b = s_prefix + incl - cnt;
        g_off2[i] = b;
        g_csr[b] = i;          // self loop
        g_cnt[i] = b + 1;      // fill cursor
        g_inv[i] = rsqrtf((float)cnt);
        if (i == N_NODES - 1) g_off2[N_NODES] = b + cnt;
    }
}

__global__ void k_fill_edges() {
    int e = blockIdx.x * blockDim.x + threadIdx.x;
    if (e < N_EDGES) {
        int pos = atomicAdd(&g_cnt[g_dst[e]], 1);
        g_csr[pos] = g_src[e];
    }
}

// ---------------- HMMA bf16x3 GEMM, fp16/fp32 in & out, fused att dots --------
template <int BN, bool IN16, bool OUT16>
__global__ void __launch_bounds__(256)
tc_gemm(const void* __restrict__ Xv, const unsigned short* __restrict__ wperm,
        const float* __restrict__ bias, void* __restrict__ Yv, int M,
        const float* __restrict__ a_s, const float* __restrict__ a_d) {
    extern __shared__ char smem[];
    constexpr int NT = BN / 16;
    constexpr int OFF_ALO = 32768;
    constexpr int OFF_B   = 65536;
    constexpr int B_HALF  = 128 * BN * 2;

    int tid  = threadIdx.x;
    int wid  = tid >> 5;
    int lane = tid & 31;
    int row0 = blockIdx.x * 128;

    {
        const uint4* src = (const uint4*)wperm;
        uint4* dst = (uint4*)(smem + OFF_B);
        int n16 = (2 * B_HALF) / 16;
        for (int i = tid; i < n16; i += 256) dst[i] = src[i];
    }
    {
        uint32_t* ah = (uint32_t*)smem;
        uint32_t* al = (uint32_t*)(smem + OFF_ALO);
#pragma unroll
        for (int it = 0; it < 16; ++it) {
            int idx = it * 256 + tid;
            int r = idx >> 5;
            int c = (idx & 31) * 4;
            int gr = row0 + r;
            float4 v = make_float4(0.f, 0.f, 0.f, 0.f);
            if (gr < M) {
                if (IN16) {
                    uint2 u = ((const uint2*)Xv)[(size_t)gr * 32 + (idx & 31)];
                    float2 f0 = __half22float2(*reinterpret_cast<__half2*>(&u.x));
                    float2 f1 = __half22float2(*reinterpret_cast<__half2*>(&u.y));
                    v = make_float4(f0.x, f0.y, f1.x, f1.y);
                } else {
                    v = ((const float4*)Xv)[(size_t)gr * 32 + (idx & 31)];
                }
            }
            __nv_bfloat16 h0 = __float2bfloat16(v.x), h1 = __float2bfloat16(v.y);
            __nv_bfloat16 h2 = __float2bfloat16(v.z), h3 = __float2bfloat16(v.w);
            float l0 = v.x - __bfloat162float(h0), l1 = v.y - __bfloat162float(h1);
            float l2 = v.z - __bfloat162float(h2), l3 = v.w - __bfloat162float(h3);
            uint32_t hi0 = (uint32_t)__bfloat16_as_ushort(h0) |
                           ((uint32_t)__bfloat16_as_ushort(h1) << 16);
            uint32_t hi1 = (uint32_t)__bfloat16_as_ushort(h2) |
                           ((uint32_t)__bfloat16_as_ushort(h3) << 16);
            uint32_t lo0 = pack_bf16(l0, l1);
            uint32_t lo1 = pack_bf16(l2, l3);
            int mt = r >> 4, rr = r & 15;
            int kt = c >> 4, cc = c & 15;
            int reg = ((cc >> 3) << 1) | (rr >> 3);
            int ln0 = (rr & 7) * 4 + ((cc & 7) >> 1);
            int base = (mt * 8 + kt) * 32;
            ah[(base + ln0) * 4 + reg]     = hi0;
            ah[(base + ln0 + 1) * 4 + reg] = hi1;
            al[(base + ln0) * 4 + reg]     = lo0;
            al[(base + ln0 + 1) * 4 + reg] = lo1;
        }
    }
    __syncthreads();

    int wm = wid & 3;
    int wn = wid >> 2;
    float acc[2][NT][4];
#pragma unroll
    for (int i = 0; i < 2; ++i)
#pragma unroll
        for (int j = 0; j < NT; ++j)
#pragma unroll
            for (int q = 0; q < 4; ++q) acc[i][j][q] = 0.f;

    const uint4* Ah = (const uint4*)smem;
    const uint4* Al = (const uint4*)(smem + OFF_ALO);
    const uint2* Bh = (const uint2*)(smem + OFF_B);
    const uint2* Bl = (const uint2*)(smem + OFF_B + B_HALF);
#pragma unroll
    for (int kt = 0; kt < 8; ++kt) {
        uint4 ah0 = Ah[((wm * 2 + 0) * 8 + kt) * 32 + lane];
        uint4 ah1 = Ah[((wm * 2 + 1) * 8 + kt) * 32 + lane];
        uint4 al0 = Al[((wm * 2 + 0) * 8 + kt) * 32 + lane];
        uint4 al1 = Al[((wm * 2 + 1) * 8 + kt) * 32 + lane];
        uint2 b[NT];
#pragma unroll
        for (int j = 0; j < NT; ++j)
            b[j] = Bh[((wn * NT + j) * 8 + kt) * 32 + lane];
#pragma unroll
        for (int j = 0; j < NT; ++j) {
            mma16816(acc[0][j], (const uint32_t*)&ah0, (const uint32_t*)&b[j]);
            mma16816(acc[1][j], (const uint32_t*)&ah1, (const uint32_t*)&b[j]);
        }
#pragma unroll
        for (int j = 0; j < NT; ++j) {
            mma16816(acc[0][j], (const uint32_t*)&al0, (const uint32_t*)&b[j]);
            mma16816(acc[1][j], (const uint32_t*)&al1, (const uint32_t*)&b[j]);
        }
#pragma unroll
        for (int j = 0; j < NT; ++j)
            b[j] = Bl[((wn * NT + j) * 8 + kt) * 32 + lane];
#pragma unroll
        for (int j = 0; j < NT; ++j) {
            mma16816(acc[0][j], (const uint32_t*)&ah0, (const uint32_t*)&b[j]);
            mma16816(acc[1][j], (const uint32_t*)&ah1, (const uint32_t*)&b[j]);
        }
    }

    int rbase = row0 + wm * 32 + (lane >> 2);
    int cbase = wn * NT * 8 + (lane & 3) * 2;
#pragma unroll
    for (int i = 0; i < 2; ++i) {
        int r = rbase + i * 16;
#pragma unroll
        for (int j = 0; j < NT; ++j) {
            int cc = cbase + j * 8;
            float bx = 0.f, by = 0.f;
            if (bias) { bx = bias[cc]; by = bias[cc + 1]; }
            if (OUT16) {
                __half* Y = (__half*)Yv;
                if (r < M)
                    *(__half2*)&Y[(size_t)r * BN + cc] =
                        __floats2half2_rn(acc[i][j][0] + bx, acc[i][j][1] + by);
                if (r + 8 < M)
                    *(__half2*)&Y[(size_t)(r + 8) * BN + cc] =
                        __floats2half2_rn(acc[i][j][2] + bx, acc[i][j][3] + by);
            } else {
                float* Y = (float*)Yv;
                if (r < M) {
                    float2 v0 = make_float2(acc[i][j][0] + bx, acc[i][j][1] + by);
                    *(float2*)&Y[(size_t)r * BN + cc] = v0;
                }
                if (r + 8 < M) {
                    float2 v1 = make_float2(acc[i][j][2] + bx, acc[i][j][3] + by);
                    *(float2*)&Y[(size_t)(r + 8) * BN + cc] = v1;
                }
            }
        }
    }

    if (a_s) {
        float ps[2][2] = {{0.f, 0.f}, {0.f, 0.f}};
        float pd[2][2] = {{0.f, 0.f}, {0.f, 0.f}};
#pragma unroll
        for (int i = 0; i < 2; ++i)
#pragma unroll
            for (int j = 0; j < NT; ++j) {
                int cc = cbase + j * 8;
                float as0 = a_s[cc], as1 = a_s[cc + 1];
                float ad0 = a_d[cc], ad1 = a_d[cc + 1];
                ps[i][0] += acc[i][j][0] * as0 + acc[i][j][1] * as1;
                pd[i][0] += acc[i][j][0] * ad0 + acc[i][j][1] * ad1;
                ps[i][1] += acc[i][j][2] * as0 + acc[i][j][3] * as1;
                pd[i][1] += acc[i][j][2] * ad0 + acc[i][j][3] * ad1;
            }
#pragma unroll
        for (int i = 0; i < 2; ++i)
#pragma unroll
            for (int h = 0; h < 2; ++h) {
                float s = ps[i][h], d = pd[i][h];
                s += __shfl_xor_sync(0xffffffffu, s, 1);
                s += __shfl_xor_sync(0xffffffffu, s, 2);
                d += __shfl_xor_sync(0xffffffffu, d, 1);
                d += __shfl_xor_sync(0xffffffffu, d, 2);
                if ((lane & 3) == 0) {
                    int r = row0 + wm * 32 + i * 16 + h * 8 + (lane >> 2);
                    if (r < M) {
                        atomicAdd(&g_s[r], s);
                        atomicAdd(&g_d[r], d);
                    }
                }
            }
    }
}

// ---------------- fp16 row gather helper --------------------------------------
__device__ __forceinline__ float4 load_row16(const uint2* xw, int s, int lane) {
    uint2 u = xw[(size_t)s * 32 + lane];
    float2 f0 = __half22float2(*reinterpret_cast<__half2*>(&u.x));
    float2 f1 = __half22float2(*reinterpret_cast<__half2*>(&u.y));
    return make_float4(f0.x, f0.y, f1.x, f1.y);
}

__device__ __forceinline__ void store_row(void* out, int w, int lane, float4 acc, bool out16) {
    if (out16) {
        __half2 h0 = __floats2half2_rn(acc.x, acc.y);
        __half2 h1 = __floats2half2_rn(acc.z, acc.w);
        uint2 u;
        u.x = *reinterpret_cast<uint32_t*>(&h0);
        u.y = *reinterpret_cast<uint32_t*>(&h1);
        ((uint2*)out)[(size_t)w * 32 + lane] = u;
    } else {
        ((float4*)out)[(size_t)w * 32 + lane] = acc;
    }
}

// ---------------- GCN aggregate: fp16 gather -----------------------------------
template <bool OUT16>
__global__ void gcn_agg(const __half* __restrict__ xw,
                        const float* __restrict__ bias,
                        void* __restrict__ out) {
    int w = (blockIdx.x * blockDim.x + threadIdx.x) >> 5;
    if (w >= N_NODES) return;
    int lane = threadIdx.x & 31;
    if (lane == 0) { g_s[w] = 0.f; g_d[w] = 0.f; }
    int beg = g_off2[w], end = g_off2[w + 1];
    float invd = g_inv[w];
    const uint2* xw2 = (const uint2*)xw;
    float4 acc = make_float4(0.f, 0.f, 0.f, 0.f);
    int p = beg;
    for (; p + 1 < end; p += 2) {
        int s0 = g_csr[p], s1 = g_csr[p + 1];
        float c0 = invd * g_inv[s0];
        float c1 = invd * g_inv[s1];
        float4 v0 = load_row16(xw2, s0, lane);
        float4 v1 = load_row16(xw2, s1, lane);
        acc.x += c0 * v0.x + c1 * v1.x;
        acc.y += c0 * v0.y + c1 * v1.y;
        acc.z += c0 * v0.z + c1 * v1.z;
        acc.w += c0 * v0.w + c1 * v1.w;
    }
    if (p < end) {
        int s0 = g_csr[p];
        float c0 = invd * g_inv[s0];
        float4 v0 = load_row16(xw2, s0, lane);
        acc.x += c0 * v0.x; acc.y += c0 * v0.y;
        acc.z += c0 * v0.z; acc.w += c0 * v0.w;
    }
    float4 b = ((const float4*)bias)[lane];
    acc.x = fmaxf(acc.x + b.x, 0.f);
    acc.y = fmaxf(acc.y + b.y, 0.f);
    acc.z = fmaxf(acc.z + b.z, 0.f);
    acc.w = fmaxf(acc.w + b.w, 0.f);
    store_row(out, w, lane, acc, OUT16);
}

// ---------------- GAT aggregate: fp16 gather, register-cached ------------------
template <bool OUT16>
__global__ void gat_agg(const __half* __restrict__ xw,
                        const float* __restrict__ bias,
                        void* __restrict__ out) {
    int w = (blockIdx.x * blockDim.x + threadIdx.x) >> 5;
    if (w >= N_NODES) return;
    int lane = threadIdx.x & 31;
    int beg = g_off2[w], end = g_off2[w + 1];
    int deg = end - beg;
    float dd = g_d[w];
    const uint2* xw2 = (const uint2*)xw;
    float4 acc = make_float4(0.f, 0.f, 0.f, 0.f);

    if (deg <= 64) {
        int p0 = beg + lane, p1 = beg + 32 + lane;
        int s0 = 0, s1 = 0;
        float e0 = -1e30f, e1 = -1e30f;
        if (p0 < end) {
            s0 = g_csr[p0];
            float t = g_s[s0] + dd;
            e0 = (t > 0.f) ? t : 0.2f * t;
        }
        if (p1 < end) {
            s1 = g_csr[p1];
            float t = g_s[s1] + dd;
            e1 = (t > 0.f) ? t : 0.2f * t;
        }
        float m = fmaxf(e0, e1);
#pragma unroll
        for (int o = 16; o; o >>= 1) m = fmaxf(m, __shfl_xor_sync(0xffffffffu, m, o));
        float ex0 = (p0 < end) ? __expf(e0 - m) : 0.f;
        float ex1 = (p1 < end) ? __expf(e1 - m) : 0.f;
        float sum = ex0 + ex1;
#pragma unroll
        for (int o = 16; o; o >>= 1) sum += __shfl_xor_sync(0xffffffffu, sum, o);
        float invden = 1.0f / sum;

        int idx = 0;
        for (; idx + 1 < deg; idx += 2) {
            float exa = __shfl_sync(0xffffffffu, idx < 32 ? ex0 : ex1, idx & 31);
            int   sa  = __shfl_sync(0xffffffffu, idx < 32 ? s0 : s1, idx & 31);
            float exb = __shfl_sync(0xffffffffu, (idx + 1) < 32 ? ex0 : ex1, (idx + 1) & 31);
            int   sb  = __shfl_sync(0xffffffffu, (idx + 1) < 32 ? s0 : s1, (idx + 1) & 31);
            float wa = exa * invden, wb = exb * invden;
            float4 va = load_row16(xw2, sa, lane);
            float4 vb = load_row16(xw2, sb, lane);
            acc.x += wa * va.x + wb * vb.x;
            acc.y += wa * va.y + wb * vb.y;
            acc.z += wa * va.z + wb * vb.z;
            acc.w += wa * va.w + wb * vb.w;
        }
        if (idx < deg) {
            float exa = __shfl_sync(0xffffffffu, idx < 32 ? ex0 : ex1, idx & 31);
            int   sa  = __shfl_sync(0xffffffffu, idx < 32 ? s0 : s1, idx & 31);
            float wa = exa * invden;
            float4 va = load_row16(xw2, sa, lane);
            acc.x += wa * va.x; acc.y += wa * va.y;
            acc.z += wa * va.z; acc.w += wa * va.w;
        }
    } else {
        float m = -1e30f;
        for (int p = beg + lane; p < end; p += 32) {
            int s = g_csr[p];
            float e = g_s[s] + dd;
            e = (e > 0.f) ? e : 0.2f * e;
            g_esc[p] = e;
            m = fmaxf(m, e);
        }
#pragma unroll
        for (int o = 16; o; o >>= 1) m = fmaxf(m, __shfl_xor_sync(0xffffffffu, m, o));
        float sum = 0.f;
        for (int p = beg + lane; p < end; p += 32) {
            float ex = __expf(g_esc[p] - m);
            g_esc[p] = ex;
            sum += ex;
        }
#pragma unroll
        for (int o = 16; o; o >>= 1) sum += __shfl_xor_sync(0xffffffffu, sum, o);
        float invden = 1.0f / sum;
        __syncwarp();
        for (int p = beg; p < end; ++p) {
            int s = g_csr[p];
            float wgt = g_esc[p] * invden;
            float4 v = load_row16(xw2, s, lane);
            acc.x += wgt * v.x; acc.y += wgt * v.y;
            acc.z += wgt * v.z; acc.w += wgt * v.w;
        }
    }

    float4 b = ((const float4*)bias)[lane];
    acc.x = fmaxf(acc.x + b.x, 0.f);
    acc.y = fmaxf(acc.y + b.y, 0.f);
    acc.z = fmaxf(acc.z + b.z, 0.f);
    acc.w = fmaxf(acc.w + b.w, 0.f);
    store_row(out, w, lane, acc, OUT16);
}

// ---------------- host launch ---------------------------------------------------
extern "C" void kernel_launch(void* const* d_in, const int* in_sizes, int n_in,
                              void* d_out, int out_size) {
    const float* x     = (const float*)d_in[0];
    const void*  ei    = d_in[1];
    const float* W1    = (const float*)d_in[2];
    const float* b1    = (const float*)d_in[3];
    const float* Wg1   = (const float*)d_in[4];
    const float* asrc1 = (const float*)d_in[5];
    const float* adst1 = (const float*)d_in[6];
    const float* bg1   = (const float*)d_in[7];
    const float* W2    = (const float*)d_in[8];
    const float* b2    = (const float*)d_in[9];
    const float* Wg2   = (const float*)d_in[10];
    const float* asrc2 = (const float*)d_in[11];
    const float* adst2 = (const float*)d_in[12];
    const float* bg2   = (const float*)d_in[13];
    const float* Wo    = (const float*)d_in[14];
    const float* bo    = (const float*)d_in[15];

    float* out_h = (float*)d_out;
    float* out_z = out_h + (size_t)N_NODES * HD;

    float *pA = nullptr, *pB = nullptr;
    unsigned short* pW = nullptr;
    cudaGetSymbolAddress((void**)&pA, g_bufA);
    cudaGetSymbolAddress((void**)&pB, g_bufB);
    cudaGetSymbolAddress((void**)&pW, g_wperm);
    __half* pA16 = (__half*)pA;      // fp16 xw buffer
    __half* pB16 = (__half*)pB;      // fp16 aggregated features
    const size_t WSTRIDE = 2 * 128 * 128;

    const int TB = 256;
    dim3 nb_edge((N_EDGES + TB - 1) / TB);
    dim3 nb_warp(((size_t)N_NODES * 32 + TB - 1) / TB);
    dim3 nb_gemm((N_NODES + 127) / 128);

    const int SMEM128 = 65536 + 128 * 128 * 2 * 2;
    const int SMEM64  = 65536 + 128 * 64 * 2 * 2;
    cudaFuncSetAttribute((const void*)tc_gemm<128, false, true>,
                         cudaFuncAttributeMaxDynamicSharedMemorySize, SMEM128);
    cudaFuncSetAttribute((const void*)tc_gemm<128, true, true>,
                         cudaFuncAttributeMaxDynamicSharedMemorySize, SMEM128);
    cudaFuncSetAttribute((const void*)tc_gemm<64, false, false>,
                         cudaFuncAttributeMaxDynamicSharedMemorySize, SMEM64);

    // CSR build + weight conversion (4 launches)
    k_pre<<<NB_SCAN, 1024>>>((const unsigned int*)ei);
    k_convert_count<<<dim3(nb_edge.x, 2), TB>>>(ei, W1, Wg1, W2, Wg2, Wo);
    k_scan_fused<<<NB_SCAN, 1024>>>();
    k_fill_edges<<<nb_edge, TB>>>();

    // Layer 1: GCN (x fp32 -> xw fp16; agg out fp16)
    tc_gemm<128, false, true><<<nb_gemm, TB, SMEM128>>>(x, pW, nullptr, pA16, N_NODES, nullptr, nullptr);
    gcn_agg<true><<<nb_warp, TB>>>(pA16, b1, pB16);   // <- profiled launch #6

    // Layer 2: GAT (fp16 in, xw fp16, fused att dots; agg out fp16)
    tc_gemm<128, true, true><<<nb_gemm, TB, SMEM128>>>(pB16, pW + WSTRIDE, nullptr, pA16, N_NODES, asrc1, adst1);
    gat_agg<true><<<nb_warp, TB>>>(pA16, bg1, pB16);

    // Layer 3: GCN (fp16 chain)
    tc_gemm<128, true, true><<<nb_gemm, TB, SMEM128>>>(pB16, pW + 2 * WSTRIDE, nullptr, pA16, N_NODES, nullptr, nullptr);
    gcn_agg<true><<<nb_warp, TB>>>(pA16, b2, pB16);

    // Layer 4: GAT -> h into d_out (fp32 output, contract)
    tc_gemm<128, true, true><<<nb_gemm, TB, SMEM128>>>(pB16, pW + 3 * WSTRIDE, nullptr, pA16, N_NODES, asrc2, adst2);
    gat_agg<false><<<nb_warp, TB>>>(pA16, bg2, out_h);

    // Output head: z = h @ Wo + bo (fp32 in/out)
    tc_gemm<64, false, false><<<nb_gemm, TB, SMEM64>>>(out_h, pW + 4 * WSTRIDE, bo, out_z, N_NODES, nullptr, nullptr);
}

// round 10
// speedup vs baseline: 1.5006x; 1.0033x over previous
#include <cuda_runtime.h>
#include <cuda_bf16.h>
#include <cuda_fp16.h>
#include <math.h>
#include <stdint.h>

// Problem constants
#define N_NODES 50000
#define N_EDGES 800000
#define TOT_E   850000
#define HD      128
#define NB_SCAN 49            // ceil(50000/1024)

// ---------------- device scratch --------------------------------------------
__device__ float g_bufA[(size_t)N_NODES * HD];   // fp16 xw (reinterpreted)
__device__ float g_bufB[(size_t)N_NODES * HD];   // fp16 aggregated features
__device__ int   g_src[N_EDGES];
__device__ int   g_dst[N_EDGES];
__device__ int   g_flag;
__device__ int   g_cnt[N_NODES];
__device__ int   g_off2[N_NODES + 1];
__device__ int   g_csr[TOT_E];
__device__ int   g_bpub[NB_SCAN];
__device__ float g_inv[N_NODES];
__device__ float g_s[N_NODES];
__device__ float g_d[N_NODES];
__device__ float g_esc[TOT_E];          // fallback only (deg > 64)
__device__ unsigned short g_wperm[5][2 * 128 * 128];

// ---------------- warp MMA helper --------------------------------------------
__device__ __forceinline__ void mma16816(float* d, const uint32_t* a, const uint32_t* b) {
    asm volatile(
        "mma.sync.aligned.m16n8k16.row.col.f32.bf16.bf16.f32 "
        "{%0,%1,%2,%3}, {%4,%5,%6,%7}, {%8,%9}, {%0,%1,%2,%3};"
        : "+f"(d[0]), "+f"(d[1]), "+f"(d[2]), "+f"(d[3])
        : "r"(a[0]), "r"(a[1]), "r"(a[2]), "r"(a[3]), "r"(b[0]), "r"(b[1]));
}

__device__ __forceinline__ uint32_t pack_bf16(float x, float y) {
    __nv_bfloat16 hx = __float2bfloat16(x), hy = __float2bfloat16(y);
    return (uint32_t)__bfloat16_as_ushort(hx) |
           ((uint32_t)__bfloat16_as_ushort(hy) << 16);
}

// ---------------- pre: zero counts + init lookback + detect edge dtype --------
__global__ void k_pre(const unsigned int* __restrict__ w) {
    int i = blockIdx.x * 1024 + threadIdx.x;
    if (i < N_NODES) g_cnt[i] = 0;
    if (blockIdx.x == 1 && threadIdx.x < NB_SCAN) g_bpub[threadIdx.x] = -1;
    if (blockIdx.x == 0) {
        __shared__ int sflag;
        if (threadIdx.x == 0) sflag = 0;
        __syncthreads();
        if (w[2 * threadIdx.x + 1] != 0u) atomicOr(&sflag, 1);
        __syncthreads();
        if (threadIdx.x == 0) g_flag = sflag;
    }
}

// ---------------- fused: edge convert+count (y=0) | weight conversion (y=1) --
__global__ void k_convert_count(const void* __restrict__ ei,
                                const float* __restrict__ W1, const float* __restrict__ Wg1,
                                const float* __restrict__ W2, const float* __restrict__ Wg2,
                                const float* __restrict__ Wo) {
    if (blockIdx.y == 0) {
        int e = blockIdx.x * blockDim.x + threadIdx.x;
        if (e >= N_EDGES) return;
        int s, d;
        if (g_flag) {
            const int* p = (const int*)ei;
            s = p[e]; d = p[N_EDGES + e];
        } else {
            const long long* p = (const long long*)ei;
            s = (int)p[e]; d = (int)p[N_EDGES + e];
        }
        g_src[e] = s;
        g_dst[e] = d;
        atomicAdd(&g_cnt[d], 1);
    } else {
        int idx = blockIdx.x * blockDim.x + threadIdx.x;
        if (idx >= 4 * 16384 + 8192) return;
        int wsel, base, BN;
        if (idx < 16384)      { wsel = 0; base = 0;      BN = 128; }
        else if (idx < 32768) { wsel = 1; base = 16384;  BN = 128; }
        else if (idx < 49152) { wsel = 2; base = 32768;  BN = 128; }
        else if (idx < 65536) { wsel = 3; base = 49152;  BN = 128; }
        else                  { wsel = 4; base = 65536;  BN = 64;  }
        const float* W = (wsel == 0) ? W1 : (wsel == 1) ? Wg1 : (wsel == 2) ? W2
                       : (wsel == 3) ? Wg2 : Wo;
        int li = idx - base;
        int total = 128 * BN;
        int k = li / BN, n = li % BN;
        float v = W[li];
        __nv_bfloat16 h = __float2bfloat16(v);
        __nv_bfloat16 l = __float2bfloat16(v - __bfloat162float(h));
        int nt = n >> 3, kt = k >> 4, kk = k & 15;
        int reg = kk >> 3, klo = kk & 7;
        int lane = (n & 7) * 4 + (klo >> 1);
        int slot = ((nt * 8 + kt) * 32 + lane) * 2 + reg;
        int pos = slot * 2 + (kk & 1);
        g_wperm[wsel][pos] = __bfloat16_as_ushort(h);
        g_wperm[wsel][total + pos] = __bfloat16_as_ushort(l);
    }
}

// ---------------- single-kernel scan + finalize (decoupled lookback) ----------
__global__ void k_scan_fused() {
    __shared__ int sd[1024];
    __shared__ int s_prefix;
    int tid = threadIdx.x;
    int blk = blockIdx.x;
    int i = blk * 1024 + tid;
    int cnt = (i < N_NODES) ? g_cnt[i] + 1 : 0;   // +1 = self loop
    sd[tid] = cnt;
    __syncthreads();
    for (int off = 1; off < 1024; off <<= 1) {
        int t = (tid >= off) ? sd[tid - off] : 0;
        __syncthreads();
        sd[tid] += t;
        __syncthreads();
    }
    int incl = sd[tid];
    if (tid == 1023) *(volatile int*)&g_bpub[blk] = sd[1023];
    if (tid < 32) {
        int pre = 0;
        for (int j = tid; j < blk; j += 32) {
            int v;
            do { v = *(volatile int*)&g_bpub[j]; } while (v == -1);
            pre += v;
        }
#pragma unroll
        for (int o = 16; o; o >>= 1) pre += __shfl_xor_sync(0xffffffffu, pre, o);
        if (tid == 0) s_prefix = pre;
    }
    __syncthreads();
    if (i < N_NODES) {
        int b = s_prefix + incl - cnt;
        g_off2[i] = b;
        g_csr[b] = i;          // self loop
        g_cnt[i] = b + 1;      // fill cursor
        g_inv[i] = rsqrtf((float)cnt);
        if (i == N_NODES - 1) g_off2[N_NODES] = b + cnt;
    }
}

__global__ void k_fill_edges() {
    int e = blockIdx.x * blockDim.x + threadIdx.x;
    if (e < N_EDGES) {
        int pos = atomicAdd(&g_cnt[g_dst[e]], 1);
        g_csr[pos] = g_src[e];
    }
}

// ---------------- HMMA bf16x3 GEMM, fp16/fp32 in & out, fused att dots --------
template <int BN, bool IN16, bool OUT16>
__global__ void __launch_bounds__(256)
tc_gemm(const void* __restrict__ Xv, const unsigned short* __restrict__ wperm,
        const float* __restrict__ bias, void* __restrict__ Yv, int M,
        const float* __restrict__ a_s, const float* __restrict__ a_d) {
    extern __shared__ char smem[];
    constexpr int NT = BN / 16;
    constexpr int OFF_ALO = 32768;
    constexpr int OFF_B   = 65536;
    constexpr int B_HALF  = 128 * BN * 2;

    int tid  = threadIdx.x;
    int wid  = tid >> 5;
    int lane = tid & 31;
    int row0 = blockIdx.x * 128;

    {
        const uint4* src = (const uint4*)wperm;
        uint4* dst = (uint4*)(smem + OFF_B);
        int n16 = (2 * B_HALF) / 16;
        for (int i = tid; i < n16; i += 256) dst[i] = src[i];
    }
    {
        uint32_t* ah = (uint32_t*)smem;
        uint32_t* al = (uint32_t*)(smem + OFF_ALO);
#pragma unroll
        for (int it = 0; it < 16; ++it) {
            int idx = it * 256 + tid;
            int r = idx >> 5;
            int c = (idx & 31) * 4;
            int gr = row0 + r;
            float4 v = make_float4(0.f, 0.f, 0.f, 0.f);
            if (gr < M) {
                if (IN16) {
                    uint2 u = ((const uint2*)Xv)[(size_t)gr * 32 + (idx & 31)];
                    float2 f0 = __half22float2(*reinterpret_cast<__half2*>(&u.x));
                    float2 f1 = __half22float2(*reinterpret_cast<__half2*>(&u.y));
                    v = make_float4(f0.x, f0.y, f1.x, f1.y);
                } else {
                    v = ((const float4*)Xv)[(size_t)gr * 32 + (idx & 31)];
                }
            }
            __nv_bfloat16 h0 = __float2bfloat16(v.x), h1 = __float2bfloat16(v.y);
            __nv_bfloat16 h2 = __float2bfloat16(v.z), h3 = __float2bfloat16(v.w);
            float l0 = v.x - __bfloat162float(h0), l1 = v.y - __bfloat162float(h1);
            float l2 = v.z - __bfloat162float(h2), l3 = v.w - __bfloat162float(h3);
            uint32_t hi0 = (uint32_t)__bfloat16_as_ushort(h0) |
                           ((uint32_t)__bfloat16_as_ushort(h1) << 16);
            uint32_t hi1 = (uint32_t)__bfloat16_as_ushort(h2) |
                           ((uint32_t)__bfloat16_as_ushort(h3) << 16);
            uint32_t lo0 = pack_bf16(l0, l1);
            uint32_t lo1 = pack_bf16(l2, l3);
            int mt = r >> 4, rr = r & 15;
            int kt = c >> 4, cc = c & 15;
            int reg = ((cc >> 3) << 1) | (rr >> 3);
            int ln0 = (rr & 7) * 4 + ((cc & 7) >> 1);
            int base = (mt * 8 + kt) * 32;
            ah[(base + ln0) * 4 + reg]     = hi0;
            ah[(base + ln0 + 1) * 4 + reg] = hi1;
            al[(base + ln0) * 4 + reg]     = lo0;
            al[(base + ln0 + 1) * 4 + reg] = lo1;
        }
    }
    __syncthreads();

    int wm = wid & 3;
    int wn = wid >> 2;
    float acc[2][NT][4];
#pragma unroll
    for (int i = 0; i < 2; ++i)
#pragma unroll
        for (int j = 0; j < NT; ++j)
#pragma unroll
            for (int q = 0; q < 4; ++q) acc[i][j][q] = 0.f;

    const uint4* Ah = (const uint4*)smem;
    const uint4* Al = (const uint4*)(smem + OFF_ALO);
    const uint2* Bh = (const uint2*)(smem + OFF_B);
    const uint2* Bl = (const uint2*)(smem + OFF_B + B_HALF);
#pragma unroll
    for (int kt = 0; kt < 8; ++kt) {
        uint4 ah0 = Ah[((wm * 2 + 0) * 8 + kt) * 32 + lane];
        uint4 ah1 = Ah[((wm * 2 + 1) * 8 + kt) * 32 + lane];
        uint4 al0 = Al[((wm * 2 + 0) * 8 + kt) * 32 + lane];
        uint4 al1 = Al[((wm * 2 + 1) * 8 + kt) * 32 + lane];
        uint2 b[NT];
#pragma unroll
        for (int j = 0; j < NT; ++j)
            b[j] = Bh[((wn * NT + j) * 8 + kt) * 32 + lane];
#pragma unroll
        for (int j = 0; j < NT; ++j) {
            mma16816(acc[0][j], (const uint32_t*)&ah0, (const uint32_t*)&b[j]);
            mma16816(acc[1][j], (const uint32_t*)&ah1, (const uint32_t*)&b[j]);
        }
#pragma unroll
        for (int j = 0; j < NT; ++j) {
            mma16816(acc[0][j], (const uint32_t*)&al0, (const uint32_t*)&b[j]);
            mma16816(acc[1][j], (const uint32_t*)&al1, (const uint32_t*)&b[j]);
        }
#pragma unroll
        for (int j = 0; j < NT; ++j)
            b[j] = Bl[((wn * NT + j) * 8 + kt) * 32 + lane];
#pragma unroll
        for (int j = 0; j < NT; ++j) {
            mma16816(acc[0][j], (const uint32_t*)&ah0, (const uint32_t*)&b[j]);
            mma16816(acc[1][j], (const uint32_t*)&ah1, (const uint32_t*)&b[j]);
        }
    }

    int rbase = row0 + wm * 32 + (lane >> 2);
    int cbase = wn * NT * 8 + (lane & 3) * 2;
#pragma unroll
    for (int i = 0; i < 2; ++i) {
        int r = rbase + i * 16;
#pragma unroll
        for (int j = 0; j < NT; ++j) {
            int cc = cbase + j * 8;
            float bx = 0.f, by = 0.f;
            if (bias) { bx = bias[cc]; by = bias[cc + 1]; }
            if (OUT16) {
                __half* Y = (__half*)Yv;
                if (r < M)
                    *(__half2*)&Y[(size_t)r * BN + cc] =
                        __floats2half2_rn(acc[i][j][0] + bx, acc[i][j][1] + by);
                if (r + 8 < M)
                    *(__half2*)&Y[(size_t)(r + 8) * BN + cc] =
                        __floats2half2_rn(acc[i][j][2] + bx, acc[i][j][3] + by);
            } else {
                float* Y = (float*)Yv;
                if (r < M) {
                    float2 v0 = make_float2(acc[i][j][0] + bx, acc[i][j][1] + by);
                    *(float2*)&Y[(size_t)r * BN + cc] = v0;
                }
                if (r + 8 < M) {
                    float2 v1 = make_float2(acc[i][j][2] + bx, acc[i][j][3] + by);
                    *(float2*)&Y[(size_t)(r + 8) * BN + cc] = v1;
                }
            }
        }
    }

    if (a_s) {
        float ps[2][2] = {{0.f, 0.f}, {0.f, 0.f}};
        float pd[2][2] = {{0.f, 0.f}, {0.f, 0.f}};
#pragma unroll
        for (int i = 0; i < 2; ++i)
#pragma unroll
            for (int j = 0; j < NT; ++j) {
                int cc = cbase + j * 8;
                float as0 = a_s[cc], as1 = a_s[cc + 1];
                float ad0 = a_d[cc], ad1 = a_d[cc + 1];
                ps[i][0] += acc[i][j][0] * as0 + acc[i][j][1] * as1;
                pd[i][0] += acc[i][j][0] * ad0 + acc[i][j][1] * ad1;
                ps[i][1] += acc[i][j][2] * as0 + acc[i][j][3] * as1;
                pd[i][1] += acc[i][j][2] * ad0 + acc[i][j][3] * ad1;
            }
#pragma unroll
        for (int i = 0; i < 2; ++i)
#pragma unroll
            for (int h = 0; h < 2; ++h) {
                float s = ps[i][h], d = pd[i][h];
                s += __shfl_xor_sync(0xffffffffu, s, 1);
                s += __shfl_xor_sync(0xffffffffu, s, 2);
                d += __shfl_xor_sync(0xffffffffu, d, 1);
                d += __shfl_xor_sync(0xffffffffu, d, 2);
                if ((lane & 3) == 0) {
                    int r = row0 + wm * 32 + i * 16 + h * 8 + (lane >> 2);
                    if (r < M) {
                        atomicAdd(&g_s[r], s);
                        atomicAdd(&g_d[r], d);
                    }
                }
            }
    }
}

// ---------------- half-warp gather helpers -------------------------------------
// Row = 128 halfs = 16 uint4; lane gl in [0,16) holds 8 halfs (uint4).
struct F8 { float v[8]; };

__device__ __forceinline__ F8 load_row8(const uint4* xw4, int s, int gl) {
    uint4 u = xw4[(size_t)s * 16 + gl];
    F8 r;
    float2 f;
    f = __half22float2(*reinterpret_cast<__half2*>(&u.x)); r.v[0] = f.x; r.v[1] = f.y;
    f = __half22float2(*reinterpret_cast<__half2*>(&u.y)); r.v[2] = f.x; r.v[3] = f.y;
    f = __half22float2(*reinterpret_cast<__half2*>(&u.z)); r.v[4] = f.x; r.v[5] = f.y;
    f = __half22float2(*reinterpret_cast<__half2*>(&u.w)); r.v[6] = f.x; r.v[7] = f.y;
    return r;
}

__device__ __forceinline__ void store_row8(void* out, int w, int gl,
                                           const float* a, bool out16) {
    if (out16) {
        uint4 u;
        __half2 h;
        h = __floats2half2_rn(a[0], a[1]); u.x = *reinterpret_cast<uint32_t*>(&h);
        h = __floats2half2_rn(a[2], a[3]); u.y = *reinterpret_cast<uint32_t*>(&h);
        h = __floats2half2_rn(a[4], a[5]); u.z = *reinterpret_cast<uint32_t*>(&h);
        h = __floats2half2_rn(a[6], a[7]); u.w = *reinterpret_cast<uint32_t*>(&h);
        ((uint4*)out)[(size_t)w * 16 + gl] = u;
    } else {
        float* o = (float*)out + (size_t)w * 128 + gl * 8;
        *(float4*)o       = make_float4(a[0], a[1], a[2], a[3]);
        *(float4*)(o + 4) = make_float4(a[4], a[5], a[6], a[7]);
    }
}

// ---------------- GCN aggregate: half-warp per node ----------------------------
template <bool OUT16>
__global__ void gcn_agg(const __half* __restrict__ xw,
                        const float* __restrict__ bias,
                        void* __restrict__ out) {
    int gwarp = (blockIdx.x * blockDim.x + threadIdx.x) >> 5;
    int lane = threadIdx.x & 31;
    int grp = lane >> 4, gl = lane & 15;
    int w = gwarp * 2 + grp;
    if (w >= N_NODES) return;
    if (gl == 0) { g_s[w] = 0.f; g_d[w] = 0.f; }
    int beg = g_off2[w], end = g_off2[w + 1];
    float invd = g_inv[w];
    const uint4* xw4 = (const uint4*)xw;
    float acc[8] = {0.f, 0.f, 0.f, 0.f, 0.f, 0.f, 0.f, 0.f};
    int p = beg;
    for (; p + 1 < end; p += 2) {
        int s0 = g_csr[p], s1 = g_csr[p + 1];
        float c0 = invd * g_inv[s0];
        float c1 = invd * g_inv[s1];
        F8 v0 = load_row8(xw4, s0, gl);
        F8 v1 = load_row8(xw4, s1, gl);
#pragma unroll
        for (int q = 0; q < 8; ++q) acc[q] += c0 * v0.v[q] + c1 * v1.v[q];
    }
    if (p < end) {
        int s0 = g_csr[p];
        float c0 = invd * g_inv[s0];
        F8 v0 = load_row8(xw4, s0, gl);
#pragma unroll
        for (int q = 0; q < 8; ++q) acc[q] += c0 * v0.v[q];
    }
    const float4* b4 = (const float4*)bias;
    float4 b0 = b4[gl * 2], b1 = b4[gl * 2 + 1];
    acc[0] = fmaxf(acc[0] + b0.x, 0.f); acc[1] = fmaxf(acc[1] + b0.y, 0.f);
    acc[2] = fmaxf(acc[2] + b0.z, 0.f); acc[3] = fmaxf(acc[3] + b0.w, 0.f);
    acc[4] = fmaxf(acc[4] + b1.x, 0.f); acc[5] = fmaxf(acc[5] + b1.y, 0.f);
    acc[6] = fmaxf(acc[6] + b1.z, 0.f); acc[7] = fmaxf(acc[7] + b1.w, 0.f);
    store_row8(out, w, gl, acc, OUT16);
}

// ---------------- GAT aggregate: half-warp per node, register-cached -----------
template <bool OUT16>
__global__ void gat_agg(const __half* __restrict__ xw,
                        const float* __restrict__ bias,
                        void* __restrict__ out) {
    int gwarp = (blockIdx.x * blockDim.x + threadIdx.x) >> 5;
    int lane = threadIdx.x & 31;
    int grp = lane >> 4, gl = lane & 15;
    int w = gwarp * 2 + grp;
    if (w >= N_NODES) return;
    int beg = g_off2[w], end = g_off2[w + 1];
    int deg = end - beg;
    float dd = g_d[w];
    const uint4* xw4 = (const uint4*)xw;
    float acc[8] = {0.f, 0.f, 0.f, 0.f, 0.f, 0.f, 0.f, 0.f};

    if (deg <= 64) {
        // 4 cached slots per lane: positions beg + gl + 16*r
        int sc[4];
        float ex[4];
        float m = -1e30f;
#pragma unroll
        for (int rr = 0; rr < 4; ++rr) {
            int p = beg + gl + 16 * rr;
            sc[rr] = 0; ex[rr] = -1e30f;
            if (p < end) {
                sc[rr] = g_csr[p];
                float t = g_s[sc[rr]] + dd;
                ex[rr] = (t > 0.f) ? t : 0.2f * t;
            }
            m = fmaxf(m, ex[rr]);
        }
#pragma unroll
        for (int o = 8; o; o >>= 1) m = fmaxf(m, __shfl_xor_sync(0xffffffffu, m, o));
        float sum = 0.f;
#pragma unroll
        for (int rr = 0; rr < 4; ++rr) {
            int p = beg + gl + 16 * rr;
            ex[rr] = (p < end) ? __expf(ex[rr] - m) : 0.f;
            sum += ex[rr];
        }
#pragma unroll
        for (int o = 8; o; o >>= 1) sum += __shfl_xor_sync(0xffffffffu, sum, o);
        float invden = 1.0f / sum;

        int base = grp << 4;
        int idx = 0;
        for (; idx + 1 < deg; idx += 2) {
            int r0 = idx >> 4,      l0 = (idx & 15) + base;
            int r1 = (idx + 1) >> 4, l1 = ((idx + 1) & 15) + base;
            float e0 = (r0 == 0) ? ex[0] : (r0 == 1) ? ex[1] : (r0 == 2) ? ex[2] : ex[3];
            int   c0 = (r0 == 0) ? sc[0] : (r0 == 1) ? sc[1] : (r0 == 2) ? sc[2] : sc[3];
            float e1 = (r1 == 0) ? ex[0] : (r1 == 1) ? ex[1] : (r1 == 2) ? ex[2] : ex[3];
            int   c1 = (r1 == 0) ? sc[0] : (r1 == 1) ? sc[1] : (r1 == 2) ? sc[2] : sc[3];
            float wa = __shfl_sync(0xffffffffu, e0, l0) * invden;
            int   sa = __shfl_sync(0xffffffffu, c0, l0);
            float wb = __shfl_sync(0xffffffffu, e1, l1) * invden;
            int   sb = __shfl_sync(0xffffffffu, c1, l1);
            F8 va = load_row8(xw4, sa, gl);
            F8 vb = load_row8(xw4, sb, gl);
#pragma unroll
            for (int q = 0; q < 8; ++q) acc[q] += wa * va.v[q] + wb * vb.v[q];
        }
        if (idx < deg) {
            int r0 = idx >> 4, l0 = (idx & 15) + base;
            float e0 = (r0 == 0) ? ex[0] : (r0 == 1) ? ex[1] : (r0 == 2) ? ex[2] : ex[3];
            int   c0 = (r0 == 0) ? sc[0] : (r0 == 1) ? sc[1] : (r0 == 2) ? sc[2] : sc[3];
            float wa = __shfl_sync(0xffffffffu, e0, l0) * invden;
            int   sa = __shfl_sync(0xffffffffu, c0, l0);
            F8 va = load_row8(xw4, sa, gl);
#pragma unroll
            for (int q = 0; q < 8; ++q) acc[q] += wa * va.v[q];
        }
    } else {
        // fallback via g_esc, 16-lane strides
        float m = -1e30f;
        for (int p = beg + gl; p < end; p += 16) {
            int s = g_csr[p];
            float e = g_s[s] + dd;
            e = (e > 0.f) ? e : 0.2f * e;
            g_esc[p] = e;
            m = fmaxf(m, e);
        }
#pragma unroll
        for (int o = 8; o; o >>= 1) m = fmaxf(m, __shfl_xor_sync(0xffffffffu, m, o));
        float sum = 0.f;
        for (int p = beg + gl; p < end; p += 16) {
            float e = __expf(g_esc[p] - m);
            g_esc[p] = e;
            sum += e;
        }
#pragma unroll
        for (int o = 8; o; o >>= 1) sum += __shfl_xor_sync(0xffffffffu, sum, o);
        float invden = 1.0f / sum;
        __syncwarp();
        for (int p = beg; p < end; ++p) {
            int s = g_csr[p];
            float wgt = g_esc[p] * invden;
            F8 v = load_row8(xw4, s, gl);
#pragma unroll
            for (int q = 0; q < 8; ++q) acc[q] += wgt * v.v[q];
        }
    }

    const float4* b4 = (const float4*)bias;
    float4 b0 = b4[gl * 2], b1 = b4[gl * 2 + 1];
    acc[0] = fmaxf(acc[0] + b0.x, 0.f); acc[1] = fmaxf(acc[1] + b0.y, 0.f);
    acc[2] = fmaxf(acc[2] + b0.z, 0.f); acc[3] = fmaxf(acc[3] + b0.w, 0.f);
    acc[4] = fmaxf(acc[4] + b1.x, 0.f); acc[5] = fmaxf(acc[5] + b1.y, 0.f);
    acc[6] = fmaxf(acc[6] + b1.z, 0.f); acc[7] = fmaxf(acc[7] + b1.w, 0.f);
    store_row8(out, w, gl, acc, OUT16);
}

// ---------------- host launch ---------------------------------------------------
extern "C" void kernel_launch(void* const* d_in, const int* in_sizes, int n_in,
                              void* d_out, int out_size) {
    const float* x     = (const float*)d_in[0];
    const void*  ei    = d_in[1];
    const float* W1    = (const float*)d_in[2];
    const float* b1    = (const float*)d_in[3];
    const float* Wg1   = (const float*)d_in[4];
    const float* asrc1 = (const float*)d_in[5];
    const float* adst1 = (const float*)d_in[6];
    const float* bg1   = (const float*)d_in[7];
    const float* W2    = (const float*)d_in[8];
    const float* b2    = (const float*)d_in[9];
    const float* Wg2   = (const float*)d_in[10];
    const float* asrc2 = (const float*)d_in[11];
    const float* adst2 = (const float*)d_in[12];
    const float* bg2   = (const float*)d_in[13];
    const float* Wo    = (const float*)d_in[14];
    const float* bo    = (const float*)d_in[15];

    float* out_h = (float*)d_out;
    float* out_z = out_h + (size_t)N_NODES * HD;

    float *pA = nullptr, *pB = nullptr;
    unsigned short* pW = nullptr;
    cudaGetSymbolAddress((void**)&pA, g_bufA);
    cudaGetSymbolAddress((void**)&pB, g_bufB);
    cudaGetSymbolAddress((void**)&pW, g_wperm);
    __half* pA16 = (__half*)pA;
    __half* pB16 = (__half*)pB;
    const size_t WSTRIDE = 2 * 128 * 128;

    const int TB = 256;
    dim3 nb_edge((N_EDGES + TB - 1) / TB);
    // half-warp per node: 2 nodes/warp, 8 warps/block -> 16 nodes/block
    dim3 nb_hw((N_NODES + 15) / 16);
    dim3 nb_gemm((N_NODES + 127) / 128);

    const int SMEM128 = 65536 + 128 * 128 * 2 * 2;
    const int SMEM64  = 65536 + 128 * 64 * 2 * 2;
    cudaFuncSetAttribute((const void*)tc_gemm<128, false, true>,
                         cudaFuncAttributeMaxDynamicSharedMemorySize, SMEM128);
    cudaFuncSetAttribute((const void*)tc_gemm<128, true, true>,
                         cudaFuncAttributeMaxDynamicSharedMemorySize, SMEM128);
    cudaFuncSetAttribute((const void*)tc_gemm<64, false, false>,
                         cudaFuncAttributeMaxDynamicSharedMemorySize, SMEM64);

    // CSR build + weight conversion (4 launches)
    k_pre<<<NB_SCAN, 1024>>>((const unsigned int*)ei);
    k_convert_count<<<dim3(nb_edge.x, 2), TB>>>(ei, W1, Wg1, W2, Wg2, Wo);
    k_scan_fused<<<NB_SCAN, 1024>>>();
    k_fill_edges<<<nb_edge, TB>>>();

    // Layer 1: GCN
    tc_gemm<128, false, true><<<nb_gemm, TB, SMEM128>>>(x, pW, nullptr, pA16, N_NODES, nullptr, nullptr);
    gcn_agg<true><<<nb_hw, TB>>>(pA16, b1, pB16);

    // Layer 2: GAT
    tc_gemm<128, true, true><<<nb_gemm, TB, SMEM128>>>(pB16, pW + WSTRIDE, nullptr, pA16, N_NODES, asrc1, adst1);
    gat_agg<true><<<nb_hw, TB>>>(pA16, bg1, pB16);

    // Layer 3: GCN
    tc_gemm<128, true, true><<<nb_gemm, TB, SMEM128>>>(pB16, pW + 2 * WSTRIDE, nullptr, pA16, N_NODES, nullptr, nullptr);
    gcn_agg<true><<<nb_hw, TB>>>(pA16, b2, pB16);

    // Layer 4: GAT -> h into d_out (fp32)
    tc_gemm<128, true, true><<<nb_gemm, TB, SMEM128>>>(pB16, pW + 3 * WSTRIDE, nullptr, pA16, N_NODES, asrc2, adst2);
    gat_agg<false><<<nb_hw, TB>>>(pA16, bg2, out_h);

    // Output head: z = h @ Wo + bo (fp32 in/out)
    tc_gemm<64, false, false><<<nb_gemm, TB, SMEM64>>>(out_h, pW + 4 * WSTRIDE, bo, out_z, N_NODES, nullptr, nullptr);
}

// round 11
// speedup vs baseline: 2.0336x; 1.3552x over previous
#include <cuda_runtime.h>
#include <cuda_fp16.h>
#include <math.h>
#include <stdint.h>

// Problem constants
#define N_NODES 50000
#define N_EDGES 800000
#define TOT_E   850000
#define HD      128
#define NB_SCAN 49            // ceil(50000/1024)

// ---------------- device scratch --------------------------------------------
__device__ float g_bufA[(size_t)N_NODES * HD];   // fp16 xw (reinterpreted)
__device__ float g_bufB[(size_t)N_NODES * HD];   // fp16 aggregated features
__device__ int   g_src[N_EDGES];
__device__ int   g_dst[N_EDGES];
__device__ int   g_flag;
__device__ int   g_cnt[N_NODES];
__device__ int   g_off2[N_NODES + 1];
__device__ int   g_csr[TOT_E];
__device__ int   g_bpub[NB_SCAN];
__device__ float g_inv[N_NODES];
__device__ float g_s[N_NODES];
__device__ float g_d[N_NODES];
__device__ float g_esc[TOT_E];          // fallback only (deg > 64)
__device__ unsigned short g_wperm[5][128 * 128];  // fp16 fragment-permuted weights

// ---------------- warp MMA helper (fp16 inputs, fp32 accum) -------------------
__device__ __forceinline__ void mma16816(float* d, const uint32_t* a, const uint32_t* b) {
    asm volatile(
        "mma.sync.aligned.m16n8k16.row.col.f32.f16.f16.f32 "
        "{%0,%1,%2,%3}, {%4,%5,%6,%7}, {%8,%9}, {%0,%1,%2,%3};"
        : "+f"(d[0]), "+f"(d[1]), "+f"(d[2]), "+f"(d[3])
        : "r"(a[0]), "r"(a[1]), "r"(a[2]), "r"(a[3]), "r"(b[0]), "r"(b[1]));
}

// ---------------- pre: zero counts + init lookback + detect edge dtype --------
__global__ void k_pre(const unsigned int* __restrict__ w) {
    int i = blockIdx.x * 1024 + threadIdx.x;
    if (i < N_NODES) g_cnt[i] = 0;
    if (blockIdx.x == 1 && threadIdx.x < NB_SCAN) g_bpub[threadIdx.x] = -1;
    if (blockIdx.x == 0) {
        __shared__ int sflag;
        if (threadIdx.x == 0) sflag = 0;
        __syncthreads();
        if (w[2 * threadIdx.x + 1] != 0u) atomicOr(&sflag, 1);
        __syncthreads();
        if (threadIdx.x == 0) g_flag = sflag;
    }
}

// ---------------- fused: edge convert+count (y=0) | weight conversion (y=1) --
__global__ void k_convert_count(const void* __restrict__ ei,
                                const float* __restrict__ W1, const float* __restrict__ Wg1,
                                const float* __restrict__ W2, const float* __restrict__ Wg2,
                                const float* __restrict__ Wo) {
    if (blockIdx.y == 0) {
        int e = blockIdx.x * blockDim.x + threadIdx.x;
        if (e >= N_EDGES) return;
        int s, d;
        if (g_flag) {
            const int* p = (const int*)ei;
            s = p[e]; d = p[N_EDGES + e];
        } else {
            const long long* p = (const long long*)ei;
            s = (int)p[e]; d = (int)p[N_EDGES + e];
        }
        g_src[e] = s;
        g_dst[e] = d;
        atomicAdd(&g_cnt[d], 1);
    } else {
        int idx = blockIdx.x * blockDim.x + threadIdx.x;
        if (idx >= 4 * 16384 + 8192) return;
        int wsel, base, BN;
        if (idx < 16384)      { wsel = 0; base = 0;      BN = 128; }
        else if (idx < 32768) { wsel = 1; base = 16384;  BN = 128; }
        else if (idx < 49152) { wsel = 2; base = 32768;  BN = 128; }
        else if (idx < 65536) { wsel = 3; base = 49152;  BN = 128; }
        else                  { wsel = 4; base = 65536;  BN = 64;  }
        const float* W = (wsel == 0) ? W1 : (wsel == 1) ? Wg1 : (wsel == 2) ? W2
                       : (wsel == 3) ? Wg2 : Wo;
        int li = idx - base;
        int k = li / BN, n = li % BN;
        __half h = __float2half_rn(W[li]);
        int nt = n >> 3, kt = k >> 4, kk = k & 15;
        int reg = kk >> 3, klo = kk & 7;
        int lane = (n & 7) * 4 + (klo >> 1);
        int slot = ((nt * 8 + kt) * 32 + lane) * 2 + reg;
        int pos = slot * 2 + (kk & 1);
        g_wperm[wsel][pos] = __half_as_ushort(h);
    }
}

// ---------------- single-kernel scan + finalize (decoupled lookback) ----------
__global__ void k_scan_fused() {
    __shared__ int sd[1024];
    __shared__ int s_prefix;
    int tid = threadIdx.x;
    int blk = blockIdx.x;
    int i = blk * 1024 + tid;
    int cnt = (i < N_NODES) ? g_cnt[i] + 1 : 0;   // +1 = self loop
    sd[tid] = cnt;
    __syncthreads();
    for (int off = 1; off < 1024; off <<= 1) {
        int t = (tid >= off) ? sd[tid - off] : 0;
        __syncthreads();
        sd[tid] += t;
        __syncthreads();
    }
    int incl = sd[tid];
    if (tid == 1023) *(volatile int*)&g_bpub[blk] = sd[1023];
    if (tid < 32) {
        int pre = 0;
        for (int j = tid; j < blk; j += 32) {
            int v;
            do { v = *(volatile int*)&g_bpub[j]; } while (v == -1);
            pre += v;
        }
#pragma unroll
        for (int o = 16; o; o >>= 1) pre += __shfl_xor_sync(0xffffffffu, pre, o);
        if (tid == 0) s_prefix = pre;
    }
    __syncthreads();
    if (i < N_NODES) {
        int b = s_prefix + incl - cnt;
        g_off2[i] = b;
        g_csr[b] = i;          // self loop
        g_cnt[i] = b + 1;      // fill cursor
        g_inv[i] = rsqrtf((float)cnt);
        if (i == N_NODES - 1) g_off2[N_NODES] = b + cnt;
    }
}

__global__ void k_fill_edges() {
    int e = blockIdx.x * blockDim.x + threadIdx.x;
    if (e < N_EDGES) {
        int pos = atomicAdd(&g_cnt[g_dst[e]], 1);
        g_csr[pos] = g_src[e];
    }
}

// ---------------- single-pass fp16 HMMA GEMM + fused att dots ------------------
// smem: A frag (32 KB) + B frag (BN*128*2 B) -> 64 KB @ BN=128 -> 2+ blocks/SM
template <int BN, bool IN16, bool OUT16>
__global__ void __launch_bounds__(256)
tc_gemm(const void* __restrict__ Xv, const unsigned short* __restrict__ wperm,
        const float* __restrict__ bias, void* __restrict__ Yv, int M,
        const float* __restrict__ a_s, const float* __restrict__ a_d) {
    extern __shared__ char smem[];
    constexpr int NT = BN / 16;
    constexpr int OFF_B = 32768;
    constexpr int B_BYTES = 128 * BN * 2;

    int tid  = threadIdx.x;
    int wid  = tid >> 5;
    int lane = tid & 31;
    int row0 = blockIdx.x * 128;

    // copy permuted fp16 weights to smem
    {
        const uint4* src = (const uint4*)wperm;
        uint4* dst = (uint4*)(smem + OFF_B);
        int n16 = B_BYTES / 16;
        for (int i = tid; i < n16; i += 256) dst[i] = src[i];
    }
    // A tile -> fragment-permuted fp16 smem
    {
        uint32_t* ah = (uint32_t*)smem;
#pragma unroll
        for (int it = 0; it < 16; ++it) {
            int idx = it * 256 + tid;
            int r = idx >> 5;
            int c = (idx & 31) * 4;
            int gr = row0 + r;
            uint32_t hi0 = 0, hi1 = 0;
            if (gr < M) {
                if (IN16) {
                    uint2 u = ((const uint2*)Xv)[(size_t)gr * 32 + (idx & 31)];
                    hi0 = u.x; hi1 = u.y;        // fp16 passthrough, no convert
                } else {
                    float4 v = ((const float4*)Xv)[(size_t)gr * 32 + (idx & 31)];
                    __half2 h0 = __floats2half2_rn(v.x, v.y);
                    __half2 h1 = __floats2half2_rn(v.z, v.w);
                    hi0 = *reinterpret_cast<uint32_t*>(&h0);
                    hi1 = *reinterpret_cast<uint32_t*>(&h1);
                }
            }
            int mt = r >> 4, rr = r & 15;
            int kt = c >> 4, cc = c & 15;
            int reg = ((cc >> 3) << 1) | (rr >> 3);
            int ln0 = (rr & 7) * 4 + ((cc & 7) >> 1);
            int base = (mt * 8 + kt) * 32;
            ah[(base + ln0) * 4 + reg]     = hi0;
            ah[(base + ln0 + 1) * 4 + reg] = hi1;
        }
    }
    __syncthreads();

    int wm = wid & 3;
    int wn = wid >> 2;
    float acc[2][NT][4];
#pragma unroll
    for (int i = 0; i < 2; ++i)
#pragma unroll
        for (int j = 0; j < NT; ++j)
#pragma unroll
            for (int q = 0; q < 4; ++q) acc[i][j][q] = 0.f;

    const uint4* Ah = (const uint4*)smem;
    const uint2* Bh = (const uint2*)(smem + OFF_B);
#pragma unroll
    for (int kt = 0; kt < 8; ++kt) {
        uint4 a0 = Ah[((wm * 2 + 0) * 8 + kt) * 32 + lane];
        uint4 a1 = Ah[((wm * 2 + 1) * 8 + kt) * 32 + lane];
        uint2 b[NT];
#pragma unroll
        for (int j = 0; j < NT; ++j)
            b[j] = Bh[((wn * NT + j) * 8 + kt) * 32 + lane];
#pragma unroll
        for (int j = 0; j < NT; ++j) {
            mma16816(acc[0][j], (const uint32_t*)&a0, (const uint32_t*)&b[j]);
            mma16816(acc[1][j], (const uint32_t*)&a1, (const uint32_t*)&b[j]);
        }
    }

    int rbase = row0 + wm * 32 + (lane >> 2);
    int cbase = wn * NT * 8 + (lane & 3) * 2;
#pragma unroll
    for (int i = 0; i < 2; ++i) {
        int r = rbase + i * 16;
#pragma unroll
        for (int j = 0; j < NT; ++j) {
            int cc = cbase + j * 8;
            float bx = 0.f, by = 0.f;
            if (bias) { bx = bias[cc]; by = bias[cc + 1]; }
            if (OUT16) {
                __half* Y = (__half*)Yv;
                if (r < M)
                    *(__half2*)&Y[(size_t)r * BN + cc] =
                        __floats2half2_rn(acc[i][j][0] + bx, acc[i][j][1] + by);
                if (r + 8 < M)
                    *(__half2*)&Y[(size_t)(r + 8) * BN + cc] =
                        __floats2half2_rn(acc[i][j][2] + bx, acc[i][j][3] + by);
            } else {
                float* Y = (float*)Yv;
                if (r < M) {
                    float2 v0 = make_float2(acc[i][j][0] + bx, acc[i][j][1] + by);
                    *(float2*)&Y[(size_t)r * BN + cc] = v0;
                }
                if (r + 8 < M) {
                    float2 v1 = make_float2(acc[i][j][2] + bx, acc[i][j][3] + by);
                    *(float2*)&Y[(size_t)(r + 8) * BN + cc] = v1;
                }
            }
        }
    }

    if (a_s) {
        float ps[2][2] = {{0.f, 0.f}, {0.f, 0.f}};
        float pd[2][2] = {{0.f, 0.f}, {0.f, 0.f}};
#pragma unroll
        for (int i = 0; i < 2; ++i)
#pragma unroll
            for (int j = 0; j < NT; ++j) {
                int cc = cbase + j * 8;
                float as0 = a_s[cc], as1 = a_s[cc + 1];
                float ad0 = a_d[cc], ad1 = a_d[cc + 1];
                ps[i][0] += acc[i][j][0] * as0 + acc[i][j][1] * as1;
                pd[i][0] += acc[i][j][0] * ad0 + acc[i][j][1] * ad1;
                ps[i][1] += acc[i][j][2] * as0 + acc[i][j][3] * as1;
                pd[i][1] += acc[i][j][2] * ad0 + acc[i][j][3] * ad1;
            }
#pragma unroll
        for (int i = 0; i < 2; ++i)
#pragma unroll
            for (int h = 0; h < 2; ++h) {
                float s = ps[i][h], d = pd[i][h];
                s += __shfl_xor_sync(0xffffffffu, s, 1);
                s += __shfl_xor_sync(0xffffffffu, s, 2);
                d += __shfl_xor_sync(0xffffffffu, d, 1);
                d += __shfl_xor_sync(0xffffffffu, d, 2);
                if ((lane & 3) == 0) {
                    int r = row0 + wm * 32 + i * 16 + h * 8 + (lane >> 2);
                    if (r < M) {
                        atomicAdd(&g_s[r], s);
                        atomicAdd(&g_d[r], d);
                    }
                }
            }
    }
}

// ---------------- half-warp gather helpers -------------------------------------
struct F8 { float v[8]; };

__device__ __forceinline__ F8 load_row8(const uint4* xw4, int s, int gl) {
    uint4 u = xw4[(size_t)s * 16 + gl];
    F8 r;
    float2 f;
    f = __half22float2(*reinterpret_cast<__half2*>(&u.x)); r.v[0] = f.x; r.v[1] = f.y;
    f = __half22float2(*reinterpret_cast<__half2*>(&u.y)); r.v[2] = f.x; r.v[3] = f.y;
    f = __half22float2(*reinterpret_cast<__half2*>(&u.z)); r.v[4] = f.x; r.v[5] = f.y;
    f = __half22float2(*reinterpret_cast<__half2*>(&u.w)); r.v[6] = f.x; r.v[7] = f.y;
    return r;
}

__device__ __forceinline__ void store_row8(void* out, int w, int gl,
                                           const float* a, bool out16) {
    if (out16) {
        uint4 u;
        __half2 h;
        h = __floats2half2_rn(a[0], a[1]); u.x = *reinterpret_cast<uint32_t*>(&h);
        h = __floats2half2_rn(a[2], a[3]); u.y = *reinterpret_cast<uint32_t*>(&h);
        h = __floats2half2_rn(a[4], a[5]); u.z = *reinterpret_cast<uint32_t*>(&h);
        h = __floats2half2_rn(a[6], a[7]); u.w = *reinterpret_cast<uint32_t*>(&h);
        ((uint4*)out)[(size_t)w * 16 + gl] = u;
    } else {
        float* o = (float*)out + (size_t)w * 128 + gl * 8;
        *(float4*)o       = make_float4(a[0], a[1], a[2], a[3]);
        *(float4*)(o + 4) = make_float4(a[4], a[5], a[6], a[7]);
    }
}

// ---------------- GCN aggregate: half-warp per node ----------------------------
template <bool OUT16>
__global__ void gcn_agg(const __half* __restrict__ xw,
                        const float* __restrict__ bias,
                        void* __restrict__ out) {
    int gwarp = (blockIdx.x * blockDim.x + threadIdx.x) >> 5;
    int lane = threadIdx.x & 31;
    int grp = lane >> 4, gl = lane & 15;
    int w = gwarp * 2 + grp;
    if (w >= N_NODES) return;
    if (gl == 0) { g_s[w] = 0.f; g_d[w] = 0.f; }
    int beg = g_off2[w], end = g_off2[w + 1];
    float invd = g_inv[w];
    const uint4* xw4 = (const uint4*)xw;
    float acc[8] = {0.f, 0.f, 0.f, 0.f, 0.f, 0.f, 0.f, 0.f};
    int p = beg;
    for (; p + 1 < end; p += 2) {
        int s0 = g_csr[p], s1 = g_csr[p + 1];
        float c0 = invd * g_inv[s0];
        float c1 = invd * g_inv[s1];
        F8 v0 = load_row8(xw4, s0, gl);
        F8 v1 = load_row8(xw4, s1, gl);
#pragma unroll
        for (int q = 0; q < 8; ++q) acc[q] += c0 * v0.v[q] + c1 * v1.v[q];
    }
    if (p < end) {
        int s0 = g_csr[p];
        float c0 = invd * g_inv[s0];
        F8 v0 = load_row8(xw4, s0, gl);
#pragma unroll
        for (int q = 0; q < 8; ++q) acc[q] += c0 * v0.v[q];
    }
    const float4* b4 = (const float4*)bias;
    float4 b0 = b4[gl * 2], b1 = b4[gl * 2 + 1];
    acc[0] = fmaxf(acc[0] + b0.x, 0.f); acc[1] = fmaxf(acc[1] + b0.y, 0.f);
    acc[2] = fmaxf(acc[2] + b0.z, 0.f); acc[3] = fmaxf(acc[3] + b0.w, 0.f);
    acc[4] = fmaxf(acc[4] + b1.x, 0.f); acc[5] = fmaxf(acc[5] + b1.y, 0.f);
    acc[6] = fmaxf(acc[6] + b1.z, 0.f); acc[7] = fmaxf(acc[7] + b1.w, 0.f);
    store_row8(out, w, gl, acc, OUT16);
}

// ---------------- GAT aggregate: half-warp per node, register-cached -----------
template <bool OUT16>
__global__ void gat_agg(const __half* __restrict__ xw,
                        const float* __restrict__ bias,
                        void* __restrict__ out) {
    int gwarp = (blockIdx.x * blockDim.x + threadIdx.x) >> 5;
    int lane = threadIdx.x & 31;
    int grp = lane >> 4, gl = lane & 15;
    int w = gwarp * 2 + grp;
    if (w >= N_NODES) return;
    int beg = g_off2[w], end = g_off2[w + 1];
    int deg = end - beg;
    float dd = g_d[w];
    const uint4* xw4 = (const uint4*)xw;
    float acc[8] = {0.f, 0.f, 0.f, 0.f, 0.f, 0.f, 0.f, 0.f};

    if (deg <= 64) {
        int sc[4];
        float ex[4];
        float m = -1e30f;
#pragma unroll
        for (int rr = 0; rr < 4; ++rr) {
            int p = beg + gl + 16 * rr;
            sc[rr] = 0; ex[rr] = -1e30f;
            if (p < end) {
                sc[rr] = g_csr[p];
                float t = g_s[sc[rr]] + dd;
                ex[rr] = (t > 0.f) ? t : 0.2f * t;
            }
            m = fmaxf(m, ex[rr]);
        }
#pragma unroll
        for (int o = 8; o; o >>= 1) m = fmaxf(m, __shfl_xor_sync(0xffffffffu, m, o));
        float sum = 0.f;
#pragma unroll
        for (int rr = 0; rr < 4; ++rr) {
            int p = beg + gl + 16 * rr;
            ex[rr] = (p < end) ? __expf(ex[rr] - m) : 0.f;
            sum += ex[rr];
        }
#pragma unroll
        for (int o = 8; o; o >>= 1) sum += __shfl_xor_sync(0xffffffffu, sum, o);
        float invden = 1.0f / sum;

        int base = grp << 4;
        int idx = 0;
        for (; idx + 1 < deg; idx += 2) {
            int r0 = idx >> 4,       l0 = (idx & 15) + base;
            int r1 = (idx + 1) >> 4, l1 = ((idx + 1) & 15) + base;
            float e0 = (r0 == 0) ? ex[0] : (r0 == 1) ? ex[1] : (r0 == 2) ? ex[2] : ex[3];
            int   c0 = (r0 == 0) ? sc[0] : (r0 == 1) ? sc[1] : (r0 == 2) ? sc[2] : sc[3];
            float e1 = (r1 == 0) ? ex[0] : (r1 == 1) ? ex[1] : (r1 == 2) ? ex[2] : ex[3];
            int   c1 = (r1 == 0) ? sc[0] : (r1 == 1) ? sc[1] : (r1 == 2) ? sc[2] : sc[3];
            float wa = __shfl_sync(0xffffffffu, e0, l0) * invden;
            int   sa = __shfl_sync(0xffffffffu, c0, l0);
            float wb = __shfl_sync(0xffffffffu, e1, l1) * invden;
            int   sb = __shfl_sync(0xffffffffu, c1, l1);
            F8 va = load_row8(xw4, sa, gl);
            F8 vb = load_row8(xw4, sb, gl);
#pragma unroll
            for (int q = 0; q < 8; ++q) acc[q] += wa * va.v[q] + wb * vb.v[q];
        }
        if (idx < deg) {
            int r0 = idx >> 4, l0 = (idx & 15) + base;
            float e0 = (r0 == 0) ? ex[0] : (r0 == 1) ? ex[1] : (r0 == 2) ? ex[2] : ex[3];
            int   c0 = (r0 == 0) ? sc[0] : (r0 == 1) ? sc[1] : (r0 == 2) ? sc[2] : sc[3];
            float wa = __shfl_sync(0xffffffffu, e0, l0) * invden;
            int   sa = __shfl_sync(0xffffffffu, c0, l0);
            F8 va = load_row8(xw4, sa, gl);
#pragma unroll
            for (int q = 0; q < 8; ++q) acc[q] += wa * va.v[q];
        }
    } else {
        float m = -1e30f;
        for (int p = beg + gl; p < end; p += 16) {
            int s = g_csr[p];
            float e = g_s[s] + dd;
            e = (e > 0.f) ? e : 0.2f * e;
            g_esc[p] = e;
            m = fmaxf(m, e);
        }
#pragma unroll
        for (int o = 8; o; o >>= 1) m = fmaxf(m, __shfl_xor_sync(0xffffffffu, m, o));
        float sum = 0.f;
        for (int p = beg + gl; p < end; p += 16) {
            float e = __expf(g_esc[p] - m);
            g_esc[p] = e;
            sum += e;
        }
#pragma unroll
        for (int o = 8; o; o >>= 1) sum += __shfl_xor_sync(0xffffffffu, sum, o);
        float invden = 1.0f / sum;
        __syncwarp();
        for (int p = beg; p < end; ++p) {
            int s = g_csr[p];
            float wgt = g_esc[p] * invden;
            F8 v = load_row8(xw4, s, gl);
#pragma unroll
            for (int q = 0; q < 8; ++q) acc[q] += wgt * v.v[q];
        }
    }

    const float4* b4 = (const float4*)bias;
    float4 b0 = b4[gl * 2], b1 = b4[gl * 2 + 1];
    acc[0] = fmaxf(acc[0] + b0.x, 0.f); acc[1] = fmaxf(acc[1] + b0.y, 0.f);
    acc[2] = fmaxf(acc[2] + b0.z, 0.f); acc[3] = fmaxf(acc[3] + b0.w, 0.f);
    acc[4] = fmaxf(acc[4] + b1.x, 0.f); acc[5] = fmaxf(acc[5] + b1.y, 0.f);
    acc[6] = fmaxf(acc[6] + b1.z, 0.f); acc[7] = fmaxf(acc[7] + b1.w, 0.f);
    store_row8(out, w, gl, acc, OUT16);
}

// ---------------- host launch ---------------------------------------------------
extern "C" void kernel_launch(void* const* d_in, const int* in_sizes, int n_in,
                              void* d_out, int out_size) {
    const float* x     = (const float*)d_in[0];
    const void*  ei    = d_in[1];
    const float* W1    = (const float*)d_in[2];
    const float* b1    = (const float*)d_in[3];
    const float* Wg1   = (const float*)d_in[4];
    const float* asrc1 = (const float*)d_in[5];
    const float* adst1 = (const float*)d_in[6];
    const float* bg1   = (const float*)d_in[7];
    const float* W2    = (const float*)d_in[8];
    const float* b2    = (const float*)d_in[9];
    const float* Wg2   = (const float*)d_in[10];
    const float* asrc2 = (const float*)d_in[11];
    const float* adst2 = (const float*)d_in[12];
    const float* bg2   = (const float*)d_in[13];
    const float* Wo    = (const float*)d_in[14];
    const float* bo    = (const float*)d_in[15];

    float* out_h = (float*)d_out;
    float* out_z = out_h + (size_t)N_NODES * HD;

    float *pA = nullptr, *pB = nullptr;
    unsigned short* pW = nullptr;
    cudaGetSymbolAddress((void**)&pA, g_bufA);
    cudaGetSymbolAddress((void**)&pB, g_bufB);
    cudaGetSymbolAddress((void**)&pW, g_wperm);
    __half* pA16 = (__half*)pA;
    __half* pB16 = (__half*)pB;
    const size_t WSTRIDE = 128 * 128;

    const int TB = 256;
    dim3 nb_edge((N_EDGES + TB - 1) / TB);
    dim3 nb_hw((N_NODES + 15) / 16);
    dim3 nb_gemm((N_NODES + 127) / 128);

    const int SMEM128 = 32768 + 128 * 128 * 2;  // 65536
    const int SMEM64  = 32768 + 128 * 64 * 2;   // 49152
    cudaFuncSetAttribute((const void*)tc_gemm<128, false, true>,
                         cudaFuncAttributeMaxDynamicSharedMemorySize, SMEM128);
    cudaFuncSetAttribute((const void*)tc_gemm<128, true, true>,
                         cudaFuncAttributeMaxDynamicSharedMemorySize, SMEM128);
    cudaFuncSetAttribute((const void*)tc_gemm<64, false, false>,
                         cudaFuncAttributeMaxDynamicSharedMemorySize, SMEM64);

    // CSR build + weight conversion (4 launches)
    k_pre<<<NB_SCAN, 1024>>>((const unsigned int*)ei);
    k_convert_count<<<dim3(nb_edge.x, 2), TB>>>(ei, W1, Wg1, W2, Wg2, Wo);
    k_scan_fused<<<NB_SCAN, 1024>>>();
    k_fill_edges<<<nb_edge, TB>>>();

    // Layer 1: GCN
    tc_gemm<128, false, true><<<nb_gemm, TB, SMEM128>>>(x, pW, nullptr, pA16, N_NODES, nullptr, nullptr);
    gcn_agg<true><<<nb_hw, TB>>>(pA16, b1, pB16);

    // Layer 2: GAT
    tc_gemm<128, true, true><<<nb_gemm, TB, SMEM128>>>(pB16, pW + WSTRIDE, nullptr, pA16, N_NODES, asrc1, adst1);
    gat_agg<true><<<nb_hw, TB>>>(pA16, bg1, pB16);

    // Layer 3: GCN
    tc_gemm<128, true, true><<<nb_gemm, TB, SMEM128>>>(pB16, pW + 2 * WSTRIDE, nullptr, pA16, N_NODES, nullptr, nullptr);
    gcn_agg<true><<<nb_hw, TB>>>(pA16, b2, pB16);

    // Layer 4: GAT -> h into d_out (fp32)
    tc_gemm<128, true, true><<<nb_gemm, TB, SMEM128>>>(pB16, pW + 3 * WSTRIDE, nullptr, pA16, N_NODES, asrc2, adst2);
    gat_agg<false><<<nb_hw, TB>>>(pA16, bg2, out_h);

    // Output head: z = h @ Wo + bo (fp32 in/out)
    tc_gemm<64, false, false><<<nb_gemm, TB, SMEM64>>>(out_h, pW + 4 * WSTRIDE, bo, out_z, N_NODES, nullptr, nullptr);
}